// round 1
// baseline (speedup 1.0000x reference)
#include <cuda_runtime.h>
#include <math.h>

#define Bn   4
#define Cn   256
#define Sn   4096
#define DFFn 1024
#define NBn  128
#define BSn  32

#define BSC (Bn*Sn*Cn)     // 4,194,304 floats
#define BST (Bn*Sn*DFFn)   // 16,777,216 floats

// ---- scratch (static device arrays: allowed; no runtime allocation) ----
__device__ float g_X1[BSC];
__device__ float g_X2[BSC];
__device__ float g_ATT[BSC];
__device__ float g_H[BSC];
__device__ float g_T[BST];

// ============================================================
// K1: x = LN( (w_proj @ src)^T + b_proj ) ; src (B,C,S) -> X (B,S,C)
// grid (S/32, B), block 256
// ============================================================
__global__ __launch_bounds__(256) void proj_ln_kernel(
    const float* __restrict__ src, const float* __restrict__ W,
    const float* __restrict__ bias, const float* __restrict__ gam,
    const float* __restrict__ bet, float* __restrict__ Xout)
{
    __shared__ float Wsm[256*33];   // [o][cc], pad 33 (also reused as Ysm 32x257)
    __shared__ float Xsm[32*36];    // [cc][j], pad 36 (float4-friendly)
    const int b = blockIdx.y;
    const int s0 = blockIdx.x << 5;
    const int t  = threadIdx.x;

    float acc[32];
#pragma unroll
    for (int j = 0; j < 32; j++) acc[j] = 0.f;

    for (int ck = 0; ck < 8; ck++) {
        // stage W chunk: thread t owns output row o=t, 32 c values
        const float4* wg = reinterpret_cast<const float4*>(W + t*256 + (ck<<5));
#pragma unroll
        for (int i = 0; i < 8; i++) {
            float4 w4 = wg[i];
            Wsm[t*33 + i*4 + 0] = w4.x;
            Wsm[t*33 + i*4 + 1] = w4.y;
            Wsm[t*33 + i*4 + 2] = w4.z;
            Wsm[t*33 + i*4 + 3] = w4.w;
        }
        // stage src chunk (coalesced): Xsm[cc][j] = src[b, ck*32+cc, s0+j]
#pragma unroll
        for (int k2 = 0; k2 < 4; k2++) {
            int e  = t + (k2 << 8);
            int cc = e >> 5;
            int j  = e & 31;
            Xsm[cc*36 + j] = src[((b*Cn + (ck<<5) + cc) << 12) + s0 + j];
        }
        __syncthreads();
#pragma unroll
        for (int cc = 0; cc < 32; cc++) {
            float wv = Wsm[t*33 + cc];
            const float4* xr = reinterpret_cast<const float4*>(Xsm + cc*36);
#pragma unroll
            for (int jj = 0; jj < 8; jj++) {
                float4 x4 = xr[jj];
                acc[jj*4+0] += wv * x4.x;
                acc[jj*4+1] += wv * x4.y;
                acc[jj*4+2] += wv * x4.z;
                acc[jj*4+3] += wv * x4.w;
            }
        }
        __syncthreads();
    }

    const float bv = bias[t];
    // transpose through smem (reuse Wsm): Ysm[j][o], 32x257
    float* Ysm = Wsm;
#pragma unroll
    for (int j = 0; j < 32; j++) Ysm[j*257 + t] = acc[j] + bv;
    __syncthreads();

    const int warp = t >> 5, lane = t & 31;
#pragma unroll
    for (int r = 0; r < 4; r++) {
        int j = (warp << 2) + r;
        float v[8]; float sum = 0.f, sq = 0.f;
#pragma unroll
        for (int k2 = 0; k2 < 8; k2++) {
            v[k2] = Ysm[j*257 + lane + (k2 << 5)];
            sum += v[k2]; sq += v[k2]*v[k2];
        }
#pragma unroll
        for (int o = 16; o > 0; o >>= 1) {
            sum += __shfl_xor_sync(0xffffffffu, sum, o);
            sq  += __shfl_xor_sync(0xffffffffu, sq , o);
        }
        float mean = sum * (1.f/256.f);
        float var  = sq  * (1.f/256.f) - mean*mean;
        float rstd = rsqrtf(var + 1e-5f);
        int base = (((b << 12) + s0 + j) << 8);
#pragma unroll
        for (int k2 = 0; k2 < 8; k2++) {
            int o = lane + (k2 << 5);
            Xout[base + o] = (v[k2] - mean) * rstd * gam[o] + bet[o];
        }
    }
}

// ============================================================
// K2: block-sparse flash attention. grid (NB, B), block 256, dyn smem
// row block 0: full attention (global rows). rows n>=1: gathered blocks.
// padding rule: valid entries of block_idx row are an ascending prefix
// starting with 0; trailing zeros (at j>0) are padding -> break.
// ============================================================
#define QP 257
#define VP 260
#define ATTN_SMEM_FLOATS (32*QP*2 + 32*VP + 32*33 + 96)

__global__ __launch_bounds__(256) void attn_kernel(
    const float* __restrict__ X1, const float* __restrict__ X2,
    const int* __restrict__ bidx, int K, float* __restrict__ ATT)
{
    extern __shared__ float sm[];
    float* qsm  = sm;
    float* ksm  = qsm + 32*QP;
    float* vsm  = ksm + 32*QP;
    float* ssm  = vsm + 32*VP;
    float* mrow = ssm + 32*33;
    float* lrow = mrow + 32;
    float* arow = lrow + 32;

    const int b = blockIdx.y, n = blockIdx.x;
    const int t = threadIdx.x;
    const int tx = t & 15, ty = t >> 4;          // score 2x2 micro-tile
    const int qv = t >> 3, dbase = (t & 7) << 5; // PV: thread owns (q, 32 d)
    const int warp = t >> 5, lane = t & 31;

#pragma unroll
    for (int i = 0; i < 32; i++)
        qsm[i*QP + t] = X1[(((b << 12) + (n << 5) + i) << 8) + t];
    if (t < 32) { mrow[t] = -1e30f; lrow[t] = 0.f; }

    float out[32];
#pragma unroll
    for (int j = 0; j < 32; j++) out[j] = 0.f;
    __syncthreads();

    const int nIter = (n == 0) ? NBn : K;
    for (int it = 0; it < nIter; it++) {
        int kb;
        if (n == 0) kb = it;
        else {
            kb = bidx[(n - 1)*K + it];
            if (it > 0 && kb == 0) break;   // padding suffix
        }
        // K = V = X2 tile: one global load, two smem layouts
#pragma unroll
        for (int i = 0; i < 32; i++) {
            float val = X2[(((b << 12) + (kb << 5) + i) << 8) + t];
            ksm[i*QP + t] = val;
            vsm[i*VP + t] = val;
        }
        __syncthreads();

        // scores: 2q x 2k per thread
        float s00 = 0.f, s01 = 0.f, s10 = 0.f, s11 = 0.f;
        const float* q0 = qsm + (ty << 1)*QP;
        const float* q1 = q0 + QP;
        const float* k0 = ksm + (tx << 1)*QP;
        const float* k1 = k0 + QP;
#pragma unroll 8
        for (int d = 0; d < 256; d++) {
            float qa = q0[d], qb = q1[d], ka = k0[d], kc = k1[d];
            s00 += qa*ka; s01 += qa*kc; s10 += qb*ka; s11 += qb*kc;
        }
        const float scl = 0.0625f; // 1/sqrt(256)
        ssm[(ty<<1)*33 + (tx<<1)    ] = s00*scl;
        ssm[(ty<<1)*33 + (tx<<1) + 1] = s01*scl;
        ssm[((ty<<1)+1)*33 + (tx<<1)    ] = s10*scl;
        ssm[((ty<<1)+1)*33 + (tx<<1) + 1] = s11*scl;
        __syncthreads();

        // online softmax: warp handles 4 rows
#pragma unroll
        for (int r = 0; r < 4; r++) {
            int row = (warp << 2) + r;
            float sv = ssm[row*33 + lane];
            float mx = sv;
#pragma unroll
            for (int o = 16; o > 0; o >>= 1)
                mx = fmaxf(mx, __shfl_xor_sync(0xffffffffu, mx, o));
            float mold = mrow[row];
            float mnew = fmaxf(mold, mx);
            float p = __expf(sv - mnew);
            float ps = p;
#pragma unroll
            for (int o = 16; o > 0; o >>= 1)
                ps += __shfl_xor_sync(0xffffffffu, ps, o);
            if (lane == 0) {
                float a = __expf(mold - mnew);
                arow[row] = a;
                lrow[row] = lrow[row]*a + ps;
                mrow[row] = mnew;
            }
            ssm[row*33 + lane] = p;  // P in place
        }
        __syncthreads();

        // PV accumulate
        float alpha = arow[qv];
#pragma unroll
        for (int j = 0; j < 32; j++) out[j] *= alpha;
        const float* prow = ssm + qv*33;
#pragma unroll 4
        for (int k2 = 0; k2 < 32; k2++) {
            float p = prow[k2];
            const float4* vr = reinterpret_cast<const float4*>(vsm + k2*VP + dbase);
#pragma unroll
            for (int jj = 0; jj < 8; jj++) {
                float4 v4 = vr[jj];
                out[jj*4+0] += p*v4.x; out[jj*4+1] += p*v4.y;
                out[jj*4+2] += p*v4.z; out[jj*4+3] += p*v4.w;
            }
        }
        __syncthreads();
    }

    const float linv = 1.f / lrow[qv];
    const int base = (((b << 12) + (n << 5) + qv) << 8) + dbase;
#pragma unroll
    for (int j = 0; j < 32; j++) ATT[base + j] = out[j]*linv;
}

// ============================================================
// K3: H = LN(X1 + ATT). warp per row. grid = B*S/8, block 256
// ============================================================
__global__ __launch_bounds__(256) void add_ln_kernel(
    const float* __restrict__ X1, const float* __restrict__ ATT,
    const float* __restrict__ gam, const float* __restrict__ bet,
    float* __restrict__ H)
{
    const int row  = (blockIdx.x << 3) + (threadIdx.x >> 5);
    const int lane = threadIdx.x & 31;
    const int base = row << 8;
    float v[8]; float sum = 0.f, sq = 0.f;
#pragma unroll
    for (int k = 0; k < 8; k++) {
        int o = lane + (k << 5);
        v[k] = X1[base + o] + ATT[base + o];
        sum += v[k]; sq += v[k]*v[k];
    }
#pragma unroll
    for (int o = 16; o > 0; o >>= 1) {
        sum += __shfl_xor_sync(0xffffffffu, sum, o);
        sq  += __shfl_xor_sync(0xffffffffu, sq , o);
    }
    float mean = sum * (1.f/256.f);
    float var  = sq  * (1.f/256.f) - mean*mean;
    float rstd = rsqrtf(var + 1e-5f);
#pragma unroll
    for (int k = 0; k < 8; k++) {
        int o = lane + (k << 5);
        H[base + o] = (v[k] - mean)*rstd*gam[o] + bet[o];
    }
}

// ============================================================
// K4: T = gelu(H @ w1 + b1).  grid (B*S/32, DFF/256), block 256
// ============================================================
__global__ __launch_bounds__(256) void ffn1_kernel(
    const float* __restrict__ H, const float* __restrict__ w1,
    const float* __restrict__ b1, float* __restrict__ T)
{
    __shared__ float Asm[32*36];    // [cc][j] transposed H chunk
    __shared__ float Wsm[32*256];   // [cc][f] w1 chunk
    const int row0 = blockIdx.x << 5;
    const int fb   = blockIdx.y << 8;
    const int t = threadIdx.x, lane = t & 31;

    float acc[32];
#pragma unroll
    for (int j = 0; j < 32; j++) acc[j] = 0.f;

    for (int ck = 0; ck < 8; ck++) {
#pragma unroll
        for (int k2 = 0; k2 < 4; k2++) {
            int jr = (t >> 5) + (k2 << 3);
            Asm[lane*36 + jr] = H[((row0 + jr) << 8) + (ck << 5) + lane];
        }
#pragma unroll
        for (int i = 0; i < 32; i++)
            Wsm[(i << 8) + t] = w1[((ck << 5) + i)*DFFn + fb + t];
        __syncthreads();
#pragma unroll
        for (int cc = 0; cc < 32; cc++) {
            float wv = Wsm[(cc << 8) + t];
            const float4* ar = reinterpret_cast<const float4*>(Asm + cc*36);
#pragma unroll
            for (int jj = 0; jj < 8; jj++) {
                float4 a4 = ar[jj];
                acc[jj*4+0] += wv*a4.x; acc[jj*4+1] += wv*a4.y;
                acc[jj*4+2] += wv*a4.z; acc[jj*4+3] += wv*a4.w;
            }
        }
        __syncthreads();
    }
    const float bv = b1[fb + t];
#pragma unroll
    for (int j = 0; j < 32; j++) {
        float x = acc[j] + bv;
        float ge = 0.5f*x*(1.f + erff(x*0.70710678118654752f)); // exact gelu
        T[((row0 + j) << 10) + fb + t] = ge;
    }
}

// ============================================================
// K5: out = transpose(H + T @ w2 + b2) -> (B,C,S). grid B*S/32, block 256
// ============================================================
__global__ __launch_bounds__(256) void ffn2_kernel(
    const float* __restrict__ T, const float* __restrict__ w2,
    const float* __restrict__ b2, const float* __restrict__ H,
    float* __restrict__ Out)
{
    __shared__ float smem[32*36 + 32*256];  // 9344 floats; reused as Ysm (256*33=8448)
    float* Asm = smem;
    float* Wsm = smem + 32*36;
    const int row0 = blockIdx.x << 5;
    const int t = threadIdx.x, lane = t & 31;

    float acc[32];
#pragma unroll
    for (int j = 0; j < 32; j++) acc[j] = 0.f;

    for (int ck = 0; ck < 32; ck++) {
#pragma unroll
        for (int k2 = 0; k2 < 4; k2++) {
            int jr = (t >> 5) + (k2 << 3);
            Asm[lane*36 + jr] = T[((row0 + jr) << 10) + (ck << 5) + lane];
        }
#pragma unroll
        for (int i = 0; i < 32; i++)
            Wsm[(i << 8) + t] = w2[(((ck << 5) + i) << 8) + t];
        __syncthreads();
#pragma unroll
        for (int cc = 0; cc < 32; cc++) {
            float wv = Wsm[(cc << 8) + t];
            const float4* ar = reinterpret_cast<const float4*>(Asm + cc*36);
#pragma unroll
            for (int jj = 0; jj < 8; jj++) {
                float4 a4 = ar[jj];
                acc[jj*4+0] += wv*a4.x; acc[jj*4+1] += wv*a4.y;
                acc[jj*4+2] += wv*a4.z; acc[jj*4+3] += wv*a4.w;
            }
        }
        __syncthreads();
    }

    const float bv = b2[t];
    float* Ysm = smem;  // safe: all threads past last sync'd GEMM phase
#pragma unroll
    for (int j = 0; j < 32; j++) {
        float val = acc[j] + bv + H[((row0 + j) << 8) + t];  // coalesced residual
        Ysm[t*33 + j] = val;
    }
    __syncthreads();
    const int b  = row0 >> 12;
    const int s0 = row0 & 4095;
    float* orow = Out + (((b << 8) + t) << 12) + s0;  // (b*C + c)*S + s0, c = t
#pragma unroll
    for (int jj = 0; jj < 8; jj++) {
        float4 v4 = make_float4(Ysm[t*33 + jj*4 + 0], Ysm[t*33 + jj*4 + 1],
                                Ysm[t*33 + jj*4 + 2], Ysm[t*33 + jj*4 + 3]);
        reinterpret_cast<float4*>(orow)[jj] = v4;
    }
}

// ============================================================
extern "C" void kernel_launch(void* const* d_in, const int* in_sizes, int n_in,
                              void* d_out, int out_size)
{
    const float* src1  = (const float*)d_in[0];
    const float* src2  = (const float*)d_in[1];
    const float* wproj = (const float*)d_in[2];
    const float* bproj = (const float*)d_in[3];
    const float* g13   = (const float*)d_in[4];
    const float* be13  = (const float*)d_in[5];
    const float* g12   = (const float*)d_in[6];
    const float* be12  = (const float*)d_in[7];
    const float* w1    = (const float*)d_in[8];
    const float* b1    = (const float*)d_in[9];
    const float* w2    = (const float*)d_in[10];
    const float* b2    = (const float*)d_in[11];
    const int*   bidx  = (const int*)d_in[12];
    const int K = in_sizes[12] / (NBn - 1);   // block_idx is (127, K)
    float* out = (float*)d_out;

    float *X1, *X2, *ATT, *H, *T;
    cudaGetSymbolAddress((void**)&X1,  g_X1);
    cudaGetSymbolAddress((void**)&X2,  g_X2);
    cudaGetSymbolAddress((void**)&ATT, g_ATT);
    cudaGetSymbolAddress((void**)&H,   g_H);
    cudaGetSymbolAddress((void**)&T,   g_T);

    const int attn_smem = ATTN_SMEM_FLOATS * 4;  // 103,680 B
    cudaFuncSetAttribute(attn_kernel, cudaFuncAttributeMaxDynamicSharedMemorySize, attn_smem);

    dim3 gProj(Sn/32, Bn);
    proj_ln_kernel<<<gProj, 256>>>(src1, wproj, bproj, g13, be13, X1);
    proj_ln_kernel<<<gProj, 256>>>(src2, wproj, bproj, g13, be13, X2);

    attn_kernel<<<dim3(NBn, Bn), 256, attn_smem>>>(X1, X2, bidx, K, ATT);

    add_ln_kernel<<<(Bn*Sn)/8, 256>>>(X1, ATT, g12, be12, H);

    ffn1_kernel<<<dim3((Bn*Sn)/32, DFFn/256), 256>>>(H, w1, b1, T);

    ffn2_kernel<<<(Bn*Sn)/32, 256>>>(T, w2, b2, H, out);
}

// round 2
// speedup vs baseline: 2.2614x; 2.2614x over previous
#include <cuda_runtime.h>
#include <math.h>

#define Bn   4
#define Cn   256
#define Sn   4096
#define DFFn 1024
#define NBn  128
#define BSn  32
#define NSPLIT 16

#define BSC (Bn*Sn*Cn)     // 4,194,304 floats
#define BST (Bn*Sn*DFFn)   // 16,777,216 floats

// ---- scratch (static device arrays: allowed; no runtime allocation) ----
__device__ float g_X1[BSC];
__device__ float g_X2[BSC];
__device__ float g_ATT[BSC];
__device__ float g_H[BSC];
__device__ float g_T[BST];
__device__ float g_GO[Bn*NSPLIT*32*256];  // global-attn partial outputs
__device__ float g_GM[Bn*NSPLIT*32];      // partial row max
__device__ float g_GL[Bn*NSPLIT*32];      // partial row sum

// ============================================================
// K1: x = LN( (w_proj @ src)^T + b_proj ) ; src (B,C,S) -> X (B,S,C)
// grid (S/32, B, 2) — z selects src1/src2. block 256
// ============================================================
__global__ __launch_bounds__(256) void proj_ln_kernel(
    const float* __restrict__ src1, const float* __restrict__ src2,
    const float* __restrict__ W,
    const float* __restrict__ bias, const float* __restrict__ gam,
    const float* __restrict__ bet,
    float* __restrict__ X1, float* __restrict__ X2)
{
    __shared__ float Wsm[256*33];   // [o][cc], pad 33 (reused as Ysm 32x257)
    __shared__ float Xsm[32*36];    // [cc][j]
    const float* src = blockIdx.z ? src2 : src1;
    float* Xout      = blockIdx.z ? g_X2 : g_X1;
    (void)X1; (void)X2;
    const int b = blockIdx.y;
    const int s0 = blockIdx.x << 5;
    const int t  = threadIdx.x;

    float acc[32];
#pragma unroll
    for (int j = 0; j < 32; j++) acc[j] = 0.f;

    for (int ck = 0; ck < 8; ck++) {
        const float4* wg = reinterpret_cast<const float4*>(W + t*256 + (ck<<5));
#pragma unroll
        for (int i = 0; i < 8; i++) {
            float4 w4 = wg[i];
            Wsm[t*33 + i*4 + 0] = w4.x;
            Wsm[t*33 + i*4 + 1] = w4.y;
            Wsm[t*33 + i*4 + 2] = w4.z;
            Wsm[t*33 + i*4 + 3] = w4.w;
        }
#pragma unroll
        for (int k2 = 0; k2 < 4; k2++) {
            int e  = t + (k2 << 8);
            int cc = e >> 5;
            int j  = e & 31;
            Xsm[cc*36 + j] = src[((b*Cn + (ck<<5) + cc) << 12) + s0 + j];
        }
        __syncthreads();
#pragma unroll
        for (int cc = 0; cc < 32; cc++) {
            float wv = Wsm[t*33 + cc];
            const float4* xr = reinterpret_cast<const float4*>(Xsm + cc*36);
#pragma unroll
            for (int jj = 0; jj < 8; jj++) {
                float4 x4 = xr[jj];
                acc[jj*4+0] += wv * x4.x;
                acc[jj*4+1] += wv * x4.y;
                acc[jj*4+2] += wv * x4.z;
                acc[jj*4+3] += wv * x4.w;
            }
        }
        __syncthreads();
    }

    const float bv = bias[t];
    float* Ysm = Wsm;
#pragma unroll
    for (int j = 0; j < 32; j++) Ysm[j*257 + t] = acc[j] + bv;
    __syncthreads();

    const int warp = t >> 5, lane = t & 31;
#pragma unroll
    for (int r = 0; r < 4; r++) {
        int j = (warp << 2) + r;
        float v[8]; float sum = 0.f, sq = 0.f;
#pragma unroll
        for (int k2 = 0; k2 < 8; k2++) {
            v[k2] = Ysm[j*257 + lane + (k2 << 5)];
            sum += v[k2]; sq += v[k2]*v[k2];
        }
#pragma unroll
        for (int o = 16; o > 0; o >>= 1) {
            sum += __shfl_xor_sync(0xffffffffu, sum, o);
            sq  += __shfl_xor_sync(0xffffffffu, sq , o);
        }
        float mean = sum * (1.f/256.f);
        float var  = sq  * (1.f/256.f) - mean*mean;
        float rstd = rsqrtf(var + 1e-5f);
        int base = (((b << 12) + s0 + j) << 8);
#pragma unroll
        for (int k2 = 0; k2 < 8; k2++) {
            int o = lane + (k2 << 5);
            Xout[base + o] = (v[k2] - mean) * rstd * gam[o] + bet[o];
        }
    }
}

// ============================================================
// shared attention tile machinery constants
// ============================================================
#define QP 257
#define VP 260
#define ATTN_SMEM_FLOATS (32*QP*2 + 32*VP + 32*33 + 96)

// ============================================================
// K2a: sparse rows (n = 1..127). grid (127, B), block 256, dyn smem
// ============================================================
__global__ __launch_bounds__(256) void attn_sparse_kernel(
    const float* __restrict__ X1, const float* __restrict__ X2,
    const int* __restrict__ bidx, int K, float* __restrict__ ATT)
{
    extern __shared__ float sm[];
    float* qsm  = sm;
    float* ksm  = qsm + 32*QP;
    float* vsm  = ksm + 32*QP;
    float* ssm  = vsm + 32*VP;
    float* mrow = ssm + 32*33;
    float* lrow = mrow + 32;
    float* arow = lrow + 32;

    const int b = blockIdx.y, n = blockIdx.x + 1;
    const int t = threadIdx.x;
    const int tx = t & 15, ty = t >> 4;
    const int qv = t >> 3, dbase = (t & 7) << 5;
    const int warp = t >> 5, lane = t & 31;

#pragma unroll
    for (int i = 0; i < 32; i++)
        qsm[i*QP + t] = X1[(((b << 12) + (n << 5) + i) << 8) + t];
    if (t < 32) { mrow[t] = -1e30f; lrow[t] = 0.f; }

    float out[32];
#pragma unroll
    for (int j = 0; j < 32; j++) out[j] = 0.f;
    __syncthreads();

    for (int it = 0; it < K; it++) {
        int kb = bidx[(n - 1)*K + it];
        if (it > 0 && kb == 0) break;   // padding suffix
#pragma unroll
        for (int i = 0; i < 32; i++) {
            float val = X2[(((b << 12) + (kb << 5) + i) << 8) + t];
            ksm[i*QP + t] = val;
            vsm[i*VP + t] = val;
        }
        __syncthreads();

        float s00 = 0.f, s01 = 0.f, s10 = 0.f, s11 = 0.f;
        const float* q0 = qsm + (ty << 1)*QP;
        const float* q1 = q0 + QP;
        const float* k0 = ksm + (tx << 1)*QP;
        const float* k1 = k0 + QP;
#pragma unroll 8
        for (int d = 0; d < 256; d++) {
            float qa = q0[d], qb = q1[d], ka = k0[d], kc = k1[d];
            s00 += qa*ka; s01 += qa*kc; s10 += qb*ka; s11 += qb*kc;
        }
        const float scl = 0.0625f;
        ssm[(ty<<1)*33 + (tx<<1)    ] = s00*scl;
        ssm[(ty<<1)*33 + (tx<<1) + 1] = s01*scl;
        ssm[((ty<<1)+1)*33 + (tx<<1)    ] = s10*scl;
        ssm[((ty<<1)+1)*33 + (tx<<1) + 1] = s11*scl;
        __syncthreads();

#pragma unroll
        for (int r = 0; r < 4; r++) {
            int row = (warp << 2) + r;
            float sv = ssm[row*33 + lane];
            float mx = sv;
#pragma unroll
            for (int o = 16; o > 0; o >>= 1)
                mx = fmaxf(mx, __shfl_xor_sync(0xffffffffu, mx, o));
            float mold = mrow[row];
            float mnew = fmaxf(mold, mx);
            float p = __expf(sv - mnew);
            float ps = p;
#pragma unroll
            for (int o = 16; o > 0; o >>= 1)
                ps += __shfl_xor_sync(0xffffffffu, ps, o);
            if (lane == 0) {
                float a = __expf(mold - mnew);
                arow[row] = a;
                lrow[row] = lrow[row]*a + ps;
                mrow[row] = mnew;
            }
            ssm[row*33 + lane] = p;
        }
        __syncthreads();

        float alpha = arow[qv];
#pragma unroll
        for (int j = 0; j < 32; j++) out[j] *= alpha;
        const float* prow = ssm + qv*33;
#pragma unroll 4
        for (int k2 = 0; k2 < 32; k2++) {
            float p = prow[k2];
            const float4* vr = reinterpret_cast<const float4*>(vsm + k2*VP + dbase);
#pragma unroll
            for (int jj = 0; jj < 8; jj++) {
                float4 v4 = vr[jj];
                out[jj*4+0] += p*v4.x; out[jj*4+1] += p*v4.y;
                out[jj*4+2] += p*v4.z; out[jj*4+3] += p*v4.w;
            }
        }
        __syncthreads();
    }

    const float linv = 1.f / lrow[qv];
    const int base = (((b << 12) + (n << 5) + qv) << 8) + dbase;
#pragma unroll
    for (int j = 0; j < 32; j++) ATT[base + j] = out[j]*linv;
}

// ============================================================
// K2b: global rows (n=0), split-softmax partials.
// grid (NSPLIT, B), block 256. Each split covers 8 key blocks.
// ============================================================
__global__ __launch_bounds__(256) void attn_global_partial(
    const float* __restrict__ X1, const float* __restrict__ X2,
    float* __restrict__ GO, float* __restrict__ GM, float* __restrict__ GL)
{
    extern __shared__ float sm[];
    float* qsm  = sm;
    float* ksm  = qsm + 32*QP;
    float* vsm  = ksm + 32*QP;
    float* ssm  = vsm + 32*VP;
    float* mrow = ssm + 32*33;
    float* lrow = mrow + 32;
    float* arow = lrow + 32;

    const int b = blockIdx.y, split = blockIdx.x;
    const int t = threadIdx.x;
    const int tx = t & 15, ty = t >> 4;
    const int qv = t >> 3, dbase = (t & 7) << 5;
    const int warp = t >> 5, lane = t & 31;

#pragma unroll
    for (int i = 0; i < 32; i++)
        qsm[i*QP + t] = X1[(((b << 12) + i) << 8) + t];
    if (t < 32) { mrow[t] = -1e30f; lrow[t] = 0.f; }

    float out[32];
#pragma unroll
    for (int j = 0; j < 32; j++) out[j] = 0.f;
    __syncthreads();

    for (int it = 0; it < NBn/NSPLIT; it++) {
        int kb = split*(NBn/NSPLIT) + it;
#pragma unroll
        for (int i = 0; i < 32; i++) {
            float val = X2[(((b << 12) + (kb << 5) + i) << 8) + t];
            ksm[i*QP + t] = val;
            vsm[i*VP + t] = val;
        }
        __syncthreads();

        float s00 = 0.f, s01 = 0.f, s10 = 0.f, s11 = 0.f;
        const float* q0 = qsm + (ty << 1)*QP;
        const float* q1 = q0 + QP;
        const float* k0 = ksm + (tx << 1)*QP;
        const float* k1 = k0 + QP;
#pragma unroll 8
        for (int d = 0; d < 256; d++) {
            float qa = q0[d], qb = q1[d], ka = k0[d], kc = k1[d];
            s00 += qa*ka; s01 += qa*kc; s10 += qb*ka; s11 += qb*kc;
        }
        const float scl = 0.0625f;
        ssm[(ty<<1)*33 + (tx<<1)    ] = s00*scl;
        ssm[(ty<<1)*33 + (tx<<1) + 1] = s01*scl;
        ssm[((ty<<1)+1)*33 + (tx<<1)    ] = s10*scl;
        ssm[((ty<<1)+1)*33 + (tx<<1) + 1] = s11*scl;
        __syncthreads();

#pragma unroll
        for (int r = 0; r < 4; r++) {
            int row = (warp << 2) + r;
            float sv = ssm[row*33 + lane];
            float mx = sv;
#pragma unroll
            for (int o = 16; o > 0; o >>= 1)
                mx = fmaxf(mx, __shfl_xor_sync(0xffffffffu, mx, o));
            float mold = mrow[row];
            float mnew = fmaxf(mold, mx);
            float p = __expf(sv - mnew);
            float ps = p;
#pragma unroll
            for (int o = 16; o > 0; o >>= 1)
                ps += __shfl_xor_sync(0xffffffffu, ps, o);
            if (lane == 0) {
                float a = __expf(mold - mnew);
                arow[row] = a;
                lrow[row] = lrow[row]*a + ps;
                mrow[row] = mnew;
            }
            ssm[row*33 + lane] = p;
        }
        __syncthreads();

        float alpha = arow[qv];
#pragma unroll
        for (int j = 0; j < 32; j++) out[j] *= alpha;
        const float* prow = ssm + qv*33;
#pragma unroll 4
        for (int k2 = 0; k2 < 32; k2++) {
            float p = prow[k2];
            const float4* vr = reinterpret_cast<const float4*>(vsm + k2*VP + dbase);
#pragma unroll
            for (int jj = 0; jj < 8; jj++) {
                float4 v4 = vr[jj];
                out[jj*4+0] += p*v4.x; out[jj*4+1] += p*v4.y;
                out[jj*4+2] += p*v4.z; out[jj*4+3] += p*v4.w;
            }
        }
        __syncthreads();
    }

    const int gi = (b*NSPLIT + split)*32;
    const int base = ((gi + qv) << 8) + dbase;
#pragma unroll
    for (int j = 0; j < 32; j++) GO[base + j] = out[j];   // unnormalized
    if (t < 32) { GM[gi + t] = mrow[t]; GL[gi + t] = lrow[t]; }
}

// ============================================================
// K2c: combine split-softmax partials into ATT rows 0..31 per batch.
// grid (B), block 256
// ============================================================
__global__ __launch_bounds__(256) void attn_global_combine(
    const float* __restrict__ GO, const float* __restrict__ GM,
    const float* __restrict__ GL, float* __restrict__ ATT)
{
    __shared__ float ms[NSPLIT*32], ls[NSPLIT*32];
    const int b = blockIdx.x, t = threadIdx.x;
    for (int k = t; k < NSPLIT*32; k += 256) {
        ms[k] = GM[b*NSPLIT*32 + k];
        ls[k] = GL[b*NSPLIT*32 + k];
    }
    __syncthreads();
#pragma unroll 4
    for (int q = 0; q < 32; q++) {
        float M = -1e30f;
#pragma unroll
        for (int i = 0; i < NSPLIT; i++) M = fmaxf(M, ms[i*32 + q]);
        float L = 0.f, acc = 0.f;
#pragma unroll
        for (int i = 0; i < NSPLIT; i++) {
            float e = __expf(ms[i*32 + q] - M);
            L   += ls[i*32 + q] * e;
            acc += GO[(((b*NSPLIT + i)*32 + q) << 8) + t] * e;
        }
        ATT[(((b << 12) + q) << 8) + t] = acc / L;
    }
}

// ============================================================
// K3: H = LN(X1 + ATT). warp per row. grid = B*S/8, block 256
// ============================================================
__global__ __launch_bounds__(256) void add_ln_kernel(
    const float* __restrict__ X1, const float* __restrict__ ATT,
    const float* __restrict__ gam, const float* __restrict__ bet,
    float* __restrict__ H)
{
    const int row  = (blockIdx.x << 3) + (threadIdx.x >> 5);
    const int lane = threadIdx.x & 31;
    const int base = row << 8;
    float v[8]; float sum = 0.f, sq = 0.f;
#pragma unroll
    for (int k = 0; k < 8; k++) {
        int o = lane + (k << 5);
        v[k] = X1[base + o] + ATT[base + o];
        sum += v[k]; sq += v[k]*v[k];
    }
#pragma unroll
    for (int o = 16; o > 0; o >>= 1) {
        sum += __shfl_xor_sync(0xffffffffu, sum, o);
        sq  += __shfl_xor_sync(0xffffffffu, sq , o);
    }
    float mean = sum * (1.f/256.f);
    float var  = sq  * (1.f/256.f) - mean*mean;
    float rstd = rsqrtf(var + 1e-5f);
#pragma unroll
    for (int k = 0; k < 8; k++) {
        int o = lane + (k << 5);
        H[base + o] = (v[k] - mean)*rstd*gam[o] + bet[o];
    }
}

// ============================================================
// K4: T = gelu(H @ w1 + b1).  grid (B*S/32, DFF/256), block 256
// ============================================================
__global__ __launch_bounds__(256) void ffn1_kernel(
    const float* __restrict__ H, const float* __restrict__ w1,
    const float* __restrict__ b1, float* __restrict__ T)
{
    __shared__ float Asm[32*36];
    __shared__ float Wsm[32*256];
    const int row0 = blockIdx.x << 5;
    const int fb   = blockIdx.y << 8;
    const int t = threadIdx.x, lane = t & 31;

    float acc[32];
#pragma unroll
    for (int j = 0; j < 32; j++) acc[j] = 0.f;

    for (int ck = 0; ck < 8; ck++) {
#pragma unroll
        for (int k2 = 0; k2 < 4; k2++) {
            int jr = (t >> 5) + (k2 << 3);
            Asm[lane*36 + jr] = H[((row0 + jr) << 8) + (ck << 5) + lane];
        }
#pragma unroll
        for (int i = 0; i < 32; i++)
            Wsm[(i << 8) + t] = w1[((ck << 5) + i)*DFFn + fb + t];
        __syncthreads();
#pragma unroll
        for (int cc = 0; cc < 32; cc++) {
            float wv = Wsm[(cc << 8) + t];
            const float4* ar = reinterpret_cast<const float4*>(Asm + cc*36);
#pragma unroll
            for (int jj = 0; jj < 8; jj++) {
                float4 a4 = ar[jj];
                acc[jj*4+0] += wv*a4.x; acc[jj*4+1] += wv*a4.y;
                acc[jj*4+2] += wv*a4.z; acc[jj*4+3] += wv*a4.w;
            }
        }
        __syncthreads();
    }
    const float bv = b1[fb + t];
#pragma unroll
    for (int j = 0; j < 32; j++) {
        float x = acc[j] + bv;
        float ge = 0.5f*x*(1.f + erff(x*0.70710678118654752f));
        T[((row0 + j) << 10) + fb + t] = ge;
    }
}

// ============================================================
// K5: out = transpose(H + T @ w2 + b2) -> (B,C,S). grid B*S/32, block 256
// ============================================================
__global__ __launch_bounds__(256) void ffn2_kernel(
    const float* __restrict__ T, const float* __restrict__ w2,
    const float* __restrict__ b2, const float* __restrict__ H,
    float* __restrict__ Out)
{
    __shared__ float smem[32*36 + 32*256];
    float* Asm = smem;
    float* Wsm = smem + 32*36;
    const int row0 = blockIdx.x << 5;
    const int t = threadIdx.x, lane = t & 31;

    float acc[32];
#pragma unroll
    for (int j = 0; j < 32; j++) acc[j] = 0.f;

    for (int ck = 0; ck < 32; ck++) {
#pragma unroll
        for (int k2 = 0; k2 < 4; k2++) {
            int jr = (t >> 5) + (k2 << 3);
            Asm[lane*36 + jr] = T[((row0 + jr) << 10) + (ck << 5) + lane];
        }
#pragma unroll
        for (int i = 0; i < 32; i++)
            Wsm[(i << 8) + t] = w2[(((ck << 5) + i) << 8) + t];
        __syncthreads();
#pragma unroll
        for (int cc = 0; cc < 32; cc++) {
            float wv = Wsm[(cc << 8) + t];
            const float4* ar = reinterpret_cast<const float4*>(Asm + cc*36);
#pragma unroll
            for (int jj = 0; jj < 8; jj++) {
                float4 a4 = ar[jj];
                acc[jj*4+0] += wv*a4.x; acc[jj*4+1] += wv*a4.y;
                acc[jj*4+2] += wv*a4.z; acc[jj*4+3] += wv*a4.w;
            }
        }
        __syncthreads();
    }

    const float bv = b2[t];
    float* Ysm = smem;
#pragma unroll
    for (int j = 0; j < 32; j++) {
        float val = acc[j] + bv + H[((row0 + j) << 8) + t];
        Ysm[t*33 + j] = val;
    }
    __syncthreads();
    const int b  = row0 >> 12;
    const int s0 = row0 & 4095;
    float* orow = Out + (((b << 8) + t) << 12) + s0;
#pragma unroll
    for (int jj = 0; jj < 8; jj++) {
        float4 v4 = make_float4(Ysm[t*33 + jj*4 + 0], Ysm[t*33 + jj*4 + 1],
                                Ysm[t*33 + jj*4 + 2], Ysm[t*33 + jj*4 + 3]);
        reinterpret_cast<float4*>(orow)[jj] = v4;
    }
}

// ============================================================
extern "C" void kernel_launch(void* const* d_in, const int* in_sizes, int n_in,
                              void* d_out, int out_size)
{
    const float* src1  = (const float*)d_in[0];
    const float* src2  = (const float*)d_in[1];
    const float* wproj = (const float*)d_in[2];
    const float* bproj = (const float*)d_in[3];
    const float* g13   = (const float*)d_in[4];
    const float* be13  = (const float*)d_in[5];
    const float* g12   = (const float*)d_in[6];
    const float* be12  = (const float*)d_in[7];
    const float* w1    = (const float*)d_in[8];
    const float* b1    = (const float*)d_in[9];
    const float* w2    = (const float*)d_in[10];
    const float* b2    = (const float*)d_in[11];
    const int*   bidx  = (const int*)d_in[12];
    const int K = in_sizes[12] / (NBn - 1);   // block_idx is (127, K)
    float* out = (float*)d_out;

    float *X1, *X2, *ATT, *H, *T, *GO, *GM, *GL;
    cudaGetSymbolAddress((void**)&X1,  g_X1);
    cudaGetSymbolAddress((void**)&X2,  g_X2);
    cudaGetSymbolAddress((void**)&ATT, g_ATT);
    cudaGetSymbolAddress((void**)&H,   g_H);
    cudaGetSymbolAddress((void**)&T,   g_T);
    cudaGetSymbolAddress((void**)&GO,  g_GO);
    cudaGetSymbolAddress((void**)&GM,  g_GM);
    cudaGetSymbolAddress((void**)&GL,  g_GL);

    const int attn_smem = ATTN_SMEM_FLOATS * 4;  // ~103.7 KB
    cudaFuncSetAttribute(attn_sparse_kernel, cudaFuncAttributeMaxDynamicSharedMemorySize, attn_smem);
    cudaFuncSetAttribute(attn_global_partial, cudaFuncAttributeMaxDynamicSharedMemorySize, attn_smem);

    proj_ln_kernel<<<dim3(Sn/32, Bn, 2), 256>>>(src1, src2, wproj, bproj, g13, be13, X1, X2);

    attn_global_partial<<<dim3(NSPLIT, Bn), 256, attn_smem>>>(X1, X2, GO, GM, GL);
    attn_sparse_kernel<<<dim3(NBn-1, Bn), 256, attn_smem>>>(X1, X2, bidx, K, ATT);
    attn_global_combine<<<Bn, 256>>>(GO, GM, GL, ATT);

    add_ln_kernel<<<(Bn*Sn)/8, 256>>>(X1, ATT, g12, be12, H);

    ffn1_kernel<<<dim3((Bn*Sn)/32, DFFn/256), 256>>>(H, w1, b1, T);

    ffn2_kernel<<<(Bn*Sn)/32, 256>>>(T, w2, b2, H, out);
}

// round 3
// speedup vs baseline: 2.5803x; 1.1410x over previous
#include <cuda_runtime.h>
#include <math.h>

#define Bn   4
#define Cn   256
#define Sn   4096
#define DFFn 1024
#define NBn  128
#define BSn  32
#define NSPLIT 16

#define BSC (Bn*Sn*Cn)     // 4,194,304 floats
#define BST (Bn*Sn*DFFn)   // 16,777,216 floats

// ---- scratch ----
__device__ float g_X1[BSC];
__device__ float g_X2[BSC];
__device__ float g_ATT[BSC];
__device__ float g_H[BSC];
__device__ float g_T[BST];          // ffn hidden; also reused as proj raw output (2*BSC <= BST)
__device__ float g_GO[Bn*NSPLIT*32*256];
__device__ float g_GM[Bn*NSPLIT*32];
__device__ float g_GL[Bn*NSPLIT*32];

// ============================================================
// Shared 128x128x16 GEMM mainloop: 256 thr, 8x8 micro-tile.
// As[k][m] pad 132 (transposed stage), Bs[k][n] pad 132.
// ============================================================
#define APAD 132
#define GEMM_SMEM  (16*APAD*2)

__device__ __forceinline__ void gemm_mainloop(
    const float* __restrict__ A, int lda,   // A row-major [m][k], tile row m0 pre-offset
    const float* __restrict__ Bm, int ldb,  // B row-major [k][n], tile col n0 pre-offset
    int Ktot, float* As, float* Bs, float acc[64], int t)
{
    const int tm = t >> 4, tn = t & 15;
    for (int k0 = 0; k0 < Ktot; k0 += 16) {
#pragma unroll
        for (int l = 0; l < 2; l++) {
            int e = t + (l << 8);
            int m = e >> 2, kq = (e & 3) << 2;
            float4 v = *reinterpret_cast<const float4*>(A + m*lda + k0 + kq);
            As[(kq+0)*APAD + m] = v.x;
            As[(kq+1)*APAD + m] = v.y;
            As[(kq+2)*APAD + m] = v.z;
            As[(kq+3)*APAD + m] = v.w;
        }
#pragma unroll
        for (int l = 0; l < 2; l++) {
            int e = t + (l << 8);
            int k = e >> 5, nq = (e & 31) << 2;
            *reinterpret_cast<float4*>(Bs + k*APAD + nq) =
                *reinterpret_cast<const float4*>(Bm + (k0 + k)*ldb + nq);
        }
        __syncthreads();
#pragma unroll
        for (int kk = 0; kk < 16; kk++) {
            float4 a0 = *reinterpret_cast<const float4*>(As + kk*APAD + tm*8);
            float4 a1 = *reinterpret_cast<const float4*>(As + kk*APAD + tm*8 + 4);
            float4 b0 = *reinterpret_cast<const float4*>(Bs + kk*APAD + tn*8);
            float4 b1 = *reinterpret_cast<const float4*>(Bs + kk*APAD + tn*8 + 4);
            float av[8] = {a0.x,a0.y,a0.z,a0.w,a1.x,a1.y,a1.z,a1.w};
            float bv[8] = {b0.x,b0.y,b0.z,b0.w,b1.x,b1.y,b1.z,b1.w};
#pragma unroll
            for (int i = 0; i < 8; i++)
#pragma unroll
                for (int j = 0; j < 8; j++)
                    acc[i*8+j] += av[i]*bv[j];
        }
        __syncthreads();
    }
}

// ============================================================
// K1a: proj GEMM: Yraw[b][s][o] = sum_c W[o][c] src[b][c][s]
// grid (C/128=2, S/128=32, B*2), block 256. Yraw in g_T.
// ============================================================
__global__ __launch_bounds__(256, 2) void proj_gemm_kernel(
    const float* __restrict__ src1, const float* __restrict__ src2,
    const float* __restrict__ W)
{
    __shared__ float sm[GEMM_SMEM];
    float* As = sm; float* Bs = sm + 16*APAD;
    const int z = blockIdx.z;
    const int b = z >> 1, ssel = z & 1;
    const float* src = ssel ? src2 : src1;
    float* Yraw = g_T + ssel*BSC;
    const int m0 = blockIdx.x << 7;   // o
    const int n0 = blockIdx.y << 7;   // s
    const int t = threadIdx.x;
    const int tm = t >> 4, tn = t & 15;

    float acc[64];
#pragma unroll
    for (int i = 0; i < 64; i++) acc[i] = 0.f;

    gemm_mainloop(W + m0*Cn, Cn,
                  src + ((b*Cn) << 12) + n0, Sn,
                  Cn, As, Bs, acc, t);

    // write Yraw[b][s][o]
#pragma unroll
    for (int j = 0; j < 8; j++) {
        int s = n0 + tn*8 + j;
        float* row = Yraw + ((b << 12) + s)*256 + m0 + tm*8;
        float4 v0 = make_float4(acc[0*8+j], acc[1*8+j], acc[2*8+j], acc[3*8+j]);
        float4 v1 = make_float4(acc[4*8+j], acc[5*8+j], acc[6*8+j], acc[7*8+j]);
        reinterpret_cast<float4*>(row)[0] = v0;
        reinterpret_cast<float4*>(row)[1] = v1;
    }
}

// ============================================================
// K1b: LN over proj raw: X = LN(Yraw + b_proj). warp per row.
// grid (2*B*S/8), block 256
// ============================================================
__global__ __launch_bounds__(256) void proj_ln_kernel(
    const float* __restrict__ bias, const float* __restrict__ gam,
    const float* __restrict__ bet)
{
    const int gr   = (blockIdx.x << 3) + (threadIdx.x >> 5);  // 0..32767
    const int ssel = gr >= Bn*Sn;
    const int row  = ssel ? gr - Bn*Sn : gr;
    const float* Yraw = g_T + ssel*BSC;
    float* Xout       = ssel ? g_X2 : g_X1;
    const int lane = threadIdx.x & 31;
    const int base = row << 8;
    float v[8]; float sum = 0.f, sq = 0.f;
#pragma unroll
    for (int k = 0; k < 8; k++) {
        int o = lane + (k << 5);
        v[k] = Yraw[base + o] + bias[o];
        sum += v[k]; sq += v[k]*v[k];
    }
#pragma unroll
    for (int o = 16; o > 0; o >>= 1) {
        sum += __shfl_xor_sync(0xffffffffu, sum, o);
        sq  += __shfl_xor_sync(0xffffffffu, sq , o);
    }
    float mean = sum * (1.f/256.f);
    float var  = sq  * (1.f/256.f) - mean*mean;
    float rstd = rsqrtf(var + 1e-5f);
#pragma unroll
    for (int k = 0; k < 8; k++) {
        int o = lane + (k << 5);
        Xout[base + o] = (v[k] - mean)*rstd*gam[o] + bet[o];
    }
}

// ============================================================
// attention tile constants
// ============================================================
#define QP 257
#define VP 260
#define ATTN_SMEM_FLOATS (32*QP*2 + 32*VP + 32*33 + 96)

// ============================================================
// K2a: sparse rows (n = 1..127). grid (127, B), block 256, dyn smem
// ============================================================
__global__ __launch_bounds__(256) void attn_sparse_kernel(
    const float* __restrict__ X1, const float* __restrict__ X2,
    const int* __restrict__ bidx, int K, float* __restrict__ ATT)
{
    extern __shared__ float sm[];
    float* qsm  = sm;
    float* ksm  = qsm + 32*QP;
    float* vsm  = ksm + 32*QP;
    float* ssm  = vsm + 32*VP;
    float* mrow = ssm + 32*33;
    float* lrow = mrow + 32;
    float* arow = lrow + 32;

    const int b = blockIdx.y, n = blockIdx.x + 1;
    const int t = threadIdx.x;
    const int tx = t & 15, ty = t >> 4;
    const int qv = t >> 3, dbase = (t & 7) << 5;
    const int warp = t >> 5, lane = t & 31;

#pragma unroll
    for (int i = 0; i < 32; i++)
        qsm[i*QP + t] = X1[(((b << 12) + (n << 5) + i) << 8) + t];
    if (t < 32) { mrow[t] = -1e30f; lrow[t] = 0.f; }

    float out[32];
#pragma unroll
    for (int j = 0; j < 32; j++) out[j] = 0.f;
    __syncthreads();

    for (int it = 0; it < K; it++) {
        int kb = bidx[(n - 1)*K + it];
        if (it > 0 && kb == 0) break;
#pragma unroll
        for (int i = 0; i < 32; i++) {
            float val = X2[(((b << 12) + (kb << 5) + i) << 8) + t];
            ksm[i*QP + t] = val;
            vsm[i*VP + t] = val;
        }
        __syncthreads();

        float s00 = 0.f, s01 = 0.f, s10 = 0.f, s11 = 0.f;
        const float* q0 = qsm + (ty << 1)*QP;
        const float* q1 = q0 + QP;
        const float* k0 = ksm + (tx << 1)*QP;
        const float* k1 = k0 + QP;
#pragma unroll 8
        for (int d = 0; d < 256; d++) {
            float qa = q0[d], qb = q1[d], ka = k0[d], kc = k1[d];
            s00 += qa*ka; s01 += qa*kc; s10 += qb*ka; s11 += qb*kc;
        }
        const float scl = 0.0625f;
        ssm[(ty<<1)*33 + (tx<<1)    ] = s00*scl;
        ssm[(ty<<1)*33 + (tx<<1) + 1] = s01*scl;
        ssm[((ty<<1)+1)*33 + (tx<<1)    ] = s10*scl;
        ssm[((ty<<1)+1)*33 + (tx<<1) + 1] = s11*scl;
        __syncthreads();

#pragma unroll
        for (int r = 0; r < 4; r++) {
            int row = (warp << 2) + r;
            float sv = ssm[row*33 + lane];
            float mx = sv;
#pragma unroll
            for (int o = 16; o > 0; o >>= 1)
                mx = fmaxf(mx, __shfl_xor_sync(0xffffffffu, mx, o));
            float mold = mrow[row];
            float mnew = fmaxf(mold, mx);
            float p = __expf(sv - mnew);
            float ps = p;
#pragma unroll
            for (int o = 16; o > 0; o >>= 1)
                ps += __shfl_xor_sync(0xffffffffu, ps, o);
            if (lane == 0) {
                float a = __expf(mold - mnew);
                arow[row] = a;
                lrow[row] = lrow[row]*a + ps;
                mrow[row] = mnew;
            }
            ssm[row*33 + lane] = p;
        }
        __syncthreads();

        float alpha = arow[qv];
#pragma unroll
        for (int j = 0; j < 32; j++) out[j] *= alpha;
        const float* prow = ssm + qv*33;
#pragma unroll 4
        for (int k2 = 0; k2 < 32; k2++) {
            float p = prow[k2];
            const float4* vr = reinterpret_cast<const float4*>(vsm + k2*VP + dbase);
#pragma unroll
            for (int jj = 0; jj < 8; jj++) {
                float4 v4 = vr[jj];
                out[jj*4+0] += p*v4.x; out[jj*4+1] += p*v4.y;
                out[jj*4+2] += p*v4.z; out[jj*4+3] += p*v4.w;
            }
        }
        __syncthreads();
    }

    const float linv = 1.f / lrow[qv];
    const int base = (((b << 12) + (n << 5) + qv) << 8) + dbase;
#pragma unroll
    for (int j = 0; j < 32; j++) ATT[base + j] = out[j]*linv;
}

// ============================================================
// K2b: global rows (n=0), split-softmax partials. grid (NSPLIT, B)
// ============================================================
__global__ __launch_bounds__(256) void attn_global_partial(
    const float* __restrict__ X1, const float* __restrict__ X2,
    float* __restrict__ GO, float* __restrict__ GM, float* __restrict__ GL)
{
    extern __shared__ float sm[];
    float* qsm  = sm;
    float* ksm  = qsm + 32*QP;
    float* vsm  = ksm + 32*QP;
    float* ssm  = vsm + 32*VP;
    float* mrow = ssm + 32*33;
    float* lrow = mrow + 32;
    float* arow = lrow + 32;

    const int b = blockIdx.y, split = blockIdx.x;
    const int t = threadIdx.x;
    const int tx = t & 15, ty = t >> 4;
    const int qv = t >> 3, dbase = (t & 7) << 5;
    const int warp = t >> 5, lane = t & 31;

#pragma unroll
    for (int i = 0; i < 32; i++)
        qsm[i*QP + t] = X1[(((b << 12) + i) << 8) + t];
    if (t < 32) { mrow[t] = -1e30f; lrow[t] = 0.f; }

    float out[32];
#pragma unroll
    for (int j = 0; j < 32; j++) out[j] = 0.f;
    __syncthreads();

    for (int it = 0; it < NBn/NSPLIT; it++) {
        int kb = split*(NBn/NSPLIT) + it;
#pragma unroll
        for (int i = 0; i < 32; i++) {
            float val = X2[(((b << 12) + (kb << 5) + i) << 8) + t];
            ksm[i*QP + t] = val;
            vsm[i*VP + t] = val;
        }
        __syncthreads();

        float s00 = 0.f, s01 = 0.f, s10 = 0.f, s11 = 0.f;
        const float* q0 = qsm + (ty << 1)*QP;
        const float* q1 = q0 + QP;
        const float* k0 = ksm + (tx << 1)*QP;
        const float* k1 = k0 + QP;
#pragma unroll 8
        for (int d = 0; d < 256; d++) {
            float qa = q0[d], qb = q1[d], ka = k0[d], kc = k1[d];
            s00 += qa*ka; s01 += qa*kc; s10 += qb*ka; s11 += qb*kc;
        }
        const float scl = 0.0625f;
        ssm[(ty<<1)*33 + (tx<<1)    ] = s00*scl;
        ssm[(ty<<1)*33 + (tx<<1) + 1] = s01*scl;
        ssm[((ty<<1)+1)*33 + (tx<<1)    ] = s10*scl;
        ssm[((ty<<1)+1)*33 + (tx<<1) + 1] = s11*scl;
        __syncthreads();

#pragma unroll
        for (int r = 0; r < 4; r++) {
            int row = (warp << 2) + r;
            float sv = ssm[row*33 + lane];
            float mx = sv;
#pragma unroll
            for (int o = 16; o > 0; o >>= 1)
                mx = fmaxf(mx, __shfl_xor_sync(0xffffffffu, mx, o));
            float mold = mrow[row];
            float mnew = fmaxf(mold, mx);
            float p = __expf(sv - mnew);
            float ps = p;
#pragma unroll
            for (int o = 16; o > 0; o >>= 1)
                ps += __shfl_xor_sync(0xffffffffu, ps, o);
            if (lane == 0) {
                float a = __expf(mold - mnew);
                arow[row] = a;
                lrow[row] = lrow[row]*a + ps;
                mrow[row] = mnew;
            }
            ssm[row*33 + lane] = p;
        }
        __syncthreads();

        float alpha = arow[qv];
#pragma unroll
        for (int j = 0; j < 32; j++) out[j] *= alpha;
        const float* prow = ssm + qv*33;
#pragma unroll 4
        for (int k2 = 0; k2 < 32; k2++) {
            float p = prow[k2];
            const float4* vr = reinterpret_cast<const float4*>(vsm + k2*VP + dbase);
#pragma unroll
            for (int jj = 0; jj < 8; jj++) {
                float4 v4 = vr[jj];
                out[jj*4+0] += p*v4.x; out[jj*4+1] += p*v4.y;
                out[jj*4+2] += p*v4.z; out[jj*4+3] += p*v4.w;
            }
        }
        __syncthreads();
    }

    const int gi = (b*NSPLIT + split)*32;
    const int base = ((gi + qv) << 8) + dbase;
#pragma unroll
    for (int j = 0; j < 32; j++) GO[base + j] = out[j];
    if (t < 32) { GM[gi + t] = mrow[t]; GL[gi + t] = lrow[t]; }
}

// ============================================================
// K2c: combine. grid (B, 32), block 256: one (b,q) per block.
// ============================================================
__global__ __launch_bounds__(256) void attn_global_combine(
    const float* __restrict__ GO, const float* __restrict__ GM,
    const float* __restrict__ GL, float* __restrict__ ATT)
{
    const int b = blockIdx.x, q = blockIdx.y, t = threadIdx.x;
    float ms[NSPLIT], ls[NSPLIT];
    float M = -1e30f;
#pragma unroll
    for (int i = 0; i < NSPLIT; i++) {
        ms[i] = GM[(b*NSPLIT + i)*32 + q];
        ls[i] = GL[(b*NSPLIT + i)*32 + q];
        M = fmaxf(M, ms[i]);
    }
    float L = 0.f, acc = 0.f;
#pragma unroll
    for (int i = 0; i < NSPLIT; i++) {
        float e = __expf(ms[i] - M);
        L   += ls[i] * e;
        acc += GO[(((b*NSPLIT + i)*32 + q) << 8) + t] * e;
    }
    ATT[(((b << 12) + q) << 8) + t] = acc / L;
}

// ============================================================
// K3: H = LN(X1 + ATT). warp per row. grid = B*S/8, block 256
// ============================================================
__global__ __launch_bounds__(256) void add_ln_kernel(
    const float* __restrict__ X1, const float* __restrict__ ATT,
    const float* __restrict__ gam, const float* __restrict__ bet,
    float* __restrict__ H)
{
    const int row  = (blockIdx.x << 3) + (threadIdx.x >> 5);
    const int lane = threadIdx.x & 31;
    const int base = row << 8;
    float v[8]; float sum = 0.f, sq = 0.f;
#pragma unroll
    for (int k = 0; k < 8; k++) {
        int o = lane + (k << 5);
        v[k] = X1[base + o] + ATT[base + o];
        sum += v[k]; sq += v[k]*v[k];
    }
#pragma unroll
    for (int o = 16; o > 0; o >>= 1) {
        sum += __shfl_xor_sync(0xffffffffu, sum, o);
        sq  += __shfl_xor_sync(0xffffffffu, sq , o);
    }
    float mean = sum * (1.f/256.f);
    float var  = sq  * (1.f/256.f) - mean*mean;
    float rstd = rsqrtf(var + 1e-5f);
#pragma unroll
    for (int k = 0; k < 8; k++) {
        int o = lane + (k << 5);
        H[base + o] = (v[k] - mean)*rstd*gam[o] + bet[o];
    }
}

// ============================================================
// K4: T = gelu(H @ w1 + b1). grid (BS/128=128, DFF/128=8), block 256
// ============================================================
__global__ __launch_bounds__(256, 2) void ffn1_kernel(
    const float* __restrict__ H, const float* __restrict__ w1,
    const float* __restrict__ b1, float* __restrict__ T)
{
    __shared__ float sm[GEMM_SMEM];
    float* As = sm; float* Bs = sm + 16*APAD;
    const int m0 = blockIdx.x << 7;
    const int n0 = blockIdx.y << 7;
    const int t = threadIdx.x;
    const int tm = t >> 4, tn = t & 15;

    float acc[64];
#pragma unroll
    for (int i = 0; i < 64; i++) acc[i] = 0.f;

    gemm_mainloop(H + m0*Cn, Cn, w1 + n0, DFFn, Cn, As, Bs, acc, t);

    float bvv[8];
#pragma unroll
    for (int j = 0; j < 8; j++) bvv[j] = b1[n0 + tn*8 + j];
#pragma unroll
    for (int i = 0; i < 8; i++) {
        float* row = T + (m0 + tm*8 + i)*DFFn + n0 + tn*8;
        float g[8];
#pragma unroll
        for (int j = 0; j < 8; j++) {
            float x = acc[i*8+j] + bvv[j];
            g[j] = 0.5f*x*(1.f + erff(x*0.70710678118654752f));
        }
        reinterpret_cast<float4*>(row)[0] = make_float4(g[0],g[1],g[2],g[3]);
        reinterpret_cast<float4*>(row)[1] = make_float4(g[4],g[5],g[6],g[7]);
    }
}

// ============================================================
// K5: Out(B,C,S) = transpose(H + T @ w2 + b2).
// grid (BS/128=128, C/128=2), block 256
// ============================================================
__global__ __launch_bounds__(256, 2) void ffn2_kernel(
    const float* __restrict__ T, const float* __restrict__ w2,
    const float* __restrict__ b2, const float* __restrict__ H,
    float* __restrict__ Out)
{
    __shared__ float sm[GEMM_SMEM];
    float* As = sm; float* Bs = sm + 16*APAD;
    const int m0 = blockIdx.x << 7;     // global row (b*4096 + s)
    const int n0 = blockIdx.y << 7;     // channel c
    const int t = threadIdx.x;
    const int tm = t >> 4, tn = t & 15;

    float acc[64];
#pragma unroll
    for (int i = 0; i < 64; i++) acc[i] = 0.f;

    gemm_mainloop(T + m0*DFFn, DFFn, w2 + n0, Cn, DFFn, As, Bs, acc, t);

    float bvv[8];
#pragma unroll
    for (int j = 0; j < 8; j++) bvv[j] = b2[n0 + tn*8 + j];
    // residual add (H row-major read)
#pragma unroll
    for (int i = 0; i < 8; i++) {
        const float* hrow = H + (m0 + tm*8 + i)*Cn + n0 + tn*8;
        float4 h0 = reinterpret_cast<const float4*>(hrow)[0];
        float4 h1 = reinterpret_cast<const float4*>(hrow)[1];
        acc[i*8+0] += bvv[0] + h0.x; acc[i*8+1] += bvv[1] + h0.y;
        acc[i*8+2] += bvv[2] + h0.z; acc[i*8+3] += bvv[3] + h0.w;
        acc[i*8+4] += bvv[4] + h1.x; acc[i*8+5] += bvv[5] + h1.y;
        acc[i*8+6] += bvv[6] + h1.z; acc[i*8+7] += bvv[7] + h1.w;
    }
    // transposed write: Out[(b, c, s)]; m rows contiguous in s within batch
    const int b  = m0 >> 12;
    const int s0 = (m0 & 4095) + tm*8;
#pragma unroll
    for (int j = 0; j < 8; j++) {
        int c = n0 + tn*8 + j;
        float* orow = Out + (((b << 8) + c) << 12) + s0;
        reinterpret_cast<float4*>(orow)[0] =
            make_float4(acc[0*8+j], acc[1*8+j], acc[2*8+j], acc[3*8+j]);
        reinterpret_cast<float4*>(orow)[1] =
            make_float4(acc[4*8+j], acc[5*8+j], acc[6*8+j], acc[7*8+j]);
    }
}

// ============================================================
extern "C" void kernel_launch(void* const* d_in, const int* in_sizes, int n_in,
                              void* d_out, int out_size)
{
    const float* src1  = (const float*)d_in[0];
    const float* src2  = (const float*)d_in[1];
    const float* wproj = (const float*)d_in[2];
    const float* bproj = (const float*)d_in[3];
    const float* g13   = (const float*)d_in[4];
    const float* be13  = (const float*)d_in[5];
    const float* g12   = (const float*)d_in[6];
    const float* be12  = (const float*)d_in[7];
    const float* w1    = (const float*)d_in[8];
    const float* b1    = (const float*)d_in[9];
    const float* w2    = (const float*)d_in[10];
    const float* b2    = (const float*)d_in[11];
    const int*   bidx  = (const int*)d_in[12];
    const int K = in_sizes[12] / (NBn - 1);
    float* out = (float*)d_out;

    float *X1, *X2, *ATT, *H, *T, *GO, *GM, *GL;
    cudaGetSymbolAddress((void**)&X1,  g_X1);
    cudaGetSymbolAddress((void**)&X2,  g_X2);
    cudaGetSymbolAddress((void**)&ATT, g_ATT);
    cudaGetSymbolAddress((void**)&H,   g_H);
    cudaGetSymbolAddress((void**)&T,   g_T);
    cudaGetSymbolAddress((void**)&GO,  g_GO);
    cudaGetSymbolAddress((void**)&GM,  g_GM);
    cudaGetSymbolAddress((void**)&GL,  g_GL);

    const int attn_smem = ATTN_SMEM_FLOATS * 4;
    cudaFuncSetAttribute(attn_sparse_kernel, cudaFuncAttributeMaxDynamicSharedMemorySize, attn_smem);
    cudaFuncSetAttribute(attn_global_partial, cudaFuncAttributeMaxDynamicSharedMemorySize, attn_smem);

    proj_gemm_kernel<<<dim3(2, 32, Bn*2), 256>>>(src1, src2, wproj);
    proj_ln_kernel<<<(2*Bn*Sn)/8, 256>>>(bproj, g13, be13);

    attn_global_partial<<<dim3(NSPLIT, Bn), 256, attn_smem>>>(X1, X2, GO, GM, GL);
    attn_sparse_kernel<<<dim3(NBn-1, Bn), 256, attn_smem>>>(X1, X2, bidx, K, ATT);
    attn_global_combine<<<dim3(Bn, 32), 256>>>(GO, GM, GL, ATT);

    add_ln_kernel<<<(Bn*Sn)/8, 256>>>(X1, ATT, g12, be12, H);

    ffn1_kernel<<<dim3((Bn*Sn)/128, DFFn/128), 256>>>(H, w1, b1, T);

    ffn2_kernel<<<dim3((Bn*Sn)/128, Cn/128), 256>>>(T, w2, b2, H, out);
}

// round 5
// speedup vs baseline: 5.9693x; 2.3135x over previous
#include <cuda_runtime.h>
#include <math.h>

#define Bn   4
#define Cn   256
#define Sn   4096
#define DFFn 1024
#define NBn  128
#define BSn  32
#define NSPLIT 16

#define BSC (Bn*Sn*Cn)     // 4,194,304 floats
#define BST (Bn*Sn*DFFn)   // 16,777,216 floats

// ---- scratch ----
__device__ float g_X1[BSC];
__device__ float g_X2[BSC];
__device__ float g_ATT[BSC];
__device__ float g_H[BSC];
__device__ float g_T[BST];          // ffn hidden; reused as proj raw output
__device__ float g_GO[Bn*NSPLIT*32*256];
__device__ float g_GM[Bn*NSPLIT*32];
__device__ float g_GL[Bn*NSPLIT*32];

// ============================================================
// 128x128x16 GEMM mainloop, 256 thr, 8x8 micro-tile, reg-prefetch pipeline.
// ============================================================
#define APAD 132
#define GEMM_SMEM  (16*APAD*2)

__device__ __forceinline__ void gemm_mainloop(
    const float* __restrict__ A, int lda,   // A row-major [m][k], tile row pre-offset
    const float* __restrict__ Bm, int ldb,  // B row-major [k][n], tile col pre-offset
    int Ktot, float* As, float* Bs, float acc[64], int t)
{
    const int tm = t >> 4, tn = t & 15;
    const int am0 = t >> 2,  akq = (t & 3) << 2;
    const int am1 = (t + 256) >> 2;
    const int bk0 = t >> 5,  bnq = (t & 31) << 2;
    const int bk1 = (t + 256) >> 5;

    float4 pa0, pa1, pb0, pb1;
    pa0 = *reinterpret_cast<const float4*>(A + am0*lda + akq);
    pa1 = *reinterpret_cast<const float4*>(A + am1*lda + akq);
    pb0 = *reinterpret_cast<const float4*>(Bm + bk0*ldb + bnq);
    pb1 = *reinterpret_cast<const float4*>(Bm + bk1*ldb + bnq);

    for (int k0 = 0; k0 < Ktot; k0 += 16) {
        As[(akq+0)*APAD + am0] = pa0.x;  As[(akq+1)*APAD + am0] = pa0.y;
        As[(akq+2)*APAD + am0] = pa0.z;  As[(akq+3)*APAD + am0] = pa0.w;
        As[(akq+0)*APAD + am1] = pa1.x;  As[(akq+1)*APAD + am1] = pa1.y;
        As[(akq+2)*APAD + am1] = pa1.z;  As[(akq+3)*APAD + am1] = pa1.w;
        *reinterpret_cast<float4*>(Bs + bk0*APAD + bnq) = pb0;
        *reinterpret_cast<float4*>(Bs + bk1*APAD + bnq) = pb1;
        __syncthreads();

        if (k0 + 16 < Ktot) {
            pa0 = *reinterpret_cast<const float4*>(A + am0*lda + k0 + 16 + akq);
            pa1 = *reinterpret_cast<const float4*>(A + am1*lda + k0 + 16 + akq);
            pb0 = *reinterpret_cast<const float4*>(Bm + (k0 + 16 + bk0)*ldb + bnq);
            pb1 = *reinterpret_cast<const float4*>(Bm + (k0 + 16 + bk1)*ldb + bnq);
        }

#pragma unroll
        for (int kk = 0; kk < 16; kk++) {
            float4 a0 = *reinterpret_cast<const float4*>(As + kk*APAD + tm*8);
            float4 a1 = *reinterpret_cast<const float4*>(As + kk*APAD + tm*8 + 4);
            float4 b0 = *reinterpret_cast<const float4*>(Bs + kk*APAD + tn*8);
            float4 b1 = *reinterpret_cast<const float4*>(Bs + kk*APAD + tn*8 + 4);
            float av[8] = {a0.x,a0.y,a0.z,a0.w,a1.x,a1.y,a1.z,a1.w};
            float bv[8] = {b0.x,b0.y,b0.z,b0.w,b1.x,b1.y,b1.z,b1.w};
#pragma unroll
            for (int i = 0; i < 8; i++)
#pragma unroll
                for (int j = 0; j < 8; j++)
                    acc[i*8+j] += av[i]*bv[j];
        }
        __syncthreads();
    }
}

// ============================================================
// K1a: proj GEMM: Yraw[b][s][o] = sum_c W[o][c] src[b][c][s]
// grid (C/128=2, S/128=32, B*2), block 256
// ============================================================
__global__ __launch_bounds__(256, 2) void proj_gemm_kernel(
    const float* __restrict__ src1, const float* __restrict__ src2,
    const float* __restrict__ W)
{
    __shared__ float sm[GEMM_SMEM];
    float* As = sm; float* Bs = sm + 16*APAD;
    const int z = blockIdx.z;
    const int b = z >> 1, ssel = z & 1;
    const float* src = ssel ? src2 : src1;
    float* Yraw = g_T + ssel*BSC;
    const int m0 = blockIdx.x << 7;   // o
    const int n0 = blockIdx.y << 7;   // s
    const int t = threadIdx.x;
    const int tm = t >> 4, tn = t & 15;

    float acc[64];
#pragma unroll
    for (int i = 0; i < 64; i++) acc[i] = 0.f;

    gemm_mainloop(W + m0*Cn, Cn,
                  src + ((b*Cn) << 12) + n0, Sn,
                  Cn, As, Bs, acc, t);

#pragma unroll
    for (int j = 0; j < 8; j++) {
        int s = n0 + tn*8 + j;
        float* row = Yraw + ((b << 12) + s)*256 + m0 + tm*8;
        reinterpret_cast<float4*>(row)[0] =
            make_float4(acc[0*8+j], acc[1*8+j], acc[2*8+j], acc[3*8+j]);
        reinterpret_cast<float4*>(row)[1] =
            make_float4(acc[4*8+j], acc[5*8+j], acc[6*8+j], acc[7*8+j]);
    }
}

// ============================================================
// K1b: LN over proj raw. warp per row. grid (2*B*S/8), block 256
// ============================================================
__global__ __launch_bounds__(256) void proj_ln_kernel(
    const float* __restrict__ bias, const float* __restrict__ gam,
    const float* __restrict__ bet)
{
    const int gr   = (blockIdx.x << 3) + (threadIdx.x >> 5);
    const int ssel = gr >= Bn*Sn;
    const int row  = ssel ? gr - Bn*Sn : gr;
    const float* Yraw = g_T + ssel*BSC;
    float* Xout       = ssel ? g_X2 : g_X1;
    const int lane = threadIdx.x & 31;
    const int base = row << 8;
    float v[8]; float sum = 0.f, sq = 0.f;
#pragma unroll
    for (int k = 0; k < 8; k++) {
        int o = lane + (k << 5);
        v[k] = Yraw[base + o] + bias[o];
        sum += v[k]; sq += v[k]*v[k];
    }
#pragma unroll
    for (int o = 16; o > 0; o >>= 1) {
        sum += __shfl_xor_sync(0xffffffffu, sum, o);
        sq  += __shfl_xor_sync(0xffffffffu, sq , o);
    }
    float mean = sum * (1.f/256.f);
    float var  = sq  * (1.f/256.f) - mean*mean;
    float rstd = rsqrtf(var + 1e-5f);
#pragma unroll
    for (int k = 0; k < 8; k++) {
        int o = lane + (k << 5);
        Xout[base + o] = (v[k] - mean)*rstd*gam[o] + bet[o];
    }
}

// ============================================================
// attention: single K/V tile (stride 257), scalar conflict-free PV.
// smem = 32*QP (Q) + 32*QP (K=V) + 32*33 (S) + 96 = 70.4 KB -> 3 CTA/SM
// ============================================================
#define QP 257
#define ATTN_SMEM_FLOATS (32*QP*2 + 32*33 + 96)

__device__ __forceinline__ void attn_tile(
    const float* __restrict__ X2, int b, int kb, int t,
    float* qsm, float* ksm, float* ssm,
    float* mrow, float* lrow, float* arow, float out[32])
{
    const int tx = t & 15, ty = t >> 4;
    const int qv = t >> 3, dcol = (t & 7) << 2;
    const int warp = t >> 5, lane = t & 31;

#pragma unroll
    for (int i = 0; i < 32; i++)
        ksm[i*QP + t] = X2[(((b << 12) + (kb << 5) + i) << 8) + t];
    __syncthreads();

    float s00 = 0.f, s01 = 0.f, s10 = 0.f, s11 = 0.f;
    const float* q0 = qsm + (ty << 1)*QP;
    const float* q1 = q0 + QP;
    const float* k0 = ksm + (tx << 1)*QP;
    const float* k1 = k0 + QP;
#pragma unroll 8
    for (int d = 0; d < 256; d++) {
        float qa = q0[d], qb = q1[d], ka = k0[d], kc = k1[d];
        s00 += qa*ka; s01 += qa*kc; s10 += qb*ka; s11 += qb*kc;
    }
    const float scl = 0.0625f;
    ssm[(ty<<1)*33 + (tx<<1)    ] = s00*scl;
    ssm[(ty<<1)*33 + (tx<<1) + 1] = s01*scl;
    ssm[((ty<<1)+1)*33 + (tx<<1)    ] = s10*scl;
    ssm[((ty<<1)+1)*33 + (tx<<1) + 1] = s11*scl;
    __syncthreads();

#pragma unroll
    for (int r = 0; r < 4; r++) {
        int row = (warp << 2) + r;
        float sv = ssm[row*33 + lane];
        float mx = sv;
#pragma unroll
        for (int o = 16; o > 0; o >>= 1)
            mx = fmaxf(mx, __shfl_xor_sync(0xffffffffu, mx, o));
        float mold = mrow[row];
        float mnew = fmaxf(mold, mx);
        float p = __expf(sv - mnew);
        float ps = p;
#pragma unroll
        for (int o = 16; o > 0; o >>= 1)
            ps += __shfl_xor_sync(0xffffffffu, ps, o);
        if (lane == 0) {
            float a = __expf(mold - mnew);
            arow[row] = a;
            lrow[row] = lrow[row]*a + ps;
            mrow[row] = mnew;
        }
        ssm[row*33 + lane] = p;
    }
    __syncthreads();

    // PV: thread owns q=qv, d = dcol + 32*jj + c. SCALAR loads:
    // bank = (k2 + dcol + c) mod 32 -> 8 distinct banks + 4-way broadcast
    // = conflict-free, and no alignment hazard (stride 257).
    float alpha = arow[qv];
#pragma unroll
    for (int j = 0; j < 32; j++) out[j] *= alpha;
    const float* prow = ssm + qv*33;
#pragma unroll 4
    for (int k2 = 0; k2 < 32; k2++) {
        float p = prow[k2];
        const float* vb = ksm + k2*QP + dcol;
#pragma unroll
        for (int jj = 0; jj < 8; jj++) {
            out[jj*4+0] += p*vb[(jj<<5)+0];
            out[jj*4+1] += p*vb[(jj<<5)+1];
            out[jj*4+2] += p*vb[(jj<<5)+2];
            out[jj*4+3] += p*vb[(jj<<5)+3];
        }
    }
    __syncthreads();
}

// K2a: sparse rows (n = 1..127). grid (127, B), block 256
__global__ __launch_bounds__(256) void attn_sparse_kernel(
    const float* __restrict__ X1, const float* __restrict__ X2,
    const int* __restrict__ bidx, int K, float* __restrict__ ATT)
{
    extern __shared__ float sm[];
    float* qsm  = sm;
    float* ksm  = qsm + 32*QP;
    float* ssm  = ksm + 32*QP;
    float* mrow = ssm + 32*33;
    float* lrow = mrow + 32;
    float* arow = lrow + 32;

    const int b = blockIdx.y, n = blockIdx.x + 1;
    const int t = threadIdx.x;
    const int qv = t >> 3, dcol = (t & 7) << 2;

#pragma unroll
    for (int i = 0; i < 32; i++)
        qsm[i*QP + t] = X1[(((b << 12) + (n << 5) + i) << 8) + t];
    if (t < 32) { mrow[t] = -1e30f; lrow[t] = 0.f; }

    float out[32];
#pragma unroll
    for (int j = 0; j < 32; j++) out[j] = 0.f;
    __syncthreads();

    for (int it = 0; it < K; it++) {
        int kb = bidx[(n - 1)*K + it];
        if (it > 0 && kb == 0) break;
        attn_tile(X2, b, kb, t, qsm, ksm, ssm, mrow, lrow, arow, out);
    }

    const float linv = 1.f / lrow[qv];
    const int base = (((b << 12) + (n << 5) + qv) << 8) + dcol;
#pragma unroll
    for (int jj = 0; jj < 8; jj++) {
        *reinterpret_cast<float4*>(ATT + base + (jj << 5)) =
            make_float4(out[jj*4+0]*linv, out[jj*4+1]*linv,
                        out[jj*4+2]*linv, out[jj*4+3]*linv);
    }
}

// K2b: global rows (n=0), split-softmax partials. grid (NSPLIT, B)
__global__ __launch_bounds__(256) void attn_global_partial(
    const float* __restrict__ X1, const float* __restrict__ X2,
    float* __restrict__ GO, float* __restrict__ GM, float* __restrict__ GL)
{
    extern __shared__ float sm[];
    float* qsm  = sm;
    float* ksm  = qsm + 32*QP;
    float* ssm  = ksm + 32*QP;
    float* mrow = ssm + 32*33;
    float* lrow = mrow + 32;
    float* arow = lrow + 32;

    const int b = blockIdx.y, split = blockIdx.x;
    const int t = threadIdx.x;
    const int qv = t >> 3, dcol = (t & 7) << 2;

#pragma unroll
    for (int i = 0; i < 32; i++)
        qsm[i*QP + t] = X1[(((b << 12) + i) << 8) + t];
    if (t < 32) { mrow[t] = -1e30f; lrow[t] = 0.f; }

    float out[32];
#pragma unroll
    for (int j = 0; j < 32; j++) out[j] = 0.f;
    __syncthreads();

    for (int it = 0; it < NBn/NSPLIT; it++) {
        int kb = split*(NBn/NSPLIT) + it;
        attn_tile(X2, b, kb, t, qsm, ksm, ssm, mrow, lrow, arow, out);
    }

    const int gi = (b*NSPLIT + split)*32;
    const int base = ((gi + qv) << 8) + dcol;
#pragma unroll
    for (int jj = 0; jj < 8; jj++) {
        *reinterpret_cast<float4*>(GO + base + (jj << 5)) =
            make_float4(out[jj*4+0], out[jj*4+1], out[jj*4+2], out[jj*4+3]);
    }
    if (t < 32) { GM[gi + t] = mrow[t]; GL[gi + t] = lrow[t]; }
}

// K2c: combine. grid (B, 32), block 256
__global__ __launch_bounds__(256) void attn_global_combine(
    const float* __restrict__ GO, const float* __restrict__ GM,
    const float* __restrict__ GL, float* __restrict__ ATT)
{
    const int b = blockIdx.x, q = blockIdx.y, t = threadIdx.x;
    float ms[NSPLIT], ls[NSPLIT];
    float M = -1e30f;
#pragma unroll
    for (int i = 0; i < NSPLIT; i++) {
        ms[i] = GM[(b*NSPLIT + i)*32 + q];
        ls[i] = GL[(b*NSPLIT + i)*32 + q];
        M = fmaxf(M, ms[i]);
    }
    float L = 0.f, acc = 0.f;
#pragma unroll
    for (int i = 0; i < NSPLIT; i++) {
        float e = __expf(ms[i] - M);
        L   += ls[i] * e;
        acc += GO[(((b*NSPLIT + i)*32 + q) << 8) + t] * e;
    }
    ATT[(((b << 12) + q) << 8) + t] = acc / L;
}

// ============================================================
// K3: H = LN(X1 + ATT). warp per row. grid = B*S/8, block 256
// ============================================================
__global__ __launch_bounds__(256) void add_ln_kernel(
    const float* __restrict__ X1, const float* __restrict__ ATT,
    const float* __restrict__ gam, const float* __restrict__ bet,
    float* __restrict__ H)
{
    const int row  = (blockIdx.x << 3) + (threadIdx.x >> 5);
    const int lane = threadIdx.x & 31;
    const int base = row << 8;
    float v[8]; float sum = 0.f, sq = 0.f;
#pragma unroll
    for (int k = 0; k < 8; k++) {
        int o = lane + (k << 5);
        v[k] = X1[base + o] + ATT[base + o];
        sum += v[k]; sq += v[k]*v[k];
    }
#pragma unroll
    for (int o = 16; o > 0; o >>= 1) {
        sum += __shfl_xor_sync(0xffffffffu, sum, o);
        sq  += __shfl_xor_sync(0xffffffffu, sq , o);
    }
    float mean = sum * (1.f/256.f);
    float var  = sq  * (1.f/256.f) - mean*mean;
    float rstd = rsqrtf(var + 1e-5f);
#pragma unroll
    for (int k = 0; k < 8; k++) {
        int o = lane + (k << 5);
        H[base + o] = (v[k] - mean)*rstd*gam[o] + bet[o];
    }
}

// ============================================================
// K4: T = gelu(H @ w1 + b1). grid (BS/128, DFF/128), block 256
// ============================================================
__global__ __launch_bounds__(256, 2) void ffn1_kernel(
    const float* __restrict__ H, const float* __restrict__ w1,
    const float* __restrict__ b1, float* __restrict__ T)
{
    __shared__ float sm[GEMM_SMEM];
    float* As = sm; float* Bs = sm + 16*APAD;
    const int m0 = blockIdx.x << 7;
    const int n0 = blockIdx.y << 7;
    const int t = threadIdx.x;
    const int tm = t >> 4, tn = t & 15;

    float acc[64];
#pragma unroll
    for (int i = 0; i < 64; i++) acc[i] = 0.f;

    gemm_mainloop(H + m0*Cn, Cn, w1 + n0, DFFn, Cn, As, Bs, acc, t);

    float bvv[8];
#pragma unroll
    for (int j = 0; j < 8; j++) bvv[j] = b1[n0 + tn*8 + j];
#pragma unroll
    for (int i = 0; i < 8; i++) {
        float* row = T + (m0 + tm*8 + i)*DFFn + n0 + tn*8;
        float g[8];
#pragma unroll
        for (int j = 0; j < 8; j++) {
            float x = acc[i*8+j] + bvv[j];
            g[j] = 0.5f*x*(1.f + erff(x*0.70710678118654752f));
        }
        reinterpret_cast<float4*>(row)[0] = make_float4(g[0],g[1],g[2],g[3]);
        reinterpret_cast<float4*>(row)[1] = make_float4(g[4],g[5],g[6],g[7]);
    }
}

// ============================================================
// K5: Out(B,C,S) = transpose(H + T @ w2 + b2). grid (BS/128, C/128)
// ============================================================
__global__ __launch_bounds__(256, 2) void ffn2_kernel(
    const float* __restrict__ T, const float* __restrict__ w2,
    const float* __restrict__ b2, const float* __restrict__ H,
    float* __restrict__ Out)
{
    __shared__ float sm[GEMM_SMEM];
    float* As = sm; float* Bs = sm + 16*APAD;
    const int m0 = blockIdx.x << 7;
    const int n0 = blockIdx.y << 7;
    const int t = threadIdx.x;
    const int tm = t >> 4, tn = t & 15;

    float acc[64];
#pragma unroll
    for (int i = 0; i < 64; i++) acc[i] = 0.f;

    gemm_mainloop(T + m0*DFFn, DFFn, w2 + n0, Cn, DFFn, As, Bs, acc, t);

    float bvv[8];
#pragma unroll
    for (int j = 0; j < 8; j++) bvv[j] = b2[n0 + tn*8 + j];
#pragma unroll
    for (int i = 0; i < 8; i++) {
        const float* hrow = H + (m0 + tm*8 + i)*Cn + n0 + tn*8;
        float4 h0 = reinterpret_cast<const float4*>(hrow)[0];
        float4 h1 = reinterpret_cast<const float4*>(hrow)[1];
        acc[i*8+0] += bvv[0] + h0.x; acc[i*8+1] += bvv[1] + h0.y;
        acc[i*8+2] += bvv[2] + h0.z; acc[i*8+3] += bvv[3] + h0.w;
        acc[i*8+4] += bvv[4] + h1.x; acc[i*8+5] += bvv[5] + h1.y;
        acc[i*8+6] += bvv[6] + h1.z; acc[i*8+7] += bvv[7] + h1.w;
    }
    const int b  = m0 >> 12;
    const int s0 = (m0 & 4095) + tm*8;
#pragma unroll
    for (int j = 0; j < 8; j++) {
        int c = n0 + tn*8 + j;
        float* orow = Out + (((b << 8) + c) << 12) + s0;
        reinterpret_cast<float4*>(orow)[0] =
            make_float4(acc[0*8+j], acc[1*8+j], acc[2*8+j], acc[3*8+j]);
        reinterpret_cast<float4*>(orow)[1] =
            make_float4(acc[4*8+j], acc[5*8+j], acc[6*8+j], acc[7*8+j]);
    }
}

// ============================================================
extern "C" void kernel_launch(void* const* d_in, const int* in_sizes, int n_in,
                              void* d_out, int out_size)
{
    const float* src1  = (const float*)d_in[0];
    const float* src2  = (const float*)d_in[1];
    const float* wproj = (const float*)d_in[2];
    const float* bproj = (const float*)d_in[3];
    const float* g13   = (const float*)d_in[4];
    const float* be13  = (const float*)d_in[5];
    const float* g12   = (const float*)d_in[6];
    const float* be12  = (const float*)d_in[7];
    const float* w1    = (const float*)d_in[8];
    const float* b1    = (const float*)d_in[9];
    const float* w2    = (const float*)d_in[10];
    const float* b2    = (const float*)d_in[11];
    const int*   bidx  = (const int*)d_in[12];
    const int K = in_sizes[12] / (NBn - 1);
    float* out = (float*)d_out;

    float *X1, *X2, *ATT, *H, *T, *GO, *GM, *GL;
    cudaGetSymbolAddress((void**)&X1,  g_X1);
    cudaGetSymbolAddress((void**)&X2,  g_X2);
    cudaGetSymbolAddress((void**)&ATT, g_ATT);
    cudaGetSymbolAddress((void**)&H,   g_H);
    cudaGetSymbolAddress((void**)&T,   g_T);
    cudaGetSymbolAddress((void**)&GO,  g_GO);
    cudaGetSymbolAddress((void**)&GM,  g_GM);
    cudaGetSymbolAddress((void**)&GL,  g_GL);

    const int attn_smem = ATTN_SMEM_FLOATS * 4;   // 70,400 B -> 3 CTA/SM
    cudaFuncSetAttribute(attn_sparse_kernel, cudaFuncAttributeMaxDynamicSharedMemorySize, attn_smem);
    cudaFuncSetAttribute(attn_global_partial, cudaFuncAttributeMaxDynamicSharedMemorySize, attn_smem);

    proj_gemm_kernel<<<dim3(2, 32, Bn*2), 256>>>(src1, src2, wproj);
    proj_ln_kernel<<<(2*Bn*Sn)/8, 256>>>(bproj, g13, be13);

    attn_global_partial<<<dim3(NSPLIT, Bn), 256, attn_smem>>>(X1, X2, GO, GM, GL);
    attn_sparse_kernel<<<dim3(NBn-1, Bn), 256, attn_smem>>>(X1, X2, bidx, K, ATT);
    attn_global_combine<<<dim3(Bn, 32), 256>>>(GO, GM, GL, ATT);

    add_ln_kernel<<<(Bn*Sn)/8, 256>>>(X1, ATT, g12, be12, H);

    ffn1_kernel<<<dim3((Bn*Sn)/128, DFFn/128), 256>>>(H, w1, b1, T);

    ffn2_kernel<<<dim3((Bn*Sn)/128, Cn/128), 256>>>(T, w2, b2, H, out);
}

// round 6
// speedup vs baseline: 6.2616x; 1.0490x over previous
#include <cuda_runtime.h>
#include <math.h>

#define Bn   4
#define Cn   256
#define Sn   4096
#define DFFn 1024
#define NBn  128
#define BSn  32
#define NSPLIT 16

#define BSC (Bn*Sn*Cn)
#define BST (Bn*Sn*DFFn)

// ---- scratch ----
__device__ float g_X1[BSC];
__device__ float g_X2[BSC];
__device__ float g_ATT[BSC];
__device__ float g_H[BSC];
__device__ float g_T[BST];
__device__ float g_GO[Bn*NSPLIT*32*256];
__device__ float g_GM[Bn*NSPLIT*32];
__device__ float g_GL[Bn*NSPLIT*32];

// ============================================================
// 128x128x16 GEMM mainloop, 256 thr, 8x8 micro-tile, reg-prefetch.
// ============================================================
#define APAD 132
#define GEMM_SMEM  (16*APAD*2)

__device__ __forceinline__ void gemm_mainloop(
    const float* __restrict__ A, int lda,
    const float* __restrict__ Bm, int ldb,
    int Ktot, float* As, float* Bs, float acc[64], int t)
{
    const int tm = t >> 4, tn = t & 15;
    const int am0 = t >> 2,  akq = (t & 3) << 2;
    const int am1 = (t + 256) >> 2;
    const int bk0 = t >> 5,  bnq = (t & 31) << 2;
    const int bk1 = (t + 256) >> 5;

    float4 pa0, pa1, pb0, pb1;
    pa0 = *reinterpret_cast<const float4*>(A + am0*lda + akq);
    pa1 = *reinterpret_cast<const float4*>(A + am1*lda + akq);
    pb0 = *reinterpret_cast<const float4*>(Bm + bk0*ldb + bnq);
    pb1 = *reinterpret_cast<const float4*>(Bm + bk1*ldb + bnq);

    for (int k0 = 0; k0 < Ktot; k0 += 16) {
        As[(akq+0)*APAD + am0] = pa0.x;  As[(akq+1)*APAD + am0] = pa0.y;
        As[(akq+2)*APAD + am0] = pa0.z;  As[(akq+3)*APAD + am0] = pa0.w;
        As[(akq+0)*APAD + am1] = pa1.x;  As[(akq+1)*APAD + am1] = pa1.y;
        As[(akq+2)*APAD + am1] = pa1.z;  As[(akq+3)*APAD + am1] = pa1.w;
        *reinterpret_cast<float4*>(Bs + bk0*APAD + bnq) = pb0;
        *reinterpret_cast<float4*>(Bs + bk1*APAD + bnq) = pb1;
        __syncthreads();

        if (k0 + 16 < Ktot) {
            pa0 = *reinterpret_cast<const float4*>(A + am0*lda + k0 + 16 + akq);
            pa1 = *reinterpret_cast<const float4*>(A + am1*lda + k0 + 16 + akq);
            pb0 = *reinterpret_cast<const float4*>(Bm + (k0 + 16 + bk0)*ldb + bnq);
            pb1 = *reinterpret_cast<const float4*>(Bm + (k0 + 16 + bk1)*ldb + bnq);
        }

#pragma unroll
        for (int kk = 0; kk < 16; kk++) {
            float4 a0 = *reinterpret_cast<const float4*>(As + kk*APAD + tm*8);
            float4 a1 = *reinterpret_cast<const float4*>(As + kk*APAD + tm*8 + 4);
            float4 b0 = *reinterpret_cast<const float4*>(Bs + kk*APAD + tn*8);
            float4 b1 = *reinterpret_cast<const float4*>(Bs + kk*APAD + tn*8 + 4);
            float av[8] = {a0.x,a0.y,a0.z,a0.w,a1.x,a1.y,a1.z,a1.w};
            float bv[8] = {b0.x,b0.y,b0.z,b0.w,b1.x,b1.y,b1.z,b1.w};
#pragma unroll
            for (int i = 0; i < 8; i++)
#pragma unroll
                for (int j = 0; j < 8; j++)
                    acc[i*8+j] += av[i]*bv[j];
        }
        __syncthreads();
    }
}

// ============================================================
// K1a: proj GEMM. grid (2, 32, B*2), block 256
// ============================================================
__global__ __launch_bounds__(256, 2) void proj_gemm_kernel(
    const float* __restrict__ src1, const float* __restrict__ src2,
    const float* __restrict__ W)
{
    __shared__ float sm[GEMM_SMEM];
    float* As = sm; float* Bs = sm + 16*APAD;
    const int z = blockIdx.z;
    const int b = z >> 1, ssel = z & 1;
    const float* src = ssel ? src2 : src1;
    float* Yraw = g_T + ssel*BSC;
    const int m0 = blockIdx.x << 7;
    const int n0 = blockIdx.y << 7;
    const int t = threadIdx.x;
    const int tm = t >> 4, tn = t & 15;

    float acc[64];
#pragma unroll
    for (int i = 0; i < 64; i++) acc[i] = 0.f;

    gemm_mainloop(W + m0*Cn, Cn, src + ((b*Cn) << 12) + n0, Sn, Cn, As, Bs, acc, t);

#pragma unroll
    for (int j = 0; j < 8; j++) {
        int s = n0 + tn*8 + j;
        float* row = Yraw + ((b << 12) + s)*256 + m0 + tm*8;
        reinterpret_cast<float4*>(row)[0] =
            make_float4(acc[0*8+j], acc[1*8+j], acc[2*8+j], acc[3*8+j]);
        reinterpret_cast<float4*>(row)[1] =
            make_float4(acc[4*8+j], acc[5*8+j], acc[6*8+j], acc[7*8+j]);
    }
}

// ============================================================
// K1b: LN over proj raw. warp per row.
// ============================================================
__global__ __launch_bounds__(256) void proj_ln_kernel(
    const float* __restrict__ bias, const float* __restrict__ gam,
    const float* __restrict__ bet)
{
    const int gr   = (blockIdx.x << 3) + (threadIdx.x >> 5);
    const int ssel = gr >= Bn*Sn;
    const int row  = ssel ? gr - Bn*Sn : gr;
    const float* Yraw = g_T + ssel*BSC;
    float* Xout       = ssel ? g_X2 : g_X1;
    const int lane = threadIdx.x & 31;
    const int base = row << 8;
    float v[8]; float sum = 0.f, sq = 0.f;
#pragma unroll
    for (int k = 0; k < 8; k++) {
        int o = lane + (k << 5);
        v[k] = Yraw[base + o] + bias[o];
        sum += v[k]; sq += v[k]*v[k];
    }
#pragma unroll
    for (int o = 16; o > 0; o >>= 1) {
        sum += __shfl_xor_sync(0xffffffffu, sum, o);
        sq  += __shfl_xor_sync(0xffffffffu, sq , o);
    }
    float mean = sum * (1.f/256.f);
    float var  = sq  * (1.f/256.f) - mean*mean;
    float rstd = rsqrtf(var + 1e-5f);
#pragma unroll
    for (int k = 0; k < 8; k++) {
        int o = lane + (k << 5);
        Xout[base + o] = (v[k] - mean)*rstd*gam[o] + bet[o];
    }
}

// ============================================================
// attention tile: vectorized score (float4) + transposed-V PV (float4).
// qsm4/ksm4: [32][260] (16B-aligned rows); vsmT: [256][36]; ssm: [32][36].
// smem = (8320 + 8320 + 9216 + 1152 + 96)*4 = 108,416 B -> 2 CTA/SM
// ============================================================
#define KP4 260
#define VTP 36
#define SSP 36
#define ATTN_SMEM_FLOATS (32*KP4*2 + 256*VTP + 32*SSP + 96)

__device__ __forceinline__ void attn_tile(
    const float* __restrict__ X2, int b, int kb, int t,
    float* qsm4, float* ksm4, float* vsmT, float* ssm,
    float* mrow, float* lrow, float* arow, float out[32])
{
    const int tx = t & 15, ty = t >> 4;
    const int qv = t >> 3, dl = t & 7;
    const int warp = t >> 5, lane = t & 31;

    // load K/V tile: row-major padded copy + transposed copy
#pragma unroll
    for (int i = 0; i < 32; i++) {
        float val = X2[(((b << 12) + (kb << 5) + i) << 8) + t];
        ksm4[i*KP4 + t] = val;
        vsmT[t*VTP + i] = val;
    }
    __syncthreads();

    // scores: q in {2ty,2ty+1}, k in {tx, tx+16}; all float4 along d
    float s00 = 0.f, s01 = 0.f, s10 = 0.f, s11 = 0.f;
    const float4* qa = reinterpret_cast<const float4*>(qsm4 + (2*ty)*KP4);
    const float4* qb = reinterpret_cast<const float4*>(qsm4 + (2*ty+1)*KP4);
    const float4* ka = reinterpret_cast<const float4*>(ksm4 + tx*KP4);
    const float4* kc = reinterpret_cast<const float4*>(ksm4 + (tx+16)*KP4);
#pragma unroll 8
    for (int g = 0; g < 64; g++) {
        float4 A = qa[g], Bq = qb[g], C = ka[g], D = kc[g];
        s00 += A.x*C.x + A.y*C.y + A.z*C.z + A.w*C.w;
        s01 += A.x*D.x + A.y*D.y + A.z*D.z + A.w*D.w;
        s10 += Bq.x*C.x + Bq.y*C.y + Bq.z*C.z + Bq.w*C.w;
        s11 += Bq.x*D.x + Bq.y*D.y + Bq.z*D.z + Bq.w*D.w;
    }
    const float scl = 0.0625f; // 1/sqrt(256)
    ssm[(2*ty  )*SSP + tx     ] = s00*scl;
    ssm[(2*ty  )*SSP + tx + 16] = s01*scl;
    ssm[(2*ty+1)*SSP + tx     ] = s10*scl;
    ssm[(2*ty+1)*SSP + tx + 16] = s11*scl;
    __syncthreads();

    // online softmax: warp handles 4 rows
#pragma unroll
    for (int r = 0; r < 4; r++) {
        int row = (warp << 2) + r;
        float sv = ssm[row*SSP + lane];
        float mx = sv;
#pragma unroll
        for (int o = 16; o > 0; o >>= 1)
            mx = fmaxf(mx, __shfl_xor_sync(0xffffffffu, mx, o));
        float mold = mrow[row];
        float mnew = fmaxf(mold, mx);
        float p = __expf(sv - mnew);
        float ps = p;
#pragma unroll
        for (int o = 16; o > 0; o >>= 1)
            ps += __shfl_xor_sync(0xffffffffu, ps, o);
        if (lane == 0) {
            float a = __expf(mold - mnew);
            arow[row] = a;
            lrow[row] = lrow[row]*a + ps;
            mrow[row] = mnew;
        }
        ssm[row*SSP + lane] = p;
    }
    __syncthreads();

    // PV: thread owns q=qv, d = dl + 8*jj. V read as float4 along k from vsmT.
    float alpha = arow[qv];
#pragma unroll
    for (int j = 0; j < 32; j++) out[j] *= alpha;

    float p[32];
    const float4* pr = reinterpret_cast<const float4*>(ssm + qv*SSP);
#pragma unroll
    for (int kq = 0; kq < 8; kq++) {
        float4 v = pr[kq];
        p[4*kq+0] = v.x; p[4*kq+1] = v.y; p[4*kq+2] = v.z; p[4*kq+3] = v.w;
    }
#pragma unroll 4
    for (int jj = 0; jj < 32; jj++) {
        const float4* vr = reinterpret_cast<const float4*>(vsmT + (dl + 8*jj)*VTP);
        float a0 = 0.f, a1 = 0.f;
#pragma unroll
        for (int kq = 0; kq < 8; kq += 2) {
            float4 v0 = vr[kq], v1 = vr[kq+1];
            a0 += p[4*kq+0]*v0.x + p[4*kq+1]*v0.y + p[4*kq+2]*v0.z + p[4*kq+3]*v0.w;
            a1 += p[4*kq+4]*v1.x + p[4*kq+5]*v1.y + p[4*kq+6]*v1.z + p[4*kq+7]*v1.w;
        }
        out[jj] += a0 + a1;
    }
    __syncthreads();
}

// K2a: sparse rows (n = 1..127). grid (127, B), block 256
__global__ __launch_bounds__(256) void attn_sparse_kernel(
    const float* __restrict__ X1, const float* __restrict__ X2,
    const int* __restrict__ bidx, int K, float* __restrict__ ATT)
{
    extern __shared__ float sm[];
    float* qsm4 = sm;
    float* ksm4 = qsm4 + 32*KP4;
    float* vsmT = ksm4 + 32*KP4;
    float* ssm  = vsmT + 256*VTP;
    float* mrow = ssm + 32*SSP;
    float* lrow = mrow + 32;
    float* arow = lrow + 32;

    const int b = blockIdx.y, n = blockIdx.x + 1;
    const int t = threadIdx.x;
    const int qv = t >> 3, dl = t & 7;

#pragma unroll
    for (int i = 0; i < 32; i++)
        qsm4[i*KP4 + t] = X1[(((b << 12) + (n << 5) + i) << 8) + t];
    if (t < 32) { mrow[t] = -1e30f; lrow[t] = 0.f; }

    float out[32];
#pragma unroll
    for (int j = 0; j < 32; j++) out[j] = 0.f;
    __syncthreads();

    for (int it = 0; it < K; it++) {
        int kb = bidx[(n - 1)*K + it];
        if (it > 0 && kb == 0) break;
        attn_tile(X2, b, kb, t, qsm4, ksm4, vsmT, ssm, mrow, lrow, arow, out);
    }

    const float linv = 1.f / lrow[qv];
    const int base = (((b << 12) + (n << 5) + qv) << 8) + dl;
#pragma unroll
    for (int jj = 0; jj < 32; jj++)
        ATT[base + 8*jj] = out[jj]*linv;
}

// K2b: global rows (n=0), split-softmax partials. grid (NSPLIT, B)
__global__ __launch_bounds__(256) void attn_global_partial(
    const float* __restrict__ X1, const float* __restrict__ X2,
    float* __restrict__ GO, float* __restrict__ GM, float* __restrict__ GL)
{
    extern __shared__ float sm[];
    float* qsm4 = sm;
    float* ksm4 = qsm4 + 32*KP4;
    float* vsmT = ksm4 + 32*KP4;
    float* ssm  = vsmT + 256*VTP;
    float* mrow = ssm + 32*SSP;
    float* lrow = mrow + 32;
    float* arow = lrow + 32;

    const int b = blockIdx.y, split = blockIdx.x;
    const int t = threadIdx.x;
    const int qv = t >> 3, dl = t & 7;

#pragma unroll
    for (int i = 0; i < 32; i++)
        qsm4[i*KP4 + t] = X1[(((b << 12) + i) << 8) + t];
    if (t < 32) { mrow[t] = -1e30f; lrow[t] = 0.f; }

    float out[32];
#pragma unroll
    for (int j = 0; j < 32; j++) out[j] = 0.f;
    __syncthreads();

    for (int it = 0; it < NBn/NSPLIT; it++) {
        int kb = split*(NBn/NSPLIT) + it;
        attn_tile(X2, b, kb, t, qsm4, ksm4, vsmT, ssm, mrow, lrow, arow, out);
    }

    const int gi = (b*NSPLIT + split)*32;
    const int base = ((gi + qv) << 8) + dl;
#pragma unroll
    for (int jj = 0; jj < 32; jj++)
        GO[base + 8*jj] = out[jj];
    if (t < 32) { GM[gi + t] = mrow[t]; GL[gi + t] = lrow[t]; }
}

// K2c: combine. grid (B, 32), block 256
__global__ __launch_bounds__(256) void attn_global_combine(
    const float* __restrict__ GO, const float* __restrict__ GM,
    const float* __restrict__ GL, float* __restrict__ ATT)
{
    const int b = blockIdx.x, q = blockIdx.y, t = threadIdx.x;
    float ms[NSPLIT], ls[NSPLIT];
    float M = -1e30f;
#pragma unroll
    for (int i = 0; i < NSPLIT; i++) {
        ms[i] = GM[(b*NSPLIT + i)*32 + q];
        ls[i] = GL[(b*NSPLIT + i)*32 + q];
        M = fmaxf(M, ms[i]);
    }
    float L = 0.f, acc = 0.f;
#pragma unroll
    for (int i = 0; i < NSPLIT; i++) {
        float e = __expf(ms[i] - M);
        L   += ls[i] * e;
        acc += GO[(((b*NSPLIT + i)*32 + q) << 8) + t] * e;
    }
    ATT[(((b << 12) + q) << 8) + t] = acc / L;
}

// ============================================================
// K3: H = LN(X1 + ATT). warp per row.
// ============================================================
__global__ __launch_bounds__(256) void add_ln_kernel(
    const float* __restrict__ X1, const float* __restrict__ ATT,
    const float* __restrict__ gam, const float* __restrict__ bet,
    float* __restrict__ H)
{
    const int row  = (blockIdx.x << 3) + (threadIdx.x >> 5);
    const int lane = threadIdx.x & 31;
    const int base = row << 8;
    float v[8]; float sum = 0.f, sq = 0.f;
#pragma unroll
    for (int k = 0; k < 8; k++) {
        int o = lane + (k << 5);
        v[k] = X1[base + o] + ATT[base + o];
        sum += v[k]; sq += v[k]*v[k];
    }
#pragma unroll
    for (int o = 16; o > 0; o >>= 1) {
        sum += __shfl_xor_sync(0xffffffffu, sum, o);
        sq  += __shfl_xor_sync(0xffffffffu, sq , o);
    }
    float mean = sum * (1.f/256.f);
    float var  = sq  * (1.f/256.f) - mean*mean;
    float rstd = rsqrtf(var + 1e-5f);
#pragma unroll
    for (int k = 0; k < 8; k++) {
        int o = lane + (k << 5);
        H[base + o] = (v[k] - mean)*rstd*gam[o] + bet[o];
    }
}

// ============================================================
// K4: T = gelu(H @ w1 + b1). grid (BS/128, DFF/128), block 256
// ============================================================
__global__ __launch_bounds__(256, 2) void ffn1_kernel(
    const float* __restrict__ H, const float* __restrict__ w1,
    const float* __restrict__ b1, float* __restrict__ T)
{
    __shared__ float sm[GEMM_SMEM];
    float* As = sm; float* Bs = sm + 16*APAD;
    const int m0 = blockIdx.x << 7;
    const int n0 = blockIdx.y << 7;
    const int t = threadIdx.x;
    const int tm = t >> 4, tn = t & 15;

    float acc[64];
#pragma unroll
    for (int i = 0; i < 64; i++) acc[i] = 0.f;

    gemm_mainloop(H + m0*Cn, Cn, w1 + n0, DFFn, Cn, As, Bs, acc, t);

    float bvv[8];
#pragma unroll
    for (int j = 0; j < 8; j++) bvv[j] = b1[n0 + tn*8 + j];
#pragma unroll
    for (int i = 0; i < 8; i++) {
        float* row = T + (m0 + tm*8 + i)*DFFn + n0 + tn*8;
        float g[8];
#pragma unroll
        for (int j = 0; j < 8; j++) {
            float x = acc[i*8+j] + bvv[j];
            g[j] = 0.5f*x*(1.f + erff(x*0.70710678118654752f));
        }
        reinterpret_cast<float4*>(row)[0] = make_float4(g[0],g[1],g[2],g[3]);
        reinterpret_cast<float4*>(row)[1] = make_float4(g[4],g[5],g[6],g[7]);
    }
}

// ============================================================
// K5: Out(B,C,S) = transpose(H + T @ w2 + b2). grid (BS/128, C/128)
// ============================================================
__global__ __launch_bounds__(256, 2) void ffn2_kernel(
    const float* __restrict__ T, const float* __restrict__ w2,
    const float* __restrict__ b2, const float* __restrict__ H,
    float* __restrict__ Out)
{
    __shared__ float sm[GEMM_SMEM];
    float* As = sm; float* Bs = sm + 16*APAD;
    const int m0 = blockIdx.x << 7;
    const int n0 = blockIdx.y << 7;
    const int t = threadIdx.x;
    const int tm = t >> 4, tn = t & 15;

    float acc[64];
#pragma unroll
    for (int i = 0; i < 64; i++) acc[i] = 0.f;

    gemm_mainloop(T + m0*DFFn, DFFn, w2 + n0, Cn, DFFn, As, Bs, acc, t);

    float bvv[8];
#pragma unroll
    for (int j = 0; j < 8; j++) bvv[j] = b2[n0 + tn*8 + j];
#pragma unroll
    for (int i = 0; i < 8; i++) {
        const float* hrow = H + (m0 + tm*8 + i)*Cn + n0 + tn*8;
        float4 h0 = reinterpret_cast<const float4*>(hrow)[0];
        float4 h1 = reinterpret_cast<const float4*>(hrow)[1];
        acc[i*8+0] += bvv[0] + h0.x; acc[i*8+1] += bvv[1] + h0.y;
        acc[i*8+2] += bvv[2] + h0.z; acc[i*8+3] += bvv[3] + h0.w;
        acc[i*8+4] += bvv[4] + h1.x; acc[i*8+5] += bvv[5] + h1.y;
        acc[i*8+6] += bvv[6] + h1.z; acc[i*8+7] += bvv[7] + h1.w;
    }
    const int b  = m0 >> 12;
    const int s0 = (m0 & 4095) + tm*8;
#pragma unroll
    for (int j = 0; j < 8; j++) {
        int c = n0 + tn*8 + j;
        float* orow = Out + (((b << 8) + c) << 12) + s0;
        reinterpret_cast<float4*>(orow)[0] =
            make_float4(acc[0*8+j], acc[1*8+j], acc[2*8+j], acc[3*8+j]);
        reinterpret_cast<float4*>(orow)[1] =
            make_float4(acc[4*8+j], acc[5*8+j], acc[6*8+j], acc[7*8+j]);
    }
}

// ============================================================
extern "C" void kernel_launch(void* const* d_in, const int* in_sizes, int n_in,
                              void* d_out, int out_size)
{
    const float* src1  = (const float*)d_in[0];
    const float* src2  = (const float*)d_in[1];
    const float* wproj = (const float*)d_in[2];
    const float* bproj = (const float*)d_in[3];
    const float* g13   = (const float*)d_in[4];
    const float* be13  = (const float*)d_in[5];
    const float* g12   = (const float*)d_in[6];
    const float* be12  = (const float*)d_in[7];
    const float* w1    = (const float*)d_in[8];
    const float* b1    = (const float*)d_in[9];
    const float* w2    = (const float*)d_in[10];
    const float* b2    = (const float*)d_in[11];
    const int*   bidx  = (const int*)d_in[12];
    const int K = in_sizes[12] / (NBn - 1);
    float* out = (float*)d_out;

    float *X1, *X2, *ATT, *H, *T, *GO, *GM, *GL;
    cudaGetSymbolAddress((void**)&X1,  g_X1);
    cudaGetSymbolAddress((void**)&X2,  g_X2);
    cudaGetSymbolAddress((void**)&ATT, g_ATT);
    cudaGetSymbolAddress((void**)&H,   g_H);
    cudaGetSymbolAddress((void**)&T,   g_T);
    cudaGetSymbolAddress((void**)&GO,  g_GO);
    cudaGetSymbolAddress((void**)&GM,  g_GM);
    cudaGetSymbolAddress((void**)&GL,  g_GL);

    const int attn_smem = ATTN_SMEM_FLOATS * 4;   // 108,416 B -> 2 CTA/SM
    cudaFuncSetAttribute(attn_sparse_kernel, cudaFuncAttributeMaxDynamicSharedMemorySize, attn_smem);
    cudaFuncSetAttribute(attn_global_partial, cudaFuncAttributeMaxDynamicSharedMemorySize, attn_smem);

    proj_gemm_kernel<<<dim3(2, 32, Bn*2), 256>>>(src1, src2, wproj);
    proj_ln_kernel<<<(2*Bn*Sn)/8, 256>>>(bproj, g13, be13);

    attn_global_partial<<<dim3(NSPLIT, Bn), 256, attn_smem>>>(X1, X2, GO, GM, GL);
    attn_sparse_kernel<<<dim3(NBn-1, Bn), 256, attn_smem>>>(X1, X2, bidx, K, ATT);
    attn_global_combine<<<dim3(Bn, 32), 256>>>(GO, GM, GL, ATT);

    add_ln_kernel<<<(Bn*Sn)/8, 256>>>(X1, ATT, g12, be12, H);

    ffn1_kernel<<<dim3((Bn*Sn)/128, DFFn/128), 256>>>(H, w1, b1, T);

    ffn2_kernel<<<dim3((Bn*Sn)/128, Cn/128), 256>>>(T, w2, b2, H, out);
}

// round 7
// speedup vs baseline: 7.8881x; 1.2597x over previous
#include <cuda_runtime.h>
#include <math.h>

#define Bn   4
#define Cn   256
#define Sn   4096
#define DFFn 1024
#define NBn  128
#define BSn  32
#define NSPLIT 16

#define BSC (Bn*Sn*Cn)
#define BST (Bn*Sn*DFFn)

// ---- scratch ----
__device__ float g_X1[BSC];
__device__ float g_X2[BSC];
__device__ float g_ATT[BSC];
__device__ float g_H[BSC];
__device__ float g_T[BST];
__device__ float g_GO[Bn*NSPLIT*32*256];
__device__ float g_GM[Bn*NSPLIT*32];
__device__ float g_GL[Bn*NSPLIT*32];

// ============================================================
// 128x128x16 GEMM mainloop, 256 thr, 8x8 micro-tile, reg-prefetch.
// ============================================================
#define APAD 132
#define GEMM_SMEM  (16*APAD*2)

__device__ __forceinline__ void gemm_mainloop(
    const float* __restrict__ A, int lda,
    const float* __restrict__ Bm, int ldb,
    int Ktot, float* As, float* Bs, float acc[64], int t)
{
    const int tm = t >> 4, tn = t & 15;
    const int am0 = t >> 2,  akq = (t & 3) << 2;
    const int am1 = (t + 256) >> 2;
    const int bk0 = t >> 5,  bnq = (t & 31) << 2;
    const int bk1 = (t + 256) >> 5;

    float4 pa0, pa1, pb0, pb1;
    pa0 = *reinterpret_cast<const float4*>(A + am0*lda + akq);
    pa1 = *reinterpret_cast<const float4*>(A + am1*lda + akq);
    pb0 = *reinterpret_cast<const float4*>(Bm + bk0*ldb + bnq);
    pb1 = *reinterpret_cast<const float4*>(Bm + bk1*ldb + bnq);

    for (int k0 = 0; k0 < Ktot; k0 += 16) {
        As[(akq+0)*APAD + am0] = pa0.x;  As[(akq+1)*APAD + am0] = pa0.y;
        As[(akq+2)*APAD + am0] = pa0.z;  As[(akq+3)*APAD + am0] = pa0.w;
        As[(akq+0)*APAD + am1] = pa1.x;  As[(akq+1)*APAD + am1] = pa1.y;
        As[(akq+2)*APAD + am1] = pa1.z;  As[(akq+3)*APAD + am1] = pa1.w;
        *reinterpret_cast<float4*>(Bs + bk0*APAD + bnq) = pb0;
        *reinterpret_cast<float4*>(Bs + bk1*APAD + bnq) = pb1;
        __syncthreads();

        if (k0 + 16 < Ktot) {
            pa0 = *reinterpret_cast<const float4*>(A + am0*lda + k0 + 16 + akq);
            pa1 = *reinterpret_cast<const float4*>(A + am1*lda + k0 + 16 + akq);
            pb0 = *reinterpret_cast<const float4*>(Bm + (k0 + 16 + bk0)*ldb + bnq);
            pb1 = *reinterpret_cast<const float4*>(Bm + (k0 + 16 + bk1)*ldb + bnq);
        }

#pragma unroll
        for (int kk = 0; kk < 16; kk++) {
            float4 a0 = *reinterpret_cast<const float4*>(As + kk*APAD + tm*8);
            float4 a1 = *reinterpret_cast<const float4*>(As + kk*APAD + tm*8 + 4);
            float4 b0 = *reinterpret_cast<const float4*>(Bs + kk*APAD + tn*8);
            float4 b1 = *reinterpret_cast<const float4*>(Bs + kk*APAD + tn*8 + 4);
            float av[8] = {a0.x,a0.y,a0.z,a0.w,a1.x,a1.y,a1.z,a1.w};
            float bv[8] = {b0.x,b0.y,b0.z,b0.w,b1.x,b1.y,b1.z,b1.w};
#pragma unroll
            for (int i = 0; i < 8; i++)
#pragma unroll
                for (int j = 0; j < 8; j++)
                    acc[i*8+j] += av[i]*bv[j];
        }
        __syncthreads();
    }
}

// ============================================================
// K1a: proj GEMM. grid (2, 32, B*2), block 256
// ============================================================
__global__ __launch_bounds__(256, 2) void proj_gemm_kernel(
    const float* __restrict__ src1, const float* __restrict__ src2,
    const float* __restrict__ W)
{
    __shared__ float sm[GEMM_SMEM];
    float* As = sm; float* Bs = sm + 16*APAD;
    const int z = blockIdx.z;
    const int b = z >> 1, ssel = z & 1;
    const float* src = ssel ? src2 : src1;
    float* Yraw = g_T + ssel*BSC;
    const int m0 = blockIdx.x << 7;
    const int n0 = blockIdx.y << 7;
    const int t = threadIdx.x;
    const int tm = t >> 4, tn = t & 15;

    float acc[64];
#pragma unroll
    for (int i = 0; i < 64; i++) acc[i] = 0.f;

    gemm_mainloop(W + m0*Cn, Cn, src + ((b*Cn) << 12) + n0, Sn, Cn, As, Bs, acc, t);

#pragma unroll
    for (int j = 0; j < 8; j++) {
        int s = n0 + tn*8 + j;
        float* row = Yraw + ((b << 12) + s)*256 + m0 + tm*8;
        reinterpret_cast<float4*>(row)[0] =
            make_float4(acc[0*8+j], acc[1*8+j], acc[2*8+j], acc[3*8+j]);
        reinterpret_cast<float4*>(row)[1] =
            make_float4(acc[4*8+j], acc[5*8+j], acc[6*8+j], acc[7*8+j]);
    }
}

// ============================================================
// K1b: LN over proj raw. warp per row.
// ============================================================
__global__ __launch_bounds__(256) void proj_ln_kernel(
    const float* __restrict__ bias, const float* __restrict__ gam,
    const float* __restrict__ bet)
{
    const int gr   = (blockIdx.x << 3) + (threadIdx.x >> 5);
    const int ssel = gr >= Bn*Sn;
    const int row  = ssel ? gr - Bn*Sn : gr;
    const float* Yraw = g_T + ssel*BSC;
    float* Xout       = ssel ? g_X2 : g_X1;
    const int lane = threadIdx.x & 31;
    const int base = row << 8;
    float v[8]; float sum = 0.f, sq = 0.f;
#pragma unroll
    for (int k = 0; k < 8; k++) {
        int o = lane + (k << 5);
        v[k] = Yraw[base + o] + bias[o];
        sum += v[k]; sq += v[k]*v[k];
    }
#pragma unroll
    for (int o = 16; o > 0; o >>= 1) {
        sum += __shfl_xor_sync(0xffffffffu, sum, o);
        sq  += __shfl_xor_sync(0xffffffffu, sq , o);
    }
    float mean = sum * (1.f/256.f);
    float var  = sq  * (1.f/256.f) - mean*mean;
    float rstd = rsqrtf(var + 1e-5f);
#pragma unroll
    for (int k = 0; k < 8; k++) {
        int o = lane + (k << 5);
        Xout[base + o] = (v[k] - mean)*rstd*gam[o] + bet[o];
    }
}

// ============================================================
// attention tile: vectorized score + PV read directly from row-major
// K/V tile (no transposed copy). Thread micro-tile: 2q x 16d.
// qsm4/ksm4: [32][260]; ssm: [32][36].
// smem = (8320*2 + 1152 + 96)*4 = 71,552 B -> 3 CTA/SM
// ============================================================
#define KP4 260
#define SSP 36
#define ATTN_SMEM_FLOATS (32*KP4*2 + 32*SSP + 96)

__device__ __forceinline__ void attn_tile(
    const float* __restrict__ X2, int b, int kb, int t,
    float* qsm4, float* ksm4, float* ssm,
    float* mrow, float* lrow, float* arow,
    float out0[16], float out1[16])
{
    const int tx = t & 15, ty = t >> 4;
    const int warp = t >> 5, lane = t & 31;

    // load K/V tile (row-major, padded, conflict-free)
#pragma unroll
    for (int i = 0; i < 32; i++)
        ksm4[i*KP4 + t] = X2[(((b << 12) + (kb << 5) + i) << 8) + t];
    __syncthreads();

    // scores: q in {2ty,2ty+1}, k in {tx, tx+16}; float4 along d
    float s00 = 0.f, s01 = 0.f, s10 = 0.f, s11 = 0.f;
    const float4* qa = reinterpret_cast<const float4*>(qsm4 + (2*ty)*KP4);
    const float4* qb = reinterpret_cast<const float4*>(qsm4 + (2*ty+1)*KP4);
    const float4* ka = reinterpret_cast<const float4*>(ksm4 + tx*KP4);
    const float4* kc = reinterpret_cast<const float4*>(ksm4 + (tx+16)*KP4);
#pragma unroll 8
    for (int g = 0; g < 64; g++) {
        float4 A = qa[g], Bq = qb[g], C = ka[g], D = kc[g];
        s00 += A.x*C.x + A.y*C.y + A.z*C.z + A.w*C.w;
        s01 += A.x*D.x + A.y*D.y + A.z*D.z + A.w*D.w;
        s10 += Bq.x*C.x + Bq.y*C.y + Bq.z*C.z + Bq.w*C.w;
        s11 += Bq.x*D.x + Bq.y*D.y + Bq.z*D.z + Bq.w*D.w;
    }
    const float scl = 0.0625f; // 1/sqrt(256)
    ssm[(2*ty  )*SSP + tx     ] = s00*scl;
    ssm[(2*ty  )*SSP + tx + 16] = s01*scl;
    ssm[(2*ty+1)*SSP + tx     ] = s10*scl;
    ssm[(2*ty+1)*SSP + tx + 16] = s11*scl;
    __syncthreads();

    // online softmax: warp handles 4 rows
#pragma unroll
    for (int r = 0; r < 4; r++) {
        int row = (warp << 2) + r;
        float sv = ssm[row*SSP + lane];
        float mx = sv;
#pragma unroll
        for (int o = 16; o > 0; o >>= 1)
            mx = fmaxf(mx, __shfl_xor_sync(0xffffffffu, mx, o));
        float mold = mrow[row];
        float mnew = fmaxf(mold, mx);
        float p = __expf(sv - mnew);
        float ps = p;
#pragma unroll
        for (int o = 16; o > 0; o >>= 1)
            ps += __shfl_xor_sync(0xffffffffu, ps, o);
        if (lane == 0) {
            float a = __expf(mold - mnew);
            arow[row] = a;
            lrow[row] = lrow[row]*a + ps;
            mrow[row] = mnew;
        }
        ssm[row*SSP + lane] = p;
    }
    __syncthreads();

    // PV: out[q=2ty+{0,1}][d=4tx+64g+c] from row-major V (= ksm4).
    // V float4 reads: 16 lanes x 16B contiguous = optimal 2 wavefronts.
    float a0 = arow[2*ty], a1 = arow[2*ty+1];
#pragma unroll
    for (int j = 0; j < 16; j++) { out0[j] *= a0; out1[j] *= a1; }
    const float* p0r = ssm + (2*ty)*SSP;
    const float* p1r = ssm + (2*ty+1)*SSP;
#pragma unroll 4
    for (int k = 0; k < 32; k++) {
        float p0 = p0r[k], p1 = p1r[k];
        const float* vrow = ksm4 + k*KP4 + 4*tx;
#pragma unroll
        for (int g = 0; g < 4; g++) {
            float4 v = *reinterpret_cast<const float4*>(vrow + (g << 6));
            out0[g*4+0] += p0*v.x; out0[g*4+1] += p0*v.y;
            out0[g*4+2] += p0*v.z; out0[g*4+3] += p0*v.w;
            out1[g*4+0] += p1*v.x; out1[g*4+1] += p1*v.y;
            out1[g*4+2] += p1*v.z; out1[g*4+3] += p1*v.w;
        }
    }
    __syncthreads();
}

// K2: merged attention. grid (127+NSPLIT, B), block 256.
//   x < 127        : sparse row n = x+1   -> ATT
//   x >= 127       : global split x-127   -> GO/GM/GL
__global__ __launch_bounds__(256) void attn_kernel(
    const float* __restrict__ X1, const float* __restrict__ X2,
    const int* __restrict__ bidx, int K, float* __restrict__ ATT,
    float* __restrict__ GO, float* __restrict__ GM, float* __restrict__ GL)
{
    extern __shared__ float sm[];
    float* qsm4 = sm;
    float* ksm4 = qsm4 + 32*KP4;
    float* ssm  = ksm4 + 32*KP4;
    float* mrow = ssm + 32*SSP;
    float* lrow = mrow + 32;
    float* arow = lrow + 32;

    const int b = blockIdx.y, x = blockIdx.x;
    const int t = threadIdx.x;
    const int tx = t & 15, ty = t >> 4;
    const bool sparse = (x < NBn - 1);
    const int n = sparse ? (x + 1) : 0;

#pragma unroll
    for (int i = 0; i < 32; i++)
        qsm4[i*KP4 + t] = X1[(((b << 12) + (n << 5) + i) << 8) + t];
    if (t < 32) { mrow[t] = -1e30f; lrow[t] = 0.f; }

    float out0[16], out1[16];
#pragma unroll
    for (int j = 0; j < 16; j++) { out0[j] = 0.f; out1[j] = 0.f; }
    __syncthreads();

    if (sparse) {
        for (int it = 0; it < K; it++) {
            int kb = bidx[(n - 1)*K + it];
            if (it > 0 && kb == 0) break;
            attn_tile(X2, b, kb, t, qsm4, ksm4, ssm, mrow, lrow, arow, out0, out1);
        }
        const float l0 = 1.f / lrow[2*ty];
        const float l1 = 1.f / lrow[2*ty+1];
        const int base0 = (((b << 12) + (n << 5) + 2*ty) << 8) + 4*tx;
        const int base1 = base0 + 256;
#pragma unroll
        for (int g = 0; g < 4; g++) {
            *reinterpret_cast<float4*>(ATT + base0 + (g << 6)) =
                make_float4(out0[g*4+0]*l0, out0[g*4+1]*l0, out0[g*4+2]*l0, out0[g*4+3]*l0);
            *reinterpret_cast<float4*>(ATT + base1 + (g << 6)) =
                make_float4(out1[g*4+0]*l1, out1[g*4+1]*l1, out1[g*4+2]*l1, out1[g*4+3]*l1);
        }
    } else {
        const int split = x - (NBn - 1);
        for (int it = 0; it < NBn/NSPLIT; it++) {
            int kb = split*(NBn/NSPLIT) + it;
            attn_tile(X2, b, kb, t, qsm4, ksm4, ssm, mrow, lrow, arow, out0, out1);
        }
        const int gi = (b*NSPLIT + split)*32;
        const int base0 = ((gi + 2*ty) << 8) + 4*tx;
        const int base1 = base0 + 256;
#pragma unroll
        for (int g = 0; g < 4; g++) {
            *reinterpret_cast<float4*>(GO + base0 + (g << 6)) =
                make_float4(out0[g*4+0], out0[g*4+1], out0[g*4+2], out0[g*4+3]);
            *reinterpret_cast<float4*>(GO + base1 + (g << 6)) =
                make_float4(out1[g*4+0], out1[g*4+1], out1[g*4+2], out1[g*4+3]);
        }
        if (t < 32) { GM[gi + t] = mrow[t]; GL[gi + t] = lrow[t]; }
    }
}

// K2c: combine. grid (B, 32), block 256
__global__ __launch_bounds__(256) void attn_global_combine(
    const float* __restrict__ GO, const float* __restrict__ GM,
    const float* __restrict__ GL, float* __restrict__ ATT)
{
    const int b = blockIdx.x, q = blockIdx.y, t = threadIdx.x;
    float ms[NSPLIT], ls[NSPLIT];
    float M = -1e30f;
#pragma unroll
    for (int i = 0; i < NSPLIT; i++) {
        ms[i] = GM[(b*NSPLIT + i)*32 + q];
        ls[i] = GL[(b*NSPLIT + i)*32 + q];
        M = fmaxf(M, ms[i]);
    }
    float L = 0.f, acc = 0.f;
#pragma unroll
    for (int i = 0; i < NSPLIT; i++) {
        float e = __expf(ms[i] - M);
        L   += ls[i] * e;
        acc += GO[(((b*NSPLIT + i)*32 + q) << 8) + t] * e;
    }
    ATT[(((b << 12) + q) << 8) + t] = acc / L;
}

// ============================================================
// K3: H = LN(X1 + ATT). warp per row.
// ============================================================
__global__ __launch_bounds__(256) void add_ln_kernel(
    const float* __restrict__ X1, const float* __restrict__ ATT,
    const float* __restrict__ gam, const float* __restrict__ bet,
    float* __restrict__ H)
{
    const int row  = (blockIdx.x << 3) + (threadIdx.x >> 5);
    const int lane = threadIdx.x & 31;
    const int base = row << 8;
    float v[8]; float sum = 0.f, sq = 0.f;
#pragma unroll
    for (int k = 0; k < 8; k++) {
        int o = lane + (k << 5);
        v[k] = X1[base + o] + ATT[base + o];
        sum += v[k]; sq += v[k]*v[k];
    }
#pragma unroll
    for (int o = 16; o > 0; o >>= 1) {
        sum += __shfl_xor_sync(0xffffffffu, sum, o);
        sq  += __shfl_xor_sync(0xffffffffu, sq , o);
    }
    float mean = sum * (1.f/256.f);
    float var  = sq  * (1.f/256.f) - mean*mean;
    float rstd = rsqrtf(var + 1e-5f);
#pragma unroll
    for (int k = 0; k < 8; k++) {
        int o = lane + (k << 5);
        H[base + o] = (v[k] - mean)*rstd*gam[o] + bet[o];
    }
}

// ============================================================
// K4: T = gelu(H @ w1 + b1). grid (BS/128, DFF/128), block 256
// ============================================================
__global__ __launch_bounds__(256, 2) void ffn1_kernel(
    const float* __restrict__ H, const float* __restrict__ w1,
    const float* __restrict__ b1, float* __restrict__ T)
{
    __shared__ float sm[GEMM_SMEM];
    float* As = sm; float* Bs = sm + 16*APAD;
    const int m0 = blockIdx.x << 7;
    const int n0 = blockIdx.y << 7;
    const int t = threadIdx.x;
    const int tm = t >> 4, tn = t & 15;

    float acc[64];
#pragma unroll
    for (int i = 0; i < 64; i++) acc[i] = 0.f;

    gemm_mainloop(H + m0*Cn, Cn, w1 + n0, DFFn, Cn, As, Bs, acc, t);

    float bvv[8];
#pragma unroll
    for (int j = 0; j < 8; j++) bvv[j] = b1[n0 + tn*8 + j];
#pragma unroll
    for (int i = 0; i < 8; i++) {
        float* row = T + (m0 + tm*8 + i)*DFFn + n0 + tn*8;
        float g[8];
#pragma unroll
        for (int j = 0; j < 8; j++) {
            float x = acc[i*8+j] + bvv[j];
            g[j] = 0.5f*x*(1.f + erff(x*0.70710678118654752f));
        }
        reinterpret_cast<float4*>(row)[0] = make_float4(g[0],g[1],g[2],g[3]);
        reinterpret_cast<float4*>(row)[1] = make_float4(g[4],g[5],g[6],g[7]);
    }
}

// ============================================================
// K5: Out(B,C,S) = transpose(H + T @ w2 + b2). grid (BS/128, C/128)
// ============================================================
__global__ __launch_bounds__(256, 2) void ffn2_kernel(
    const float* __restrict__ T, const float* __restrict__ w2,
    const float* __restrict__ b2, const float* __restrict__ H,
    float* __restrict__ Out)
{
    __shared__ float sm[GEMM_SMEM];
    float* As = sm; float* Bs = sm + 16*APAD;
    const int m0 = blockIdx.x << 7;
    const int n0 = blockIdx.y << 7;
    const int t = threadIdx.x;
    const int tm = t >> 4, tn = t & 15;

    float acc[64];
#pragma unroll
    for (int i = 0; i < 64; i++) acc[i] = 0.f;

    gemm_mainloop(T + m0*DFFn, DFFn, w2 + n0, Cn, DFFn, As, Bs, acc, t);

    float bvv[8];
#pragma unroll
    for (int j = 0; j < 8; j++) bvv[j] = b2[n0 + tn*8 + j];
#pragma unroll
    for (int i = 0; i < 8; i++) {
        const float* hrow = H + (m0 + tm*8 + i)*Cn + n0 + tn*8;
        float4 h0 = reinterpret_cast<const float4*>(hrow)[0];
        float4 h1 = reinterpret_cast<const float4*>(hrow)[1];
        acc[i*8+0] += bvv[0] + h0.x; acc[i*8+1] += bvv[1] + h0.y;
        acc[i*8+2] += bvv[2] + h0.z; acc[i*8+3] += bvv[3] + h0.w;
        acc[i*8+4] += bvv[4] + h1.x; acc[i*8+5] += bvv[5] + h1.y;
        acc[i*8+6] += bvv[6] + h1.z; acc[i*8+7] += bvv[7] + h1.w;
    }
    const int b  = m0 >> 12;
    const int s0 = (m0 & 4095) + tm*8;
#pragma unroll
    for (int j = 0; j < 8; j++) {
        int c = n0 + tn*8 + j;
        float* orow = Out + (((b << 8) + c) << 12) + s0;
        reinterpret_cast<float4*>(orow)[0] =
            make_float4(acc[0*8+j], acc[1*8+j], acc[2*8+j], acc[3*8+j]);
        reinterpret_cast<float4*>(orow)[1] =
            make_float4(acc[4*8+j], acc[5*8+j], acc[6*8+j], acc[7*8+j]);
    }
}

// ============================================================
extern "C" void kernel_launch(void* const* d_in, const int* in_sizes, int n_in,
                              void* d_out, int out_size)
{
    const float* src1  = (const float*)d_in[0];
    const float* src2  = (const float*)d_in[1];
    const float* wproj = (const float*)d_in[2];
    const float* bproj = (const float*)d_in[3];
    const float* g13   = (const float*)d_in[4];
    const float* be13  = (const float*)d_in[5];
    const float* g12   = (const float*)d_in[6];
    const float* be12  = (const float*)d_in[7];
    const float* w1    = (const float*)d_in[8];
    const float* b1    = (const float*)d_in[9];
    const float* w2    = (const float*)d_in[10];
    const float* b2    = (const float*)d_in[11];
    const int*   bidx  = (const int*)d_in[12];
    const int K = in_sizes[12] / (NBn - 1);
    float* out = (float*)d_out;

    float *X1, *X2, *ATT, *H, *T, *GO, *GM, *GL;
    cudaGetSymbolAddress((void**)&X1,  g_X1);
    cudaGetSymbolAddress((void**)&X2,  g_X2);
    cudaGetSymbolAddress((void**)&ATT, g_ATT);
    cudaGetSymbolAddress((void**)&H,   g_H);
    cudaGetSymbolAddress((void**)&T,   g_T);
    cudaGetSymbolAddress((void**)&GO,  g_GO);
    cudaGetSymbolAddress((void**)&GM,  g_GM);
    cudaGetSymbolAddress((void**)&GL,  g_GL);

    const int attn_smem = ATTN_SMEM_FLOATS * 4;   // 71,552 B -> 3 CTA/SM
    cudaFuncSetAttribute(attn_kernel, cudaFuncAttributeMaxDynamicSharedMemorySize, attn_smem);

    proj_gemm_kernel<<<dim3(2, 32, Bn*2), 256>>>(src1, src2, wproj);
    proj_ln_kernel<<<(2*Bn*Sn)/8, 256>>>(bproj, g13, be13);

    attn_kernel<<<dim3(NBn - 1 + NSPLIT, Bn), 256, attn_smem>>>(
        X1, X2, bidx, K, ATT, GO, GM, GL);
    attn_global_combine<<<dim3(Bn, 32), 256>>>(GO, GM, GL, ATT);

    add_ln_kernel<<<(Bn*Sn)/8, 256>>>(X1, ATT, g12, be12, H);

    ffn1_kernel<<<dim3((Bn*Sn)/128, DFFn/128), 256>>>(H, w1, b1, T);

    ffn2_kernel<<<dim3((Bn*Sn)/128, Cn/128), 256>>>(T, w2, b2, H, out);
}

// round 9
// speedup vs baseline: 8.4711x; 1.0739x over previous
#include <cuda_runtime.h>
#include <math.h>
#include <stdint.h>

#define Bn   4
#define Cn   256
#define Sn   4096
#define DFFn 1024
#define NBn  128
#define NSPLIT 16

#define BSC (Bn*Sn*Cn)
#define BST (Bn*Sn*DFFn)

// ---- scratch ----
__device__ float g_X1[BSC];
__device__ float g_X2[BSC];
__device__ float g_ATT[BSC];
__device__ float g_H[BSC];
__device__ float g_T[BST];          // ffn hidden; also proj raw output
__device__ float g_GO[Bn*NSPLIT*32*256];
__device__ float g_GM[Bn*NSPLIT*32];
__device__ float g_GL[Bn*NSPLIT*32];

// ============================================================
// 3xTF32 mma.sync GEMM: 128x128 tile, 256 thr, warp tile 32x64.
// ============================================================
#define KP 20     // A smem row pitch (fragment-load conflict-free)
#define NP 136    // B smem row pitch (fragment-load conflict-free)

__device__ __forceinline__ uint32_t f2tf32(float v) {
    uint32_t r;
    asm("cvt.rna.tf32.f32 %0, %1;" : "=r"(r) : "f"(v));
    return r;
}
__device__ __forceinline__ void commit4(uint32_t* H, uint32_t* L, int idx, float4 v) {
    uint4 h, l;
    h.x = f2tf32(v.x); l.x = f2tf32(v.x - __uint_as_float(h.x));
    h.y = f2tf32(v.y); l.y = f2tf32(v.y - __uint_as_float(h.y));
    h.z = f2tf32(v.z); l.z = f2tf32(v.z - __uint_as_float(h.z));
    h.w = f2tf32(v.w); l.w = f2tf32(v.w - __uint_as_float(h.w));
    *reinterpret_cast<uint4*>(H + idx) = h;
    *reinterpret_cast<uint4*>(L + idx) = l;
}

#define MMA_TF32(c, a, b0, b1) \
    asm volatile("mma.sync.aligned.m16n8k8.row.col.f32.tf32.tf32.f32 " \
        "{%0,%1,%2,%3}, {%4,%5,%6,%7}, {%8,%9}, {%0,%1,%2,%3};" \
        : "+f"((c)[0]), "+f"((c)[1]), "+f"((c)[2]), "+f"((c)[3]) \
        : "r"((a)[0]), "r"((a)[1]), "r"((a)[2]), "r"((a)[3]), "r"(b0), "r"(b1))

// A[m][k] fp32 row-major (tile pre-offset, lda), B[k][n] fp32 row-major
// (tile col pre-offset, ldb). acc[mt][nt][4] per thread.
__device__ __forceinline__ void tf32_gemm(
    const float* __restrict__ A, int lda,
    const float* __restrict__ Bg, int ldb, int Ktot,
    uint32_t* AH, uint32_t* AL, uint32_t* BH, uint32_t* BL,
    float acc[2][8][4], int t)
{
    const int lane = t & 31, w = t >> 5;
    const int wm = w >> 1, wn = w & 1;
    const int arow = t >> 1, akq = (t & 1) << 3;   // A: row, k-quad base
    const int bk = t >> 4,   bnq = (t & 15) << 3;  // B: k row, n base

    float4 pa0, pa1, pb0, pb1;
    pa0 = *reinterpret_cast<const float4*>(A + arow*lda + akq);
    pa1 = *reinterpret_cast<const float4*>(A + arow*lda + akq + 4);
    pb0 = *reinterpret_cast<const float4*>(Bg + bk*ldb + bnq);
    pb1 = *reinterpret_cast<const float4*>(Bg + bk*ldb + bnq + 4);

    for (int k0 = 0; k0 < Ktot; k0 += 16) {
        commit4(AH, AL, arow*KP + akq,     pa0);
        commit4(AH, AL, arow*KP + akq + 4, pa1);
        commit4(BH, BL, bk*NP + bnq,       pb0);
        commit4(BH, BL, bk*NP + bnq + 4,   pb1);
        __syncthreads();

        if (k0 + 16 < Ktot) {
            pa0 = *reinterpret_cast<const float4*>(A + arow*lda + k0 + 16 + akq);
            pa1 = *reinterpret_cast<const float4*>(A + arow*lda + k0 + 16 + akq + 4);
            pb0 = *reinterpret_cast<const float4*>(Bg + (k0 + 16 + bk)*ldb + bnq);
            pb1 = *reinterpret_cast<const float4*>(Bg + (k0 + 16 + bk)*ldb + bnq + 4);
        }

#pragma unroll
        for (int ks = 0; ks < 16; ks += 8) {
            uint32_t Ah[2][4], Al[2][4];
#pragma unroll
            for (int mt = 0; mt < 2; mt++) {
                int r0 = (wm << 5) + (mt << 4) + (lane >> 2);
                int kk = ks + (lane & 3);
                Ah[mt][0] = AH[r0*KP + kk];       Ah[mt][1] = AH[(r0+8)*KP + kk];
                Ah[mt][2] = AH[r0*KP + kk + 4];   Ah[mt][3] = AH[(r0+8)*KP + kk + 4];
                Al[mt][0] = AL[r0*KP + kk];       Al[mt][1] = AL[(r0+8)*KP + kk];
                Al[mt][2] = AL[r0*KP + kk + 4];   Al[mt][3] = AL[(r0+8)*KP + kk + 4];
            }
#pragma unroll
            for (int nt = 0; nt < 8; nt++) {
                int nb = (wn << 6) + (nt << 3) + (lane >> 2);
                int kr = ks + (lane & 3);
                uint32_t bh0 = BH[kr*NP + nb], bh1 = BH[(kr+4)*NP + nb];
                uint32_t bl0 = BL[kr*NP + nb], bl1 = BL[(kr+4)*NP + nb];
#pragma unroll
                for (int mt = 0; mt < 2; mt++) {
                    MMA_TF32(acc[mt][nt], Ah[mt], bh0, bh1);
                    MMA_TF32(acc[mt][nt], Ah[mt], bl0, bl1);
                    MMA_TF32(acc[mt][nt], Al[mt], bh0, bh1);
                }
            }
        }
        __syncthreads();
    }
}

// ============================================================
// K1a: proj GEMM: Yraw[b][s][o] = sum_c W[o][c] src[b][c][s]
// grid (2, 32, 8=B*2), block 256.  m = o, n = s.
// ============================================================
__global__ __launch_bounds__(256) void proj_gemm_kernel(
    const float* __restrict__ src1, const float* __restrict__ src2,
    const float* __restrict__ W)
{
    __shared__ uint32_t AH[128*KP], AL[128*KP], BH[16*NP], BL[16*NP];
    const int z = blockIdx.z, b = z >> 1, ssel = z & 1;
    const float* src = ssel ? src2 : src1;
    float* Yraw = g_T + ssel*BSC;
    const int m0 = blockIdx.x << 7;   // o
    const int n0 = blockIdx.y << 7;   // s
    const int t = threadIdx.x;
    const int lane = t & 31, w = t >> 5, wm = w >> 1, wn = w & 1;

    float acc[2][8][4];
#pragma unroll
    for (int a = 0; a < 2; a++)
#pragma unroll
        for (int b2_ = 0; b2_ < 8; b2_++)
#pragma unroll
            for (int c = 0; c < 4; c++) acc[a][b2_][c] = 0.f;

    tf32_gemm(W + m0*Cn, Cn, src + b*Cn*Sn + n0, Sn, Cn,
              AH, AL, BH, BL, acc, t);

#pragma unroll
    for (int mt = 0; mt < 2; mt++)
#pragma unroll
    for (int i = 0; i < 2; i++) {
        int o = m0 + (wm << 5) + (mt << 4) + (lane >> 2) + (i << 3);
#pragma unroll
        for (int nt = 0; nt < 8; nt++) {
            int s = n0 + (wn << 6) + (nt << 3) + ((lane & 3) << 1);
            Yraw[(((b << 12) + s    ) << 8) + o] = acc[mt][nt][2*i];
            Yraw[(((b << 12) + s + 1) << 8) + o] = acc[mt][nt][2*i + 1];
        }
    }
}

// ============================================================
// K1b: LN over proj raw. warp per row. grid (2*B*S/8), 256 thr
// ============================================================
__global__ __launch_bounds__(256) void proj_ln_kernel(
    const float* __restrict__ bias, const float* __restrict__ gam,
    const float* __restrict__ bet)
{
    const int gr   = (blockIdx.x << 3) + (threadIdx.x >> 5);
    const int ssel = gr >= Bn*Sn;
    const int row  = ssel ? gr - Bn*Sn : gr;
    const float* Yraw = g_T + ssel*BSC;
    float* Xout       = ssel ? g_X2 : g_X1;
    const int lane = threadIdx.x & 31;
    const int base = row << 8;
    float v[8]; float sum = 0.f, sq = 0.f;
#pragma unroll
    for (int k = 0; k < 8; k++) {
        int o = lane + (k << 5);
        v[k] = Yraw[base + o] + bias[o];
        sum += v[k]; sq += v[k]*v[k];
    }
#pragma unroll
    for (int o = 16; o > 0; o >>= 1) {
        sum += __shfl_xor_sync(0xffffffffu, sum, o);
        sq  += __shfl_xor_sync(0xffffffffu, sq , o);
    }
    float mean = sum * (1.f/256.f);
    float var  = sq  * (1.f/256.f) - mean*mean;
    float rstd = rsqrtf(var + 1e-5f);
#pragma unroll
    for (int k = 0; k < 8; k++) {
        int o = lane + (k << 5);
        Xout[base + o] = (v[k] - mean)*rstd*gam[o] + bet[o];
    }
}

// ============================================================
// attention (unchanged R7 winner)
// ============================================================
#define KP4 260
#define SSP 36
#define ATTN_SMEM_FLOATS (32*KP4*2 + 32*SSP + 96)

__device__ __forceinline__ void attn_tile(
    const float* __restrict__ X2, int b, int kb, int t,
    float* qsm4, float* ksm4, float* ssm,
    float* mrow, float* lrow, float* arow,
    float out0[16], float out1[16])
{
    const int tx = t & 15, ty = t >> 4;
    const int warp = t >> 5, lane = t & 31;

#pragma unroll
    for (int i = 0; i < 32; i++)
        ksm4[i*KP4 + t] = X2[(((b << 12) + (kb << 5) + i) << 8) + t];
    __syncthreads();

    float s00 = 0.f, s01 = 0.f, s10 = 0.f, s11 = 0.f;
    const float4* qa = reinterpret_cast<const float4*>(qsm4 + (2*ty)*KP4);
    const float4* qb = reinterpret_cast<const float4*>(qsm4 + (2*ty+1)*KP4);
    const float4* ka = reinterpret_cast<const float4*>(ksm4 + tx*KP4);
    const float4* kc = reinterpret_cast<const float4*>(ksm4 + (tx+16)*KP4);
#pragma unroll 8
    for (int g = 0; g < 64; g++) {
        float4 A = qa[g], Bq = qb[g], C = ka[g], D = kc[g];
        s00 += A.x*C.x + A.y*C.y + A.z*C.z + A.w*C.w;
        s01 += A.x*D.x + A.y*D.y + A.z*D.z + A.w*D.w;
        s10 += Bq.x*C.x + Bq.y*C.y + Bq.z*C.z + Bq.w*C.w;
        s11 += Bq.x*D.x + Bq.y*D.y + Bq.z*D.z + Bq.w*D.w;
    }
    const float scl = 0.0625f;
    ssm[(2*ty  )*SSP + tx     ] = s00*scl;
    ssm[(2*ty  )*SSP + tx + 16] = s01*scl;
    ssm[(2*ty+1)*SSP + tx     ] = s10*scl;
    ssm[(2*ty+1)*SSP + tx + 16] = s11*scl;
    __syncthreads();

#pragma unroll
    for (int r = 0; r < 4; r++) {
        int row = (warp << 2) + r;
        float sv = ssm[row*SSP + lane];
        float mx = sv;
#pragma unroll
        for (int o = 16; o > 0; o >>= 1)
            mx = fmaxf(mx, __shfl_xor_sync(0xffffffffu, mx, o));
        float mold = mrow[row];
        float mnew = fmaxf(mold, mx);
        float p = __expf(sv - mnew);
        float ps = p;
#pragma unroll
        for (int o = 16; o > 0; o >>= 1)
            ps += __shfl_xor_sync(0xffffffffu, ps, o);
        if (lane == 0) {
            float a = __expf(mold - mnew);
            arow[row] = a;
            lrow[row] = lrow[row]*a + ps;
            mrow[row] = mnew;
        }
        ssm[row*SSP + lane] = p;
    }
    __syncthreads();

    float a0 = arow[2*ty], a1 = arow[2*ty+1];
#pragma unroll
    for (int j = 0; j < 16; j++) { out0[j] *= a0; out1[j] *= a1; }
    const float* p0r = ssm + (2*ty)*SSP;
    const float* p1r = ssm + (2*ty+1)*SSP;
#pragma unroll 4
    for (int k = 0; k < 32; k++) {
        float p0 = p0r[k], p1 = p1r[k];
        const float* vrow = ksm4 + k*KP4 + 4*tx;
#pragma unroll
        for (int g = 0; g < 4; g++) {
            float4 v = *reinterpret_cast<const float4*>(vrow + (g << 6));
            out0[g*4+0] += p0*v.x; out0[g*4+1] += p0*v.y;
            out0[g*4+2] += p0*v.z; out0[g*4+3] += p0*v.w;
            out1[g*4+0] += p1*v.x; out1[g*4+1] += p1*v.y;
            out1[g*4+2] += p1*v.z; out1[g*4+3] += p1*v.w;
        }
    }
    __syncthreads();
}

__global__ __launch_bounds__(256) void attn_kernel(
    const float* __restrict__ X1, const float* __restrict__ X2,
    const int* __restrict__ bidx, int K, float* __restrict__ ATT,
    float* __restrict__ GO, float* __restrict__ GM, float* __restrict__ GL)
{
    extern __shared__ float sm[];
    float* qsm4 = sm;
    float* ksm4 = qsm4 + 32*KP4;
    float* ssm  = ksm4 + 32*KP4;
    float* mrow = ssm + 32*SSP;
    float* lrow = mrow + 32;
    float* arow = lrow + 32;

    const int b = blockIdx.y, x = blockIdx.x;
    const int t = threadIdx.x;
    const int tx = t & 15, ty = t >> 4;
    const bool sparse = (x < NBn - 1);
    const int n = sparse ? (x + 1) : 0;

#pragma unroll
    for (int i = 0; i < 32; i++)
        qsm4[i*KP4 + t] = X1[(((b << 12) + (n << 5) + i) << 8) + t];
    if (t < 32) { mrow[t] = -1e30f; lrow[t] = 0.f; }

    float out0[16], out1[16];
#pragma unroll
    for (int j = 0; j < 16; j++) { out0[j] = 0.f; out1[j] = 0.f; }
    __syncthreads();

    if (sparse) {
        for (int it = 0; it < K; it++) {
            int kb = bidx[(n - 1)*K + it];
            if (it > 0 && kb == 0) break;
            attn_tile(X2, b, kb, t, qsm4, ksm4, ssm, mrow, lrow, arow, out0, out1);
        }
        const float l0 = 1.f / lrow[2*ty];
        const float l1 = 1.f / lrow[2*ty+1];
        const int base0 = (((b << 12) + (n << 5) + 2*ty) << 8) + 4*tx;
        const int base1 = base0 + 256;
#pragma unroll
        for (int g = 0; g < 4; g++) {
            *reinterpret_cast<float4*>(ATT + base0 + (g << 6)) =
                make_float4(out0[g*4+0]*l0, out0[g*4+1]*l0, out0[g*4+2]*l0, out0[g*4+3]*l0);
            *reinterpret_cast<float4*>(ATT + base1 + (g << 6)) =
                make_float4(out1[g*4+0]*l1, out1[g*4+1]*l1, out1[g*4+2]*l1, out1[g*4+3]*l1);
        }
    } else {
        const int split = x - (NBn - 1);
        for (int it = 0; it < NBn/NSPLIT; it++) {
            int kb = split*(NBn/NSPLIT) + it;
            attn_tile(X2, b, kb, t, qsm4, ksm4, ssm, mrow, lrow, arow, out0, out1);
        }
        const int gi = (b*NSPLIT + split)*32;
        const int base0 = ((gi + 2*ty) << 8) + 4*tx;
        const int base1 = base0 + 256;
#pragma unroll
        for (int g = 0; g < 4; g++) {
            *reinterpret_cast<float4*>(GO + base0 + (g << 6)) =
                make_float4(out0[g*4+0], out0[g*4+1], out0[g*4+2], out0[g*4+3]);
            *reinterpret_cast<float4*>(GO + base1 + (g << 6)) =
                make_float4(out1[g*4+0], out1[g*4+1], out1[g*4+2], out1[g*4+3]);
        }
        if (t < 32) { GM[gi + t] = mrow[t]; GL[gi + t] = lrow[t]; }
    }
}

__global__ __launch_bounds__(256) void attn_global_combine(
    const float* __restrict__ GO, const float* __restrict__ GM,
    const float* __restrict__ GL, float* __restrict__ ATT)
{
    const int b = blockIdx.x, q = blockIdx.y, t = threadIdx.x;
    float ms[NSPLIT], ls[NSPLIT];
    float M = -1e30f;
#pragma unroll
    for (int i = 0; i < NSPLIT; i++) {
        ms[i] = GM[(b*NSPLIT + i)*32 + q];
        ls[i] = GL[(b*NSPLIT + i)*32 + q];
        M = fmaxf(M, ms[i]);
    }
    float L = 0.f, acc = 0.f;
#pragma unroll
    for (int i = 0; i < NSPLIT; i++) {
        float e = __expf(ms[i] - M);
        L   += ls[i] * e;
        acc += GO[(((b*NSPLIT + i)*32 + q) << 8) + t] * e;
    }
    ATT[(((b << 12) + q) << 8) + t] = acc / L;
}

// ============================================================
// K3: H = LN(X1 + ATT)
// ============================================================
__global__ __launch_bounds__(256) void add_ln_kernel(
    const float* __restrict__ X1, const float* __restrict__ ATT,
    const float* __restrict__ gam, const float* __restrict__ bet,
    float* __restrict__ H)
{
    const int row  = (blockIdx.x << 3) + (threadIdx.x >> 5);
    const int lane = threadIdx.x & 31;
    const int base = row << 8;
    float v[8]; float sum = 0.f, sq = 0.f;
#pragma unroll
    for (int k = 0; k < 8; k++) {
        int o = lane + (k << 5);
        v[k] = X1[base + o] + ATT[base + o];
        sum += v[k]; sq += v[k]*v[k];
    }
#pragma unroll
    for (int o = 16; o > 0; o >>= 1) {
        sum += __shfl_xor_sync(0xffffffffu, sum, o);
        sq  += __shfl_xor_sync(0xffffffffu, sq , o);
    }
    float mean = sum * (1.f/256.f);
    float var  = sq  * (1.f/256.f) - mean*mean;
    float rstd = rsqrtf(var + 1e-5f);
#pragma unroll
    for (int k = 0; k < 8; k++) {
        int o = lane + (k << 5);
        H[base + o] = (v[k] - mean)*rstd*gam[o] + bet[o];
    }
}

// ============================================================
// K4: ffn1: T = gelu(H @ w1 + b1). grid (128, 8), 256 thr
// ============================================================
__global__ __launch_bounds__(256) void ffn1_kernel(
    const float* __restrict__ H, const float* __restrict__ w1,
    const float* __restrict__ b1, float* __restrict__ T)
{
    __shared__ uint32_t AH[128*KP], AL[128*KP], BH[16*NP], BL[16*NP];
    const int m0 = blockIdx.x << 7, n0 = blockIdx.y << 7;
    const int t = threadIdx.x;
    const int lane = t & 31, w = t >> 5, wm = w >> 1, wn = w & 1;

    float acc[2][8][4];
#pragma unroll
    for (int a = 0; a < 2; a++)
#pragma unroll
        for (int b_ = 0; b_ < 8; b_++)
#pragma unroll
            for (int c = 0; c < 4; c++) acc[a][b_][c] = 0.f;

    tf32_gemm(H + m0*Cn, Cn, w1 + n0, DFFn, Cn, AH, AL, BH, BL, acc, t);

#pragma unroll
    for (int mt = 0; mt < 2; mt++)
#pragma unroll
    for (int i = 0; i < 2; i++) {
        int m = m0 + (wm << 5) + (mt << 4) + (lane >> 2) + (i << 3);
#pragma unroll
        for (int nt = 0; nt < 8; nt++) {
            int n = n0 + (wn << 6) + (nt << 3) + ((lane & 3) << 1);
            float x0 = acc[mt][nt][2*i]   + b1[n];
            float x1 = acc[mt][nt][2*i+1] + b1[n+1];
            float g0 = 0.5f*x0*(1.f + erff(x0*0.70710678118654752f));
            float g1 = 0.5f*x1*(1.f + erff(x1*0.70710678118654752f));
            *reinterpret_cast<float2*>(T + m*DFFn + n) = make_float2(g0, g1);
        }
    }
}

// ============================================================
// K5: ffn2: Out(B,C,S) = transpose(H + T @ w2 + b2). grid (128, 2), 256 thr
// ============================================================
__global__ __launch_bounds__(256) void ffn2_kernel(
    const float* __restrict__ T, const float* __restrict__ w2,
    const float* __restrict__ b2, const float* __restrict__ H,
    float* __restrict__ Out)
{
    __shared__ uint32_t AH[128*KP], AL[128*KP], BH[16*NP], BL[16*NP];
    const int m0 = blockIdx.x << 7, n0 = blockIdx.y << 7;
    const int t = threadIdx.x;
    const int lane = t & 31, w = t >> 5, wm = w >> 1, wn = w & 1;

    float acc[2][8][4];
#pragma unroll
    for (int a = 0; a < 2; a++)
#pragma unroll
        for (int b_ = 0; b_ < 8; b_++)
#pragma unroll
            for (int c = 0; c < 4; c++) acc[a][b_][c] = 0.f;

    tf32_gemm(T + m0*DFFn, DFFn, w2 + n0, Cn, DFFn, AH, AL, BH, BL, acc, t);

#pragma unroll
    for (int mt = 0; mt < 2; mt++)
#pragma unroll
    for (int i = 0; i < 2; i++) {
        int m = m0 + (wm << 5) + (mt << 4) + (lane >> 2) + (i << 3);
        int b = m >> 12;
        int s = m & 4095;
#pragma unroll
        for (int nt = 0; nt < 8; nt++) {
            int n = n0 + (wn << 6) + (nt << 3) + ((lane & 3) << 1);
            float2 h2 = *reinterpret_cast<const float2*>(H + m*Cn + n);
            float v0 = acc[mt][nt][2*i]   + b2[n]   + h2.x;
            float v1 = acc[mt][nt][2*i+1] + b2[n+1] + h2.y;
            Out[(((b << 8) + n    ) << 12) + s] = v0;
            Out[(((b << 8) + n + 1) << 12) + s] = v1;
        }
    }
}

// ============================================================
extern "C" void kernel_launch(void* const* d_in, const int* in_sizes, int n_in,
                              void* d_out, int out_size)
{
    const float* src1  = (const float*)d_in[0];
    const float* src2  = (const float*)d_in[1];
    const float* wproj = (const float*)d_in[2];
    const float* bproj = (const float*)d_in[3];
    const float* g13   = (const float*)d_in[4];
    const float* be13  = (const float*)d_in[5];
    const float* g12   = (const float*)d_in[6];
    const float* be12  = (const float*)d_in[7];
    const float* w1    = (const float*)d_in[8];
    const float* b1    = (const float*)d_in[9];
    const float* w2    = (const float*)d_in[10];
    const float* b2    = (const float*)d_in[11];
    const int*   bidx  = (const int*)d_in[12];
    const int K = in_sizes[12] / (NBn - 1);
    float* out = (float*)d_out;

    float *X1, *X2, *ATT, *H, *T, *GO, *GM, *GL;
    cudaGetSymbolAddress((void**)&X1,  g_X1);
    cudaGetSymbolAddress((void**)&X2,  g_X2);
    cudaGetSymbolAddress((void**)&ATT, g_ATT);
    cudaGetSymbolAddress((void**)&H,   g_H);
    cudaGetSymbolAddress((void**)&T,   g_T);
    cudaGetSymbolAddress((void**)&GO,  g_GO);
    cudaGetSymbolAddress((void**)&GM,  g_GM);
    cudaGetSymbolAddress((void**)&GL,  g_GL);

    const int attn_smem = ATTN_SMEM_FLOATS * 4;
    cudaFuncSetAttribute(attn_kernel, cudaFuncAttributeMaxDynamicSharedMemorySize, attn_smem);

    proj_gemm_kernel<<<dim3(2, 32, Bn*2), 256>>>(src1, src2, wproj);
    proj_ln_kernel<<<(2*Bn*Sn)/8, 256>>>(bproj, g13, be13);

    attn_kernel<<<dim3(NBn - 1 + NSPLIT, Bn), 256, attn_smem>>>(
        X1, X2, bidx, K, ATT, GO, GM, GL);
    attn_global_combine<<<dim3(Bn, 32), 256>>>(GO, GM, GL, ATT);

    add_ln_kernel<<<(Bn*Sn)/8, 256>>>(X1, ATT, g12, be12, H);

    ffn1_kernel<<<dim3((Bn*Sn)/128, DFFn/128), 256>>>(H, w1, b1, T);
    ffn2_kernel<<<dim3((Bn*Sn)/128, Cn/128), 256>>>(T, w2, b2, H, out);
}

// round 10
// speedup vs baseline: 12.1773x; 1.4375x over previous
#include <cuda_runtime.h>
#include <cuda_fp16.h>
#include <math.h>
#include <stdint.h>

#define Bn   4
#define Cn   256
#define Sn   4096
#define DFFn 1024
#define NBn  128
#define NSPLIT 16

#define BSC (Bn*Sn*Cn)
#define BST (Bn*Sn*DFFn)

// ---- scratch ----
__device__ float g_X1[BSC];
__device__ float g_X2[BSC];
__device__ float g_ATT[BSC];
__device__ float g_H[BSC];
__device__ float g_T[BST];          // ffn hidden; also proj raw output
__device__ float g_GO[Bn*NSPLIT*32*256];
__device__ float g_GM[Bn*NSPLIT*32];
__device__ float g_GL[Bn*NSPLIT*32];

// ============================================================
// split-FP16 (3-pass) mma.sync m16n8k16 GEMM: 128x128 tile, 256 thr,
// 8 warps (4m x 2n), warp tile 32x64, K-chunk 16.
// A smem [m][kp] uint32(half2), pitch 12 (fragment-load conflict-free)
// B smem [kp][n] uint32(half2), pitch 136 (fragment-load conflict-free)
// ============================================================
#define AP 12
#define BP 136

__device__ __forceinline__ void split2(float a, float b, uint32_t& h, uint32_t& l) {
    __half ha = __float2half_rn(a), hb = __float2half_rn(b);
    __half la = __float2half_rn(a - __half2float(ha));
    __half lb = __float2half_rn(b - __half2float(hb));
    __half2 hh = __halves2half2(ha, hb), ll = __halves2half2(la, lb);
    h = *reinterpret_cast<const uint32_t*>(&hh);
    l = *reinterpret_cast<const uint32_t*>(&ll);
}

#define MMA_F16(c, a, b0, b1) \
    asm volatile("mma.sync.aligned.m16n8k16.row.col.f32.f16.f16.f32 " \
        "{%0,%1,%2,%3}, {%4,%5,%6,%7}, {%8,%9}, {%0,%1,%2,%3};" \
        : "+f"((c)[0]), "+f"((c)[1]), "+f"((c)[2]), "+f"((c)[3]) \
        : "r"((a)[0]), "r"((a)[1]), "r"((a)[2]), "r"((a)[3]), "r"(b0), "r"(b1))

// A[m][k] fp32 row-major (tile pre-offset), B[k][n] fp32 row-major (tile
// col pre-offset). acc[mt][nt][4].
__device__ __forceinline__ void f16_gemm(
    const float* __restrict__ A, int lda,
    const float* __restrict__ Bg, int ldb, int Ktot,
    uint32_t* AH, uint32_t* AL, uint32_t* BH, uint32_t* BL,
    float acc[2][8][4], int t)
{
    const int lane = t & 31, w = t >> 5;
    const int wm = w >> 1, wn = w & 1;
    const int q = lane & 3;
    // A staging: thread -> (m = t>>1, khalf = t&1), 8 floats
    const int am = t >> 1, akh = t & 1;
    // B staging: thread -> (kpair = t>>5, n = (t&31)*4), rows 2kp, 2kp+1
    const int bkp = t >> 5, bn = (lane) << 2;

    float4 pa0, pa1, pb0, pb1;
    pa0 = *reinterpret_cast<const float4*>(A + am*lda + 8*akh);
    pa1 = *reinterpret_cast<const float4*>(A + am*lda + 8*akh + 4);
    pb0 = *reinterpret_cast<const float4*>(Bg + (2*bkp    )*ldb + bn);
    pb1 = *reinterpret_cast<const float4*>(Bg + (2*bkp + 1)*ldb + bn);

    for (int k0 = 0; k0 < Ktot; k0 += 16) {
        // commit A: half2 pairs (k-adjacent) -> kp = 4*akh + j
        {
            uint4 h, l;
            split2(pa0.x, pa0.y, h.x, l.x);
            split2(pa0.z, pa0.w, h.y, l.y);
            split2(pa1.x, pa1.y, h.z, l.z);
            split2(pa1.z, pa1.w, h.w, l.w);
            *reinterpret_cast<uint4*>(AH + am*AP + 4*akh) = h;
            *reinterpret_cast<uint4*>(AL + am*AP + 4*akh) = l;
        }
        // commit B: half2 c = (B[2kp][n+c], B[2kp+1][n+c])
        {
            uint4 h, l;
            split2(pb0.x, pb1.x, h.x, l.x);
            split2(pb0.y, pb1.y, h.y, l.y);
            split2(pb0.z, pb1.z, h.z, l.z);
            split2(pb0.w, pb1.w, h.w, l.w);
            *reinterpret_cast<uint4*>(BH + bkp*BP + bn) = h;
            *reinterpret_cast<uint4*>(BL + bkp*BP + bn) = l;
        }
        __syncthreads();

        if (k0 + 16 < Ktot) {
            pa0 = *reinterpret_cast<const float4*>(A + am*lda + k0 + 16 + 8*akh);
            pa1 = *reinterpret_cast<const float4*>(A + am*lda + k0 + 16 + 8*akh + 4);
            pb0 = *reinterpret_cast<const float4*>(Bg + (k0 + 16 + 2*bkp    )*ldb + bn);
            pb1 = *reinterpret_cast<const float4*>(Bg + (k0 + 16 + 2*bkp + 1)*ldb + bn);
        }

        uint32_t Ah[2][4], Al[2][4];
#pragma unroll
        for (int mt = 0; mt < 2; mt++) {
            int r0 = (wm << 5) + (mt << 4) + (lane >> 2);
            Ah[mt][0] = AH[r0*AP + q];     Ah[mt][1] = AH[(r0+8)*AP + q];
            Ah[mt][2] = AH[r0*AP + q + 4]; Ah[mt][3] = AH[(r0+8)*AP + q + 4];
            Al[mt][0] = AL[r0*AP + q];     Al[mt][1] = AL[(r0+8)*AP + q];
            Al[mt][2] = AL[r0*AP + q + 4]; Al[mt][3] = AL[(r0+8)*AP + q + 4];
        }
#pragma unroll
        for (int nt = 0; nt < 8; nt++) {
            int nb = (wn << 6) + (nt << 3) + (lane >> 2);
            uint32_t bh0 = BH[q*BP + nb], bh1 = BH[(q+4)*BP + nb];
            uint32_t bl0 = BL[q*BP + nb], bl1 = BL[(q+4)*BP + nb];
#pragma unroll
            for (int mt = 0; mt < 2; mt++) {
                MMA_F16(acc[mt][nt], Ah[mt], bh0, bh1);
                MMA_F16(acc[mt][nt], Ah[mt], bl0, bl1);
                MMA_F16(acc[mt][nt], Al[mt], bh0, bh1);
            }
        }
        __syncthreads();
    }
}

#define GEMM_SM_DECL \
    __shared__ uint32_t AH[128*AP], AL[128*AP], BH[8*BP], BL[8*BP]

// ============================================================
// K1a: proj GEMM: Yraw[b][s][o] = sum_c W[o][c] src[b][c][s]
// grid (2, 32, 8=B*2), block 256.  m = o, n = s.
// ============================================================
__global__ __launch_bounds__(256) void proj_gemm_kernel(
    const float* __restrict__ src1, const float* __restrict__ src2,
    const float* __restrict__ W)
{
    GEMM_SM_DECL;
    const int z = blockIdx.z, b = z >> 1, ssel = z & 1;
    const float* src = ssel ? src2 : src1;
    float* Yraw = g_T + ssel*BSC;
    const int m0 = blockIdx.x << 7;   // o
    const int n0 = blockIdx.y << 7;   // s
    const int t = threadIdx.x;
    const int lane = t & 31, w = t >> 5, wm = w >> 1, wn = w & 1;

    float acc[2][8][4];
#pragma unroll
    for (int a = 0; a < 2; a++)
#pragma unroll
        for (int b2_ = 0; b2_ < 8; b2_++)
#pragma unroll
            for (int c = 0; c < 4; c++) acc[a][b2_][c] = 0.f;

    f16_gemm(W + m0*Cn, Cn, src + b*Cn*Sn + n0, Sn, Cn,
             AH, AL, BH, BL, acc, t);

#pragma unroll
    for (int mt = 0; mt < 2; mt++)
#pragma unroll
    for (int i = 0; i < 2; i++) {
        int o = m0 + (wm << 5) + (mt << 4) + (lane >> 2) + (i << 3);
#pragma unroll
        for (int nt = 0; nt < 8; nt++) {
            int s = n0 + (wn << 6) + (nt << 3) + ((lane & 3) << 1);
            Yraw[(((b << 12) + s    ) << 8) + o] = acc[mt][nt][2*i];
            Yraw[(((b << 12) + s + 1) << 8) + o] = acc[mt][nt][2*i + 1];
        }
    }
}

// ============================================================
// K1b: LN over proj raw. warp per row. grid (2*B*S/8), 256 thr
// ============================================================
__global__ __launch_bounds__(256) void proj_ln_kernel(
    const float* __restrict__ bias, const float* __restrict__ gam,
    const float* __restrict__ bet)
{
    const int gr   = (blockIdx.x << 3) + (threadIdx.x >> 5);
    const int ssel = gr >= Bn*Sn;
    const int row  = ssel ? gr - Bn*Sn : gr;
    const float* Yraw = g_T + ssel*BSC;
    float* Xout       = ssel ? g_X2 : g_X1;
    const int lane = threadIdx.x & 31;
    const int base = row << 8;
    float v[8]; float sum = 0.f, sq = 0.f;
#pragma unroll
    for (int k = 0; k < 8; k++) {
        int o = lane + (k << 5);
        v[k] = Yraw[base + o] + bias[o];
        sum += v[k]; sq += v[k]*v[k];
    }
#pragma unroll
    for (int o = 16; o > 0; o >>= 1) {
        sum += __shfl_xor_sync(0xffffffffu, sum, o);
        sq  += __shfl_xor_sync(0xffffffffu, sq , o);
    }
    float mean = sum * (1.f/256.f);
    float var  = sq  * (1.f/256.f) - mean*mean;
    float rstd = rsqrtf(var + 1e-5f);
#pragma unroll
    for (int k = 0; k < 8; k++) {
        int o = lane + (k << 5);
        Xout[base + o] = (v[k] - mean)*rstd*gam[o] + bet[o];
    }
}

// ============================================================
// attention (unchanged R7 winner)
// ============================================================
#define KP4 260
#define SSP 36
#define ATTN_SMEM_FLOATS (32*KP4*2 + 32*SSP + 96)

__device__ __forceinline__ void attn_tile(
    const float* __restrict__ X2, int b, int kb, int t,
    float* qsm4, float* ksm4, float* ssm,
    float* mrow, float* lrow, float* arow,
    float out0[16], float out1[16])
{
    const int tx = t & 15, ty = t >> 4;
    const int warp = t >> 5, lane = t & 31;

#pragma unroll
    for (int i = 0; i < 32; i++)
        ksm4[i*KP4 + t] = X2[(((b << 12) + (kb << 5) + i) << 8) + t];
    __syncthreads();

    float s00 = 0.f, s01 = 0.f, s10 = 0.f, s11 = 0.f;
    const float4* qa = reinterpret_cast<const float4*>(qsm4 + (2*ty)*KP4);
    const float4* qb = reinterpret_cast<const float4*>(qsm4 + (2*ty+1)*KP4);
    const float4* ka = reinterpret_cast<const float4*>(ksm4 + tx*KP4);
    const float4* kc = reinterpret_cast<const float4*>(ksm4 + (tx+16)*KP4);
#pragma unroll 8
    for (int g = 0; g < 64; g++) {
        float4 A = qa[g], Bq = qb[g], C = ka[g], D = kc[g];
        s00 += A.x*C.x + A.y*C.y + A.z*C.z + A.w*C.w;
        s01 += A.x*D.x + A.y*D.y + A.z*D.z + A.w*D.w;
        s10 += Bq.x*C.x + Bq.y*C.y + Bq.z*C.z + Bq.w*C.w;
        s11 += Bq.x*D.x + Bq.y*D.y + Bq.z*D.z + Bq.w*D.w;
    }
    const float scl = 0.0625f;
    ssm[(2*ty  )*SSP + tx     ] = s00*scl;
    ssm[(2*ty  )*SSP + tx + 16] = s01*scl;
    ssm[(2*ty+1)*SSP + tx     ] = s10*scl;
    ssm[(2*ty+1)*SSP + tx + 16] = s11*scl;
    __syncthreads();

#pragma unroll
    for (int r = 0; r < 4; r++) {
        int row = (warp << 2) + r;
        float sv = ssm[row*SSP + lane];
        float mx = sv;
#pragma unroll
        for (int o = 16; o > 0; o >>= 1)
            mx = fmaxf(mx, __shfl_xor_sync(0xffffffffu, mx, o));
        float mold = mrow[row];
        float mnew = fmaxf(mold, mx);
        float p = __expf(sv - mnew);
        float ps = p;
#pragma unroll
        for (int o = 16; o > 0; o >>= 1)
            ps += __shfl_xor_sync(0xffffffffu, ps, o);
        if (lane == 0) {
            float a = __expf(mold - mnew);
            arow[row] = a;
            lrow[row] = lrow[row]*a + ps;
            mrow[row] = mnew;
        }
        ssm[row*SSP + lane] = p;
    }
    __syncthreads();

    float a0 = arow[2*ty], a1 = arow[2*ty+1];
#pragma unroll
    for (int j = 0; j < 16; j++) { out0[j] *= a0; out1[j] *= a1; }
    const float* p0r = ssm + (2*ty)*SSP;
    const float* p1r = ssm + (2*ty+1)*SSP;
#pragma unroll 4
    for (int k = 0; k < 32; k++) {
        float p0 = p0r[k], p1 = p1r[k];
        const float* vrow = ksm4 + k*KP4 + 4*tx;
#pragma unroll
        for (int g = 0; g < 4; g++) {
            float4 v = *reinterpret_cast<const float4*>(vrow + (g << 6));
            out0[g*4+0] += p0*v.x; out0[g*4+1] += p0*v.y;
            out0[g*4+2] += p0*v.z; out0[g*4+3] += p0*v.w;
            out1[g*4+0] += p1*v.x; out1[g*4+1] += p1*v.y;
            out1[g*4+2] += p1*v.z; out1[g*4+3] += p1*v.w;
        }
    }
    __syncthreads();
}

__global__ __launch_bounds__(256) void attn_kernel(
    const float* __restrict__ X1, const float* __restrict__ X2,
    const int* __restrict__ bidx, int K, float* __restrict__ ATT,
    float* __restrict__ GO, float* __restrict__ GM, float* __restrict__ GL)
{
    extern __shared__ float sm[];
    float* qsm4 = sm;
    float* ksm4 = qsm4 + 32*KP4;
    float* ssm  = ksm4 + 32*KP4;
    float* mrow = ssm + 32*SSP;
    float* lrow = mrow + 32;
    float* arow = lrow + 32;

    const int b = blockIdx.y, x = blockIdx.x;
    const int t = threadIdx.x;
    const int tx = t & 15, ty = t >> 4;
    const bool sparse = (x < NBn - 1);
    const int n = sparse ? (x + 1) : 0;

#pragma unroll
    for (int i = 0; i < 32; i++)
        qsm4[i*KP4 + t] = X1[(((b << 12) + (n << 5) + i) << 8) + t];
    if (t < 32) { mrow[t] = -1e30f; lrow[t] = 0.f; }

    float out0[16], out1[16];
#pragma unroll
    for (int j = 0; j < 16; j++) { out0[j] = 0.f; out1[j] = 0.f; }
    __syncthreads();

    if (sparse) {
        for (int it = 0; it < K; it++) {
            int kb = bidx[(n - 1)*K + it];
            if (it > 0 && kb == 0) break;
            attn_tile(X2, b, kb, t, qsm4, ksm4, ssm, mrow, lrow, arow, out0, out1);
        }
        const float l0 = 1.f / lrow[2*ty];
        const float l1 = 1.f / lrow[2*ty+1];
        const int base0 = (((b << 12) + (n << 5) + 2*ty) << 8) + 4*tx;
        const int base1 = base0 + 256;
#pragma unroll
        for (int g = 0; g < 4; g++) {
            *reinterpret_cast<float4*>(ATT + base0 + (g << 6)) =
                make_float4(out0[g*4+0]*l0, out0[g*4+1]*l0, out0[g*4+2]*l0, out0[g*4+3]*l0);
            *reinterpret_cast<float4*>(ATT + base1 + (g << 6)) =
                make_float4(out1[g*4+0]*l1, out1[g*4+1]*l1, out1[g*4+2]*l1, out1[g*4+3]*l1);
        }
    } else {
        const int split = x - (NBn - 1);
        for (int it = 0; it < NBn/NSPLIT; it++) {
            int kb = split*(NBn/NSPLIT) + it;
            attn_tile(X2, b, kb, t, qsm4, ksm4, ssm, mrow, lrow, arow, out0, out1);
        }
        const int gi = (b*NSPLIT + split)*32;
        const int base0 = ((gi + 2*ty) << 8) + 4*tx;
        const int base1 = base0 + 256;
#pragma unroll
        for (int g = 0; g < 4; g++) {
            *reinterpret_cast<float4*>(GO + base0 + (g << 6)) =
                make_float4(out0[g*4+0], out0[g*4+1], out0[g*4+2], out0[g*4+3]);
            *reinterpret_cast<float4*>(GO + base1 + (g << 6)) =
                make_float4(out1[g*4+0], out1[g*4+1], out1[g*4+2], out1[g*4+3]);
        }
        if (t < 32) { GM[gi + t] = mrow[t]; GL[gi + t] = lrow[t]; }
    }
}

__global__ __launch_bounds__(256) void attn_global_combine(
    const float* __restrict__ GO, const float* __restrict__ GM,
    const float* __restrict__ GL, float* __restrict__ ATT)
{
    const int b = blockIdx.x, q = blockIdx.y, t = threadIdx.x;
    float ms[NSPLIT], ls[NSPLIT];
    float M = -1e30f;
#pragma unroll
    for (int i = 0; i < NSPLIT; i++) {
        ms[i] = GM[(b*NSPLIT + i)*32 + q];
        ls[i] = GL[(b*NSPLIT + i)*32 + q];
        M = fmaxf(M, ms[i]);
    }
    float L = 0.f, acc = 0.f;
#pragma unroll
    for (int i = 0; i < NSPLIT; i++) {
        float e = __expf(ms[i] - M);
        L   += ls[i] * e;
        acc += GO[(((b*NSPLIT + i)*32 + q) << 8) + t] * e;
    }
    ATT[(((b << 12) + q) << 8) + t] = acc / L;
}

// ============================================================
// K3: H = LN(X1 + ATT)
// ============================================================
__global__ __launch_bounds__(256) void add_ln_kernel(
    const float* __restrict__ X1, const float* __restrict__ ATT,
    const float* __restrict__ gam, const float* __restrict__ bet,
    float* __restrict__ H)
{
    const int row  = (blockIdx.x << 3) + (threadIdx.x >> 5);
    const int lane = threadIdx.x & 31;
    const int base = row << 8;
    float v[8]; float sum = 0.f, sq = 0.f;
#pragma unroll
    for (int k = 0; k < 8; k++) {
        int o = lane + (k << 5);
        v[k] = X1[base + o] + ATT[base + o];
        sum += v[k]; sq += v[k]*v[k];
    }
#pragma unroll
    for (int o = 16; o > 0; o >>= 1) {
        sum += __shfl_xor_sync(0xffffffffu, sum, o);
        sq  += __shfl_xor_sync(0xffffffffu, sq , o);
    }
    float mean = sum * (1.f/256.f);
    float var  = sq  * (1.f/256.f) - mean*mean;
    float rstd = rsqrtf(var + 1e-5f);
#pragma unroll
    for (int k = 0; k < 8; k++) {
        int o = lane + (k << 5);
        H[base + o] = (v[k] - mean)*rstd*gam[o] + bet[o];
    }
}

// ============================================================
// K4: ffn1: T = gelu(H @ w1 + b1). grid (128, 8), 256 thr
// ============================================================
__global__ __launch_bounds__(256) void ffn1_kernel(
    const float* __restrict__ H, const float* __restrict__ w1,
    const float* __restrict__ b1, float* __restrict__ T)
{
    GEMM_SM_DECL;
    const int m0 = blockIdx.x << 7, n0 = blockIdx.y << 7;
    const int t = threadIdx.x;
    const int lane = t & 31, w = t >> 5, wm = w >> 1, wn = w & 1;

    float acc[2][8][4];
#pragma unroll
    for (int a = 0; a < 2; a++)
#pragma unroll
        for (int b_ = 0; b_ < 8; b_++)
#pragma unroll
            for (int c = 0; c < 4; c++) acc[a][b_][c] = 0.f;

    f16_gemm(H + m0*Cn, Cn, w1 + n0, DFFn, Cn, AH, AL, BH, BL, acc, t);

#pragma unroll
    for (int mt = 0; mt < 2; mt++)
#pragma unroll
    for (int i = 0; i < 2; i++) {
        int m = m0 + (wm << 5) + (mt << 4) + (lane >> 2) + (i << 3);
#pragma unroll
        for (int nt = 0; nt < 8; nt++) {
            int n = n0 + (wn << 6) + (nt << 3) + ((lane & 3) << 1);
            float x0 = acc[mt][nt][2*i]   + b1[n];
            float x1 = acc[mt][nt][2*i+1] + b1[n+1];
            float g0 = 0.5f*x0*(1.f + erff(x0*0.70710678118654752f));
            float g1 = 0.5f*x1*(1.f + erff(x1*0.70710678118654752f));
            *reinterpret_cast<float2*>(T + m*DFFn + n) = make_float2(g0, g1);
        }
    }
}

// ============================================================
// K5: ffn2: Out(B,C,S) = transpose(H + T @ w2 + b2). grid (128, 2), 256 thr
// ============================================================
__global__ __launch_bounds__(256) void ffn2_kernel(
    const float* __restrict__ T, const float* __restrict__ w2,
    const float* __restrict__ b2, const float* __restrict__ H,
    float* __restrict__ Out)
{
    GEMM_SM_DECL;
    const int m0 = blockIdx.x << 7, n0 = blockIdx.y << 7;
    const int t = threadIdx.x;
    const int lane = t & 31, w = t >> 5, wm = w >> 1, wn = w & 1;

    float acc[2][8][4];
#pragma unroll
    for (int a = 0; a < 2; a++)
#pragma unroll
        for (int b_ = 0; b_ < 8; b_++)
#pragma unroll
            for (int c = 0; c < 4; c++) acc[a][b_][c] = 0.f;

    f16_gemm(T + m0*DFFn, DFFn, w2 + n0, Cn, DFFn, AH, AL, BH, BL, acc, t);

#pragma unroll
    for (int mt = 0; mt < 2; mt++)
#pragma unroll
    for (int i = 0; i < 2; i++) {
        int m = m0 + (wm << 5) + (mt << 4) + (lane >> 2) + (i << 3);
        int b = m >> 12;
        int s = m & 4095;
#pragma unroll
        for (int nt = 0; nt < 8; nt++) {
            int n = n0 + (wn << 6) + (nt << 3) + ((lane & 3) << 1);
            float2 h2 = *reinterpret_cast<const float2*>(H + m*Cn + n);
            float v0 = acc[mt][nt][2*i]   + b2[n]   + h2.x;
            float v1 = acc[mt][nt][2*i+1] + b2[n+1] + h2.y;
            Out[(((b << 8) + n    ) << 12) + s] = v0;
            Out[(((b << 8) + n + 1) << 12) + s] = v1;
        }
    }
}

// ============================================================
extern "C" void kernel_launch(void* const* d_in, const int* in_sizes, int n_in,
                              void* d_out, int out_size)
{
    const float* src1  = (const float*)d_in[0];
    const float* src2  = (const float*)d_in[1];
    const float* wproj = (const float*)d_in[2];
    const float* bproj = (const float*)d_in[3];
    const float* g13   = (const float*)d_in[4];
    const float* be13  = (const float*)d_in[5];
    const float* g12   = (const float*)d_in[6];
    const float* be12  = (const float*)d_in[7];
    const float* w1    = (const float*)d_in[8];
    const float* b1    = (const float*)d_in[9];
    const float* w2    = (const float*)d_in[10];
    const float* b2    = (const float*)d_in[11];
    const int*   bidx  = (const int*)d_in[12];
    const int K = in_sizes[12] / (NBn - 1);
    float* out = (float*)d_out;

    float *X1, *X2, *ATT, *H, *T, *GO, *GM, *GL;
    cudaGetSymbolAddress((void**)&X1,  g_X1);
    cudaGetSymbolAddress((void**)&X2,  g_X2);
    cudaGetSymbolAddress((void**)&ATT, g_ATT);
    cudaGetSymbolAddress((void**)&H,   g_H);
    cudaGetSymbolAddress((void**)&T,   g_T);
    cudaGetSymbolAddress((void**)&GO,  g_GO);
    cudaGetSymbolAddress((void**)&GM,  g_GM);
    cudaGetSymbolAddress((void**)&GL,  g_GL);

    const int attn_smem = ATTN_SMEM_FLOATS * 4;
    cudaFuncSetAttribute(attn_kernel, cudaFuncAttributeMaxDynamicSharedMemorySize, attn_smem);

    proj_gemm_kernel<<<dim3(2, 32, Bn*2), 256>>>(src1, src2, wproj);
    proj_ln_kernel<<<(2*Bn*Sn)/8, 256>>>(bproj, g13, be13);

    attn_kernel<<<dim3(NBn - 1 + NSPLIT, Bn), 256, attn_smem>>>(
        X1, X2, bidx, K, ATT, GO, GM, GL);
    attn_global_combine<<<dim3(Bn, 32), 256>>>(GO, GM, GL, ATT);

    add_ln_kernel<<<(Bn*Sn)/8, 256>>>(X1, ATT, g12, be12, H);

    ffn1_kernel<<<dim3((Bn*Sn)/128, DFFn/128), 256>>>(H, w1, b1, T);
    ffn2_kernel<<<dim3((Bn*Sn)/128, Cn/128), 256>>>(T, w2, b2, H, out);
}

// round 12
// speedup vs baseline: 14.2102x; 1.1669x over previous
#include <cuda_runtime.h>
#include <cuda_fp16.h>
#include <math.h>
#include <stdint.h>

#define Bn   4
#define Cn   256
#define Sn   4096
#define DFFn 1024
#define NBn  128
#define NSPLIT 16

#define BSC (Bn*Sn*Cn)
#define BST (Bn*Sn*DFFn)

// ---- scratch ----
__device__ float g_X1[BSC];
__device__ float g_X2[BSC];
__device__ float g_ATT[BSC];
__device__ float g_H[BSC];
__device__ float g_T[BST];          // ffn hidden; also proj raw output
__device__ float g_GO[Bn*NSPLIT*32*256];
__device__ float g_GM[Bn*NSPLIT*32];
__device__ float g_GL[Bn*NSPLIT*32];

// ============================================================
// shared fp16-split helpers
// ============================================================
__device__ __forceinline__ void split2(float a, float b, uint32_t& h, uint32_t& l) {
    __half ha = __float2half_rn(a), hb = __float2half_rn(b);
    __half la = __float2half_rn(a - __half2float(ha));
    __half lb = __float2half_rn(b - __half2float(hb));
    __half2 hh = __halves2half2(ha, hb), ll = __halves2half2(la, lb);
    h = *reinterpret_cast<const uint32_t*>(&hh);
    l = *reinterpret_cast<const uint32_t*>(&ll);
}

#define MMA_F16(c, a, b0, b1) \
    asm volatile("mma.sync.aligned.m16n8k16.row.col.f32.f16.f16.f32 " \
        "{%0,%1,%2,%3}, {%4,%5,%6,%7}, {%8,%9}, {%0,%1,%2,%3};" \
        : "+f"((c)[0]), "+f"((c)[1]), "+f"((c)[2]), "+f"((c)[3]) \
        : "r"((a)[0]), "r"((a)[1]), "r"((a)[2]), "r"((a)[3]), "r"(b0), "r"(b1))

// ============================================================
// split-FP16 (3-pass) mma.sync GEMM: 128x128 tile, 256 thr (R10 winner)
// ============================================================
#define AP 12
#define BP 136

__device__ __forceinline__ void f16_gemm(
    const float* __restrict__ A, int lda,
    const float* __restrict__ Bg, int ldb, int Ktot,
    uint32_t* AH, uint32_t* AL, uint32_t* BH, uint32_t* BL,
    float acc[2][8][4], int t)
{
    const int lane = t & 31, w = t >> 5;
    const int wm = w >> 1, wn = w & 1;
    const int q = lane & 3;
    const int am = t >> 1, akh = t & 1;
    const int bkp = t >> 5, bn = (lane) << 2;

    float4 pa0, pa1, pb0, pb1;
    pa0 = *reinterpret_cast<const float4*>(A + am*lda + 8*akh);
    pa1 = *reinterpret_cast<const float4*>(A + am*lda + 8*akh + 4);
    pb0 = *reinterpret_cast<const float4*>(Bg + (2*bkp    )*ldb + bn);
    pb1 = *reinterpret_cast<const float4*>(Bg + (2*bkp + 1)*ldb + bn);

    for (int k0 = 0; k0 < Ktot; k0 += 16) {
        {
            uint4 h, l;
            split2(pa0.x, pa0.y, h.x, l.x);
            split2(pa0.z, pa0.w, h.y, l.y);
            split2(pa1.x, pa1.y, h.z, l.z);
            split2(pa1.z, pa1.w, h.w, l.w);
            *reinterpret_cast<uint4*>(AH + am*AP + 4*akh) = h;
            *reinterpret_cast<uint4*>(AL + am*AP + 4*akh) = l;
        }
        {
            uint4 h, l;
            split2(pb0.x, pb1.x, h.x, l.x);
            split2(pb0.y, pb1.y, h.y, l.y);
            split2(pb0.z, pb1.z, h.z, l.z);
            split2(pb0.w, pb1.w, h.w, l.w);
            *reinterpret_cast<uint4*>(BH + bkp*BP + bn) = h;
            *reinterpret_cast<uint4*>(BL + bkp*BP + bn) = l;
        }
        __syncthreads();

        if (k0 + 16 < Ktot) {
            pa0 = *reinterpret_cast<const float4*>(A + am*lda + k0 + 16 + 8*akh);
            pa1 = *reinterpret_cast<const float4*>(A + am*lda + k0 + 16 + 8*akh + 4);
            pb0 = *reinterpret_cast<const float4*>(Bg + (k0 + 16 + 2*bkp    )*ldb + bn);
            pb1 = *reinterpret_cast<const float4*>(Bg + (k0 + 16 + 2*bkp + 1)*ldb + bn);
        }

        uint32_t Ah[2][4], Al[2][4];
#pragma unroll
        for (int mt = 0; mt < 2; mt++) {
            int r0 = (wm << 5) + (mt << 4) + (lane >> 2);
            Ah[mt][0] = AH[r0*AP + q];     Ah[mt][1] = AH[(r0+8)*AP + q];
            Ah[mt][2] = AH[r0*AP + q + 4]; Ah[mt][3] = AH[(r0+8)*AP + q + 4];
            Al[mt][0] = AL[r0*AP + q];     Al[mt][1] = AL[(r0+8)*AP + q];
            Al[mt][2] = AL[r0*AP + q + 4]; Al[mt][3] = AL[(r0+8)*AP + q + 4];
        }
#pragma unroll
        for (int nt = 0; nt < 8; nt++) {
            int nb = (wn << 6) + (nt << 3) + (lane >> 2);
            uint32_t bh0 = BH[q*BP + nb], bh1 = BH[(q+4)*BP + nb];
            uint32_t bl0 = BL[q*BP + nb], bl1 = BL[(q+4)*BP + nb];
#pragma unroll
            for (int mt = 0; mt < 2; mt++) {
                MMA_F16(acc[mt][nt], Ah[mt], bh0, bh1);
                MMA_F16(acc[mt][nt], Ah[mt], bl0, bl1);
                MMA_F16(acc[mt][nt], Al[mt], bh0, bh1);
            }
        }
        __syncthreads();
    }
}

#define GEMM_SM_DECL \
    __shared__ uint32_t AH[128*AP], AL[128*AP], BH[8*BP], BL[8*BP]

// ============================================================
// K1a: proj GEMM. grid (2, 32, 8=B*2), block 256.
// ============================================================
__global__ __launch_bounds__(256) void proj_gemm_kernel(
    const float* __restrict__ src1, const float* __restrict__ src2,
    const float* __restrict__ W)
{
    GEMM_SM_DECL;
    const int z = blockIdx.z, b = z >> 1, ssel = z & 1;
    const float* src = ssel ? src2 : src1;
    float* Yraw = g_T + ssel*BSC;
    const int m0 = blockIdx.x << 7;
    const int n0 = blockIdx.y << 7;
    const int t = threadIdx.x;
    const int lane = t & 31, w = t >> 5, wm = w >> 1, wn = w & 1;

    float acc[2][8][4];
#pragma unroll
    for (int a = 0; a < 2; a++)
#pragma unroll
        for (int b2_ = 0; b2_ < 8; b2_++)
#pragma unroll
            for (int c = 0; c < 4; c++) acc[a][b2_][c] = 0.f;

    f16_gemm(W + m0*Cn, Cn, src + b*Cn*Sn + n0, Sn, Cn,
             AH, AL, BH, BL, acc, t);

#pragma unroll
    for (int mt = 0; mt < 2; mt++)
#pragma unroll
    for (int i = 0; i < 2; i++) {
        int o = m0 + (wm << 5) + (mt << 4) + (lane >> 2) + (i << 3);
#pragma unroll
        for (int nt = 0; nt < 8; nt++) {
            int s = n0 + (wn << 6) + (nt << 3) + ((lane & 3) << 1);
            Yraw[(((b << 12) + s    ) << 8) + o] = acc[mt][nt][2*i];
            Yraw[(((b << 12) + s + 1) << 8) + o] = acc[mt][nt][2*i + 1];
        }
    }
}

// ============================================================
// K1b: LN over proj raw. warp per row.
// ============================================================
__global__ __launch_bounds__(256) void proj_ln_kernel(
    const float* __restrict__ bias, const float* __restrict__ gam,
    const float* __restrict__ bet)
{
    const int gr   = (blockIdx.x << 3) + (threadIdx.x >> 5);
    const int ssel = gr >= Bn*Sn;
    const int row  = ssel ? gr - Bn*Sn : gr;
    const float* Yraw = g_T + ssel*BSC;
    float* Xout       = ssel ? g_X2 : g_X1;
    const int lane = threadIdx.x & 31;
    const int base = row << 8;
    float v[8]; float sum = 0.f, sq = 0.f;
#pragma unroll
    for (int k = 0; k < 8; k++) {
        int o = lane + (k << 5);
        v[k] = Yraw[base + o] + bias[o];
        sum += v[k]; sq += v[k]*v[k];
    }
#pragma unroll
    for (int o = 16; o > 0; o >>= 1) {
        sum += __shfl_xor_sync(0xffffffffu, sum, o);
        sq  += __shfl_xor_sync(0xffffffffu, sq , o);
    }
    float mean = sum * (1.f/256.f);
    float var  = sq  * (1.f/256.f) - mean*mean;
    float rstd = rsqrtf(var + 1e-5f);
#pragma unroll
    for (int k = 0; k < 8; k++) {
        int o = lane + (k << 5);
        Xout[base + o] = (v[k] - mean)*rstd*gam[o] + bet[o];
    }
}

// ============================================================
// attention: score via split-fp16 mma, softmax + fp32 PV as before.
// smem floats: Qhi/Qlo/Khi/Klo 32*132 each (as u32), V 32*260, ssm 32*36, 96
// total = 4*4224 + 8320 + 1152 + 96 = 26,464 floats = 105,856 B -> 2 CTA/SM
// ============================================================
#define QKP 132
#define VP4 260
#define SSP 36
#define ATTN_SMEM_FLOATS (4*32*QKP + 32*VP4 + 32*SSP + 96)

__device__ __forceinline__ void attn_tile(
    const float* __restrict__ X2, int b, int kb, int t,
    const uint32_t* Qhi, const uint32_t* Qlo,
    uint32_t* Khi, uint32_t* Klo,
    float* vsm, float* ssm,
    float* mrow, float* lrow, float* arow,
    float out0[16], float out1[16])
{
    const int tx = t & 15, ty = t >> 4;
    const int warp = t >> 5, lane = t & 31;
    const int c2 = t & 127, rh = (t >> 7) << 4;

    // load K/V tile: fp32 -> split fp16 hi/lo [row][d/2] + fp32 V copy
#pragma unroll
    for (int i = 0; i < 16; i++) {
        int row = rh + i;
        float2 gl = *reinterpret_cast<const float2*>(
            X2 + (((b << 12) + (kb << 5) + row) << 8) + 2*c2);
        uint32_t h, l;
        split2(gl.x, gl.y, h, l);
        Khi[row*QKP + c2] = h;
        Klo[row*QKP + c2] = l;
        *reinterpret_cast<float2*>(vsm + row*VP4 + 2*c2) = gl;
    }
    __syncthreads();

    // score mma: warp patch (mh = warp>>2 -> rows, ne = warp&3 -> key cols)
    {
        const int mh = warp >> 2, ne = warp & 3;
        const int gr = lane >> 2, q = lane & 3;
        const int ar0 = (mh << 4) + gr;
        const int bn  = (ne << 3) + gr;
        float c[4] = {0.f, 0.f, 0.f, 0.f};
#pragma unroll
        for (int ks = 0; ks < 16; ks++) {
            int kp = (ks << 3) + q;
            uint32_t a[4], al[4];
            a[0]  = Qhi[ar0*QKP + kp];     a[1]  = Qhi[(ar0+8)*QKP + kp];
            a[2]  = Qhi[ar0*QKP + kp + 4]; a[3]  = Qhi[(ar0+8)*QKP + kp + 4];
            al[0] = Qlo[ar0*QKP + kp];     al[1] = Qlo[(ar0+8)*QKP + kp];
            al[2] = Qlo[ar0*QKP + kp + 4]; al[3] = Qlo[(ar0+8)*QKP + kp + 4];
            uint32_t bh0 = Khi[bn*QKP + kp], bh1 = Khi[bn*QKP + kp + 4];
            uint32_t bl0 = Klo[bn*QKP + kp], bl1 = Klo[bn*QKP + kp + 4];
            MMA_F16(c, a, bh0, bh1);
            MMA_F16(c, a, bl0, bl1);
            MMA_F16(c, al, bh0, bh1);
        }
        const float scl = 0.0625f; // 1/sqrt(256)
        int r  = (mh << 4) + gr;
        int cc = (ne << 3) + (q << 1);
        *reinterpret_cast<float2*>(ssm + r*SSP + cc) =
            make_float2(c[0]*scl, c[1]*scl);
        *reinterpret_cast<float2*>(ssm + (r+8)*SSP + cc) =
            make_float2(c[2]*scl, c[3]*scl);
    }
    __syncthreads();

    // online softmax: warp handles 4 rows
#pragma unroll
    for (int r = 0; r < 4; r++) {
        int row = (warp << 2) + r;
        float sv = ssm[row*SSP + lane];
        float mx = sv;
#pragma unroll
        for (int o = 16; o > 0; o >>= 1)
            mx = fmaxf(mx, __shfl_xor_sync(0xffffffffu, mx, o));
        float mold = mrow[row];
        float mnew = fmaxf(mold, mx);
        float p = __expf(sv - mnew);
        float ps = p;
#pragma unroll
        for (int o = 16; o > 0; o >>= 1)
            ps += __shfl_xor_sync(0xffffffffu, ps, o);
        if (lane == 0) {
            float a = __expf(mold - mnew);
            arow[row] = a;
            lrow[row] = lrow[row]*a + ps;
            mrow[row] = mnew;
        }
        ssm[row*SSP + lane] = p;
    }
    __syncthreads();

    // PV (fp32): out[q=2ty+{0,1}][d=4tx+64g+c] from vsm
    float a0 = arow[2*ty], a1 = arow[2*ty+1];
#pragma unroll
    for (int j = 0; j < 16; j++) { out0[j] *= a0; out1[j] *= a1; }
    const float* p0r = ssm + (2*ty)*SSP;
    const float* p1r = ssm + (2*ty+1)*SSP;
#pragma unroll 4
    for (int k = 0; k < 32; k++) {
        float p0 = p0r[k], p1 = p1r[k];
        const float* vrow = vsm + k*VP4 + 4*tx;
#pragma unroll
        for (int g = 0; g < 4; g++) {
            float4 v = *reinterpret_cast<const float4*>(vrow + (g << 6));
            out0[g*4+0] += p0*v.x; out0[g*4+1] += p0*v.y;
            out0[g*4+2] += p0*v.z; out0[g*4+3] += p0*v.w;
            out1[g*4+0] += p1*v.x; out1[g*4+1] += p1*v.y;
            out1[g*4+2] += p1*v.z; out1[g*4+3] += p1*v.w;
        }
    }
    __syncthreads();
}

__global__ __launch_bounds__(256) void attn_kernel(
    const float* __restrict__ X1, const float* __restrict__ X2,
    const int* __restrict__ bidx, int K, float* __restrict__ ATT,
    float* __restrict__ GO, float* __restrict__ GM, float* __restrict__ GL)
{
    extern __shared__ float sm[];
    uint32_t* Qhi = reinterpret_cast<uint32_t*>(sm);
    uint32_t* Qlo = Qhi + 32*QKP;
    uint32_t* Khi = Qlo + 32*QKP;
    uint32_t* Klo = Khi + 32*QKP;
    float* vsm  = sm + 4*32*QKP;
    float* ssm  = vsm + 32*VP4;
    float* mrow = ssm + 32*SSP;
    float* lrow = mrow + 32;
    float* arow = lrow + 32;

    const int b = blockIdx.y, x = blockIdx.x;
    const int t = threadIdx.x;
    const int tx = t & 15, ty = t >> 4;
    const int c2 = t & 127, rh = (t >> 7) << 4;
    const bool sparse = (x < NBn - 1);
    const int n = sparse ? (x + 1) : 0;

    // Q load + split (once per CTA)
#pragma unroll
    for (int i = 0; i < 16; i++) {
        int row = rh + i;
        float2 gl = *reinterpret_cast<const float2*>(
            X1 + (((b << 12) + (n << 5) + row) << 8) + 2*c2);
        uint32_t h, l;
        split2(gl.x, gl.y, h, l);
        Qhi[row*QKP + c2] = h;
        Qlo[row*QKP + c2] = l;
    }
    if (t < 32) { mrow[t] = -1e30f; lrow[t] = 0.f; }

    float out0[16], out1[16];
#pragma unroll
    for (int j = 0; j < 16; j++) { out0[j] = 0.f; out1[j] = 0.f; }
    __syncthreads();

    if (sparse) {
        for (int it = 0; it < K; it++) {
            int kb = bidx[(n - 1)*K + it];
            if (it > 0 && kb == 0) break;
            attn_tile(X2, b, kb, t, Qhi, Qlo, Khi, Klo, vsm, ssm,
                      mrow, lrow, arow, out0, out1);
        }
        const float l0 = 1.f / lrow[2*ty];
        const float l1 = 1.f / lrow[2*ty+1];
        const int base0 = (((b << 12) + (n << 5) + 2*ty) << 8) + 4*tx;
        const int base1 = base0 + 256;
#pragma unroll
        for (int g = 0; g < 4; g++) {
            *reinterpret_cast<float4*>(ATT + base0 + (g << 6)) =
                make_float4(out0[g*4+0]*l0, out0[g*4+1]*l0, out0[g*4+2]*l0, out0[g*4+3]*l0);
            *reinterpret_cast<float4*>(ATT + base1 + (g << 6)) =
                make_float4(out1[g*4+0]*l1, out1[g*4+1]*l1, out1[g*4+2]*l1, out1[g*4+3]*l1);
        }
    } else {
        const int split = x - (NBn - 1);
        for (int it = 0; it < NBn/NSPLIT; it++) {
            int kb = split*(NBn/NSPLIT) + it;
            attn_tile(X2, b, kb, t, Qhi, Qlo, Khi, Klo, vsm, ssm,
                      mrow, lrow, arow, out0, out1);
        }
        const int gi = (b*NSPLIT + split)*32;
        const int base0 = ((gi + 2*ty) << 8) + 4*tx;
        const int base1 = base0 + 256;
#pragma unroll
        for (int g = 0; g < 4; g++) {
            *reinterpret_cast<float4*>(GO + base0 + (g << 6)) =
                make_float4(out0[g*4+0], out0[g*4+1], out0[g*4+2], out0[g*4+3]);
            *reinterpret_cast<float4*>(GO + base1 + (g << 6)) =
                make_float4(out1[g*4+0], out1[g*4+1], out1[g*4+2], out1[g*4+3]);
        }
        if (t < 32) { GM[gi + t] = mrow[t]; GL[gi + t] = lrow[t]; }
    }
}

__global__ __launch_bounds__(256) void attn_global_combine(
    const float* __restrict__ GO, const float* __restrict__ GM,
    const float* __restrict__ GL, float* __restrict__ ATT)
{
    const int b = blockIdx.x, q = blockIdx.y, t = threadIdx.x;
    float ms[NSPLIT], ls[NSPLIT];
    float M = -1e30f;
#pragma unroll
    for (int i = 0; i < NSPLIT; i++) {
        ms[i] = GM[(b*NSPLIT + i)*32 + q];
        ls[i] = GL[(b*NSPLIT + i)*32 + q];
        M = fmaxf(M, ms[i]);
    }
    float L = 0.f, acc = 0.f;
#pragma unroll
    for (int i = 0; i < NSPLIT; i++) {
        float e = __expf(ms[i] - M);
        L   += ls[i] * e;
        acc += GO[(((b*NSPLIT + i)*32 + q) << 8) + t] * e;
    }
    ATT[(((b << 12) + q) << 8) + t] = acc / L;
}

// ============================================================
// K3: H = LN(X1 + ATT)
// ============================================================
__global__ __launch_bounds__(256) void add_ln_kernel(
    const float* __restrict__ X1, const float* __restrict__ ATT,
    const float* __restrict__ gam, const float* __restrict__ bet,
    float* __restrict__ H)
{
    const int row  = (blockIdx.x << 3) + (threadIdx.x >> 5);
    const int lane = threadIdx.x & 31;
    const int base = row << 8;
    float v[8]; float sum = 0.f, sq = 0.f;
#pragma unroll
    for (int k = 0; k < 8; k++) {
        int o = lane + (k << 5);
        v[k] = X1[base + o] + ATT[base + o];
        sum += v[k]; sq += v[k]*v[k];
    }
#pragma unroll
    for (int o = 16; o > 0; o >>= 1) {
        sum += __shfl_xor_sync(0xffffffffu, sum, o);
        sq  += __shfl_xor_sync(0xffffffffu, sq , o);
    }
    float mean = sum * (1.f/256.f);
    float var  = sq  * (1.f/256.f) - mean*mean;
    float rstd = rsqrtf(var + 1e-5f);
#pragma unroll
    for (int k = 0; k < 8; k++) {
        int o = lane + (k << 5);
        H[base + o] = (v[k] - mean)*rstd*gam[o] + bet[o];
    }
}

// ============================================================
// K4: ffn1: T = gelu(H @ w1 + b1). grid (128, 8), 256 thr
// ============================================================
__global__ __launch_bounds__(256) void ffn1_kernel(
    const float* __restrict__ H, const float* __restrict__ w1,
    const float* __restrict__ b1, float* __restrict__ T)
{
    GEMM_SM_DECL;
    const int m0 = blockIdx.x << 7, n0 = blockIdx.y << 7;
    const int t = threadIdx.x;
    const int lane = t & 31, w = t >> 5, wm = w >> 1, wn = w & 1;

    float acc[2][8][4];
#pragma unroll
    for (int a = 0; a < 2; a++)
#pragma unroll
        for (int b_ = 0; b_ < 8; b_++)
#pragma unroll
            for (int c = 0; c < 4; c++) acc[a][b_][c] = 0.f;

    f16_gemm(H + m0*Cn, Cn, w1 + n0, DFFn, Cn, AH, AL, BH, BL, acc, t);

#pragma unroll
    for (int mt = 0; mt < 2; mt++)
#pragma unroll
    for (int i = 0; i < 2; i++) {
        int m = m0 + (wm << 5) + (mt << 4) + (lane >> 2) + (i << 3);
#pragma unroll
        for (int nt = 0; nt < 8; nt++) {
            int n = n0 + (wn << 6) + (nt << 3) + ((lane & 3) << 1);
            float x0 = acc[mt][nt][2*i]   + b1[n];
            float x1 = acc[mt][nt][2*i+1] + b1[n+1];
            float g0 = 0.5f*x0*(1.f + erff(x0*0.70710678118654752f));
            float g1 = 0.5f*x1*(1.f + erff(x1*0.70710678118654752f));
            *reinterpret_cast<float2*>(T + m*DFFn + n) = make_float2(g0, g1);
        }
    }
}

// ============================================================
// K5: ffn2: Out(B,C,S) = transpose(H + T @ w2 + b2). grid (128, 2), 256 thr
// ============================================================
__global__ __launch_bounds__(256) void ffn2_kernel(
    const float* __restrict__ T, const float* __restrict__ w2,
    const float* __restrict__ b2, const float* __restrict__ H,
    float* __restrict__ Out)
{
    GEMM_SM_DECL;
    const int m0 = blockIdx.x << 7, n0 = blockIdx.y << 7;
    const int t = threadIdx.x;
    const int lane = t & 31, w = t >> 5, wm = w >> 1, wn = w & 1;

    float acc[2][8][4];
#pragma unroll
    for (int a = 0; a < 2; a++)
#pragma unroll
        for (int b_ = 0; b_ < 8; b_++)
#pragma unroll
            for (int c = 0; c < 4; c++) acc[a][b_][c] = 0.f;

    f16_gemm(T + m0*DFFn, DFFn, w2 + n0, Cn, DFFn, AH, AL, BH, BL, acc, t);

#pragma unroll
    for (int mt = 0; mt < 2; mt++)
#pragma unroll
    for (int i = 0; i < 2; i++) {
        int m = m0 + (wm << 5) + (mt << 4) + (lane >> 2) + (i << 3);
        int b = m >> 12;
        int s = m & 4095;
#pragma unroll
        for (int nt = 0; nt < 8; nt++) {
            int n = n0 + (wn << 6) + (nt << 3) + ((lane & 3) << 1);
            float2 h2 = *reinterpret_cast<const float2*>(H + m*Cn + n);
            float v0 = acc[mt][nt][2*i]   + b2[n]   + h2.x;
            float v1 = acc[mt][nt][2*i+1] + b2[n+1] + h2.y;
            Out[(((b << 8) + n    ) << 12) + s] = v0;
            Out[(((b << 8) + n + 1) << 12) + s] = v1;
        }
    }
}

// ============================================================
extern "C" void kernel_launch(void* const* d_in, const int* in_sizes, int n_in,
                              void* d_out, int out_size)
{
    const float* src1  = (const float*)d_in[0];
    const float* src2  = (const float*)d_in[1];
    const float* wproj = (const float*)d_in[2];
    const float* bproj = (const float*)d_in[3];
    const float* g13   = (const float*)d_in[4];
    const float* be13  = (const float*)d_in[5];
    const float* g12   = (const float*)d_in[6];
    const float* be12  = (const float*)d_in[7];
    const float* w1    = (const float*)d_in[8];
    const float* b1    = (const float*)d_in[9];
    const float* w2    = (const float*)d_in[10];
    const float* b2    = (const float*)d_in[11];
    const int*   bidx  = (const int*)d_in[12];
    const int K = in_sizes[12] / (NBn - 1);
    float* out = (float*)d_out;

    float *X1, *X2, *ATT, *H, *T, *GO, *GM, *GL;
    cudaGetSymbolAddress((void**)&X1,  g_X1);
    cudaGetSymbolAddress((void**)&X2,  g_X2);
    cudaGetSymbolAddress((void**)&ATT, g_ATT);
    cudaGetSymbolAddress((void**)&H,   g_H);
    cudaGetSymbolAddress((void**)&T,   g_T);
    cudaGetSymbolAddress((void**)&GO,  g_GO);
    cudaGetSymbolAddress((void**)&GM,  g_GM);
    cudaGetSymbolAddress((void**)&GL,  g_GL);

    const int attn_smem = ATTN_SMEM_FLOATS * 4;   // 105,856 B -> 2 CTA/SM
    cudaFuncSetAttribute(attn_kernel, cudaFuncAttributeMaxDynamicSharedMemorySize, attn_smem);

    proj_gemm_kernel<<<dim3(2, 32, Bn*2), 256>>>(src1, src2, wproj);
    proj_ln_kernel<<<(2*Bn*Sn)/8, 256>>>(bproj, g13, be13);

    attn_kernel<<<dim3(NBn - 1 + NSPLIT, Bn), 256, attn_smem>>>(
        X1, X2, bidx, K, ATT, GO, GM, GL);
    attn_global_combine<<<dim3(Bn, 32), 256>>>(GO, GM, GL, ATT);

    add_ln_kernel<<<(Bn*Sn)/8, 256>>>(X1, ATT, g12, be12, H);

    ffn1_kernel<<<dim3((Bn*Sn)/128, DFFn/128), 256>>>(H, w1, b1, T);
    ffn2_kernel<<<dim3((Bn*Sn)/128, Cn/128), 256>>>(T, w2, b2, H, out);
}